// round 11
// baseline (speedup 1.0000x reference)
#include <cuda_runtime.h>
#include <cuda_fp16.h>
#include <math.h>
#include <stdint.h>

// ---------------- problem constants ----------------
#define BB 4
#define TT 784
#define GG 28
#define EE 768
#define HDIM 3072
#define NHEADS 12
#define DHEAD 64
#define NLAYERS 6
#define MM (BB*TT)        // 3136
#define MPAD 3200         // 50*64
#define NBH (BB*NHEADS)   // 48

// ---------------- scratch ----------------
__device__ __half g_xp_h[MPAD * EE];
__device__ __half g_xp_l[MPAD * EE];
__device__ float  g_h[MPAD * EE];
__device__ __half g_y_h[MPAD * EE];
__device__ __half g_y_l[MPAD * EE];
__device__ __half g_qkv_h[MPAD * 3 * EE];
__device__ __half g_qkv_l[MPAD * 3 * EE];
__device__ __half g_o_h[MPAD * EE];
__device__ __half g_o_l[MPAD * EE];
__device__ __half g_mlp_h[MPAD * HDIM];
__device__ __half g_mlp_l[MPAD * HDIM];
// pre-converted weights (fp16; B-side of 2-pass scheme)
__device__ __half g_iw_h[EE * EE];
__device__ __half g_inw_h[NLAYERS * 3 * EE * EE];
__device__ __half g_outw_h[NLAYERS * EE * EE];
__device__ __half g_w1_h[NLAYERS * HDIM * EE];
__device__ __half g_w2_h[NLAYERS * EE * HDIM];

#define EPI_NONE 0
#define EPI_POS  1
#define EPI_RES  2
#define EPI_GELU 3

// ---------------- helpers ----------------
__device__ __forceinline__ void h_split(float v, __half& hi, __half& lo) {
    hi = __float2half_rn(v);
    lo = __float2half_rn(v - __half2float(hi));
}

__device__ __forceinline__ uint32_t packh2(__half a, __half b) {
    __half2 x = __halves2half2(a, b);
    return *reinterpret_cast<uint32_t*>(&x);
}

__device__ __forceinline__ void mma_f16(float d[4],
                                        uint32_t a0, uint32_t a1, uint32_t a2, uint32_t a3,
                                        uint32_t b0, uint32_t b1) {
    asm volatile(
        "mma.sync.aligned.m16n8k16.row.col.f32.f16.f16.f32 "
        "{%0,%1,%2,%3}, {%4,%5,%6,%7}, {%8,%9}, {%0,%1,%2,%3};"
        : "+f"(d[0]), "+f"(d[1]), "+f"(d[2]), "+f"(d[3])
        : "r"(a0), "r"(a1), "r"(a2), "r"(a3), "r"(b0), "r"(b1));
}

#define LDSM_X4(r0, r1, r2, r3, addr) \
    asm volatile("ldmatrix.sync.aligned.m8n8.x4.shared.b16 {%0,%1,%2,%3}, [%4];" \
        : "=r"(r0), "=r"(r1), "=r"(r2), "=r"(r3) : "r"(addr))

__device__ __forceinline__ void cpa16(uint32_t dst, const void* src) {
    asm volatile("cp.async.cg.shared.global [%0], [%1], 16;" :: "r"(dst), "l"(src));
}
__device__ __forceinline__ void cpa16z(uint32_t dst, const void* src, bool valid) {
    int sz = valid ? 16 : 0;
    asm volatile("cp.async.cg.shared.global [%0], [%1], 16, %2;"
                 :: "r"(dst), "l"(src), "r"(sz));
}
__device__ __forceinline__ void cp_commit() { asm volatile("cp.async.commit_group;"); }
__device__ __forceinline__ void cp_wait0() { asm volatile("cp.async.wait_group 0;"); }
__device__ __forceinline__ void cp_wait1() { asm volatile("cp.async.wait_group 1;"); }

// ---------------- merged weight convert (fp32 -> fp16 rn), all 5 tensors ----------------
#define CN0 ((EE*EE)/4)
#define CN1 ((NLAYERS*3*EE*EE)/4)
#define CN2 ((NLAYERS*EE*EE)/4)
#define CN3 ((NLAYERS*HDIM*EE)/4)
#define CN4 ((NLAYERS*EE*HDIM)/4)
__global__ void conv_all(const float4* __restrict__ s0, const float4* __restrict__ s1,
                         const float4* __restrict__ s2, const float4* __restrict__ s3,
                         const float4* __restrict__ s4,
                         __half2* __restrict__ d0, __half2* __restrict__ d1,
                         __half2* __restrict__ d2, __half2* __restrict__ d3,
                         __half2* __restrict__ d4)
{
    long i = (long)blockIdx.x * 256 + threadIdx.x;
    const float4* s; __half2* d; long off;
    if (i < CN0)                                  { s = s0; d = d0; off = i; }
    else if (i < (long)CN0 + CN1)                 { s = s1; d = d1; off = i - CN0; }
    else if (i < (long)CN0 + CN1 + CN2)           { s = s2; d = d2; off = i - CN0 - CN1; }
    else if (i < (long)CN0 + CN1 + CN2 + CN3)     { s = s3; d = d3; off = i - CN0 - CN1 - CN2; }
    else if (i < (long)CN0 + CN1 + CN2 + CN3 + CN4) { s = s4; d = d4; off = i - CN0 - CN1 - CN2 - CN3; }
    else return;
    float4 a = s[off];
    d[2 * off]     = __halves2half2(__float2half_rn(a.x), __float2half_rn(a.y));
    d[2 * off + 1] = __halves2half2(__float2half_rn(a.z), __float2half_rn(a.w));
}

// ---------------- patch gather (split output) ----------------
__global__ void patch_gather(const float* __restrict__ x, __half* __restrict__ xh,
                             __half* __restrict__ xl) {
    int idx = blockIdx.x * 256 + threadIdx.x;
    if (idx >= MM * EE) return;
    int j = idx % EE;
    int m = idx / EE;
    int b = m / TT, t = m % TT;
    int gr = t / GG, gc = t % GG;
    int ch = j >> 8, pr = (j >> 4) & 15, pc = j & 15;
    float v = x[(((size_t)b * 448 + gr * 16 + pr) * 448 + (gc * 16 + pc)) * 3 + ch];
    __half hv, lv;
    h_split(v, hv, lv);
    xh[idx] = hv; xl[idx] = lv;
}

// ---------------- split-FP16 2-pass GEMM, 64x128 block tile ----------------
// 8 warps (4 M-groups x 2 N-groups), warp tile 16x64. ldmatrix fragments,
// cp.async double-buffered. Stage = Ah(64x40) + Al + W(128x40) halves = 20480B.
#define GST 40
#define STAGE_B 20480
__global__ __launch_bounds__(256, 3)
void gemm_h(const __half* __restrict__ Ah, const __half* __restrict__ Al,
            const __half* __restrict__ Wh,
            const float* __restrict__ bias, const float* __restrict__ extra,
            float* __restrict__ C, __half* __restrict__ Ch, __half* __restrict__ Cl,
            int M, int N, int K, int epi, int split)
{
    extern __shared__ __half smh[];
    int tid = threadIdx.x, warp = tid >> 5, lane = tid & 31;
    int r = lane >> 2, t2 = (lane & 3) * 2;
    int m0 = blockIdx.y * 64, n0 = blockIdx.x * 128;
    int wm = (warp & 3) * 16, wn = (warp >> 2) * 64;
    uint32_t smb = (uint32_t)__cvta_generic_to_shared(smh);

    // loaders
    int a_lrow = tid >> 2, a_seg = tid & 3;           // A: 64 rows x 4 segs
    int w_lrow = tid >> 1, w_seg0 = (tid & 1) * 2;    // W: 128 rows x 2 segs each
    const __half* srcA_h = Ah + (size_t)(m0 + a_lrow) * K + a_seg * 8;
    const __half* srcA_l = Al + (size_t)(m0 + a_lrow) * K + a_seg * 8;
    const __half* srcW_h = Wh + (size_t)(n0 + w_lrow) * K;
    uint32_t dA = smb + (uint32_t)(a_lrow * GST + a_seg * 8) * 2;
    uint32_t dW = smb + 10240 + (uint32_t)(w_lrow * GST) * 2;

    // ldmatrix per-lane address components (halves)
    int a_row = wm + (lane & 15);
    int a_col = (lane >> 4) << 3;
    int b_row = wn + ((lane >> 4) << 3) + (lane & 7);
    int b_col = ((lane >> 3) & 1) << 3;

    float acc[8][4] = {};
    const int KT = K >> 5;

    auto issue = [&](int st, int kc) {
        int k0 = kc << 5;
        uint32_t sb = st * STAGE_B;
        cpa16(dA + sb,          srcA_h + k0);
        cpa16(dA + sb + 5120,   srcA_l + k0);
        cpa16(dW + sb + w_seg0 * 16,        srcW_h + k0 + w_seg0 * 8);
        cpa16(dW + sb + (w_seg0 + 1) * 16,  srcW_h + k0 + (w_seg0 + 1) * 8);
    };

    issue(0, 0); cp_commit();

    for (int kc = 0; kc < KT; kc++) {
        if (kc + 1 < KT) { issue((kc + 1) & 1, kc + 1); cp_commit(); cp_wait1(); }
        else cp_wait0();
        __syncthreads();

        uint32_t aAh = smb + (kc & 1) * STAGE_B;
        uint32_t aAl = aAh + 10240;
        uint32_t aWh = aAh + 20480;
        // note: Al offset 5120B within A region; W at 10240B
        aAl = aAh + 5120 * 2;   // 5120 halves? no: bytes. fix below.
        aAl = aAh + 10240;      // Al at +10240B? layout: Ah 0..5119B? 64*40 halves = 2560 halves = 5120B
        aAl = aAh + 5120;
        aWh = aAh + 10240;

        #pragma unroll
        for (int s = 0; s < 2; s++) {
            int ks = s * 16;
            uint32_t ah[4], al[4];
            {
                uint32_t adr = (uint32_t)(a_row * GST + ks + a_col) * 2;
                LDSM_X4(ah[0], ah[1], ah[2], ah[3], aAh + adr);
                LDSM_X4(al[0], al[1], al[2], al[3], aAl + adr);
            }
            #pragma unroll
            for (int jj = 0; jj < 4; jj++) {
                uint32_t badr = aWh + (uint32_t)((b_row + 16 * jj) * GST + ks + b_col) * 2;
                uint32_t b00, b01, b10, b11;
                LDSM_X4(b00, b01, b10, b11, badr);
                mma_f16(acc[2 * jj],     al[0], al[1], al[2], al[3], b00, b01);
                mma_f16(acc[2 * jj],     ah[0], ah[1], ah[2], ah[3], b00, b01);
                mma_f16(acc[2 * jj + 1], al[0], al[1], al[2], al[3], b10, b11);
                mma_f16(acc[2 * jj + 1], ah[0], ah[1], ah[2], ah[3], b10, b11);
            }
        }
        __syncthreads();
    }

    #pragma unroll
    for (int j = 0; j < 8; j++) {
        #pragma unroll
        for (int half = 0; half < 2; half++) {
            int m = m0 + wm + r + half * 8;
            #pragma unroll
            for (int e = 0; e < 2; e++) {
                int n = n0 + wn + 8 * j + t2 + e;
                float v = acc[j][half * 2 + e] + bias[n];
                if (epi == EPI_POS)       v += extra[(size_t)(m % TT) * N + n];
                else if (epi == EPI_RES)  v += extra[(size_t)m * N + n];
                else if (epi == EPI_GELU) v = 0.5f * v * (1.0f + erff(v * 0.70710678118654752f));
                if (split) {
                    __half hv, lv; h_split(v, hv, lv);
                    Ch[(size_t)m * N + n] = hv;
                    Cl[(size_t)m * N + n] = lv;
                } else {
                    C[(size_t)m * N + n] = v;
                }
            }
        }
    }
}

// ---------------- fused flash attention (unchanged) ----------------
#define QST 72
#define VST 152
__global__ __launch_bounds__(256, 1)
void flash_attn(const __half* __restrict__ qh, const __half* __restrict__ ql,
                __half* __restrict__ oh, __half* __restrict__ ol)
{
    extern __shared__ __half sm[];
    __half* sQh = sm;
    __half* sQl = sm + 9216;
    __half* sKh = sm + 18432;
    __half* sV  = sm + 27648;

    int bh = blockIdx.y, b = bh / NHEADS, h = bh % NHEADS;
    int q0 = blockIdx.x * 128;
    int tid = threadIdx.x, warp = tid >> 5, lane = tid & 31;
    int r = lane >> 2, t2 = (lane & 3) * 2;
    uint32_t smb = (uint32_t)__cvta_generic_to_shared(sm);

    int lrow = tid >> 1, lpart = tid & 1;

    {
        int qrow = q0 + lrow;
        bool qv = qrow < TT;
        const __half* sQg = qh + (size_t)(b * TT + (qv ? qrow : 0)) * (3 * EE) + h * DHEAD + lpart * 32;
        const __half* sQg2 = ql + (size_t)(b * TT + (qv ? qrow : 0)) * (3 * EE) + h * DHEAD + lpart * 32;
        uint32_t d0 = smb + lrow * (QST * 2) + lpart * 64;
        #pragma unroll
        for (int c = 0; c < 4; c++) {
            cpa16z(d0 + c * 16,         sQg  + c * 8, qv);
            cpa16z(d0 + 18432 + c * 16, sQg2 + c * 8, qv);
        }
    }
    cp_commit();

    int qi0 = q0 + 16 * warp + r;
    int qi1 = qi0 + 8;
    int rq0 = qi0 / GG, cq0 = qi0 - rq0 * GG;
    int rq1 = qi1 / GG, cq1 = qi1 - rq1 * GG;

    float m0 = -1e30f, m1 = -1e30f, l0 = 0.f, l1 = 0.f;
    float acc_o[8][4] = {};

    const __half* vbase = qh + (size_t)(b * TT) * (3 * EE) + 2 * EE + h * DHEAD;

    for (int kb = 0; kb < 7; kb++) {
        int k0 = kb * 128;
        __syncthreads();

        {
            int krow = k0 + lrow;
            bool kv2 = krow < TT;
            const __half* sKg = qh + (size_t)(b * TT + (kv2 ? krow : 0)) * (3 * EE) + EE + h * DHEAD + lpart * 32;
            uint32_t dk = smb + 36864 + lrow * (QST * 2) + lpart * 64;
            #pragma unroll
            for (int c = 0; c < 4; c++) cpa16z(dk + c * 16, sKg + c * 8, kv2);
        }
        cp_commit();

        {
            int vd = tid & 63;
            int kbase = (tid >> 6) * 32;
            #pragma unroll
            for (int i = 0; i < 32; i++) {
                int k = kbase + i;
                int tok = k0 + k;
                __half v = (tok < TT) ? vbase[(size_t)tok * (3 * EE) + vd] : __half(0.f);
                sV[vd * VST + k] = v;
            }
        }
        cp_wait0();
        __syncthreads();

        float s[16][4] = {};
        #pragma unroll
        for (int ds = 0; ds < 4; ds++) {
            int ks = ds * 16;
            const __half* pa = sQh + (16 * warp + r) * QST + ks + t2;
            uint32_t ah0 = *(const uint32_t*)pa;
            uint32_t ah1 = *(const uint32_t*)(pa + 8 * QST);
            uint32_t ah2 = *(const uint32_t*)(pa + 8);
            uint32_t ah3 = *(const uint32_t*)(pa + 8 * QST + 8);
            const __half* pl = sQl + (16 * warp + r) * QST + ks + t2;
            uint32_t al0 = *(const uint32_t*)pl;
            uint32_t al1 = *(const uint32_t*)(pl + 8 * QST);
            uint32_t al2 = *(const uint32_t*)(pl + 8);
            uint32_t al3 = *(const uint32_t*)(pl + 8 * QST + 8);
            #pragma unroll
            for (int j = 0; j < 16; j++) {
                const __half* pk = sKh + (8 * j + r) * QST + ks + t2;
                uint32_t b0 = *(const uint32_t*)pk;
                uint32_t b1 = *(const uint32_t*)(pk + 8);
                mma_f16(s[j], al0, al1, al2, al3, b0, b1);
                mma_f16(s[j], ah0, ah1, ah2, ah3, b0, b1);
            }
        }

        float bm0 = -1e30f, bm1 = -1e30f;
        #pragma unroll
        for (int j = 0; j < 16; j++) {
            #pragma unroll
            for (int e = 0; e < 2; e++) {
                int ki = k0 + 8 * j + t2 + e;
                int rk = ki / GG, ck = ki - rk * GG;
                bool oob = ki >= TT;
                float v0 = s[j][e] * 0.125f;
                if (oob || (abs(rq0 - rk) <= 4 && abs(cq0 - ck) <= 4)) v0 = -1e30f;
                s[j][e] = v0;
                bm0 = fmaxf(bm0, v0);
                float v1 = s[j][e + 2] * 0.125f;
                if (oob || (abs(rq1 - rk) <= 4 && abs(cq1 - ck) <= 4)) v1 = -1e30f;
                s[j][e + 2] = v1;
                bm1 = fmaxf(bm1, v1);
            }
        }
        bm0 = fmaxf(bm0, __shfl_xor_sync(0xFFFFFFFFu, bm0, 1));
        bm0 = fmaxf(bm0, __shfl_xor_sync(0xFFFFFFFFu, bm0, 2));
        bm1 = fmaxf(bm1, __shfl_xor_sync(0xFFFFFFFFu, bm1, 1));
        bm1 = fmaxf(bm1, __shfl_xor_sync(0xFFFFFFFFu, bm1, 2));

        float nm0 = fmaxf(m0, bm0), nm1 = fmaxf(m1, bm1);
        float sc0 = __expf(m0 - nm0), sc1 = __expf(m1 - nm1);
        m0 = nm0; m1 = nm1;

        float rs0 = 0.f, rs1 = 0.f;
        #pragma unroll
        for (int j = 0; j < 16; j++) {
            #pragma unroll
            for (int e = 0; e < 2; e++) {
                float p0 = __expf(s[j][e] - m0);
                s[j][e] = p0; rs0 += p0;
                float p1 = __expf(s[j][e + 2] - m1);
                s[j][e + 2] = p1; rs1 += p1;
            }
        }
        rs0 += __shfl_xor_sync(0xFFFFFFFFu, rs0, 1);
        rs0 += __shfl_xor_sync(0xFFFFFFFFu, rs0, 2);
        rs1 += __shfl_xor_sync(0xFFFFFFFFu, rs1, 1);
        rs1 += __shfl_xor_sync(0xFFFFFFFFu, rs1, 2);
        l0 = l0 * sc0 + rs0;
        l1 = l1 * sc1 + rs1;

        #pragma unroll
        for (int j2 = 0; j2 < 8; j2++) {
            acc_o[j2][0] *= sc0; acc_o[j2][1] *= sc0;
            acc_o[j2][2] *= sc1; acc_o[j2][3] *= sc1;
        }

        #pragma unroll
        for (int s2 = 0; s2 < 8; s2++) {
            __half h00, l00, h01, l01, h02, l02, h03, l03;
            __half h10, l10, h11, l11, h12, l12, h13, l13;
            h_split(s[2 * s2][0], h00, l00); h_split(s[2 * s2][1], h01, l01);
            h_split(s[2 * s2][2], h02, l02); h_split(s[2 * s2][3], h03, l03);
            h_split(s[2 * s2 + 1][0], h10, l10); h_split(s[2 * s2 + 1][1], h11, l11);
            h_split(s[2 * s2 + 1][2], h12, l12); h_split(s[2 * s2 + 1][3], h13, l13);
            uint32_t a0h = packh2(h00, h01), a1h = packh2(h02, h03);
            uint32_t a2h = packh2(h10, h11), a3h = packh2(h12, h13);
            uint32_t a0l = packh2(l00, l01), a1l = packh2(l02, l03);
            uint32_t a2l = packh2(l10, l11), a3l = packh2(l12, l13);
            #pragma unroll
            for (int j2 = 0; j2 < 8; j2++) {
                const __half* pv = sV + (8 * j2 + r) * VST + 16 * s2 + t2;
                uint32_t b0 = *(const uint32_t*)pv;
                uint32_t b1 = *(const uint32_t*)(pv + 8);
                mma_f16(acc_o[j2], a0l, a1l, a2l, a3l, b0, b1);
                mma_f16(acc_o[j2], a0h, a1h, a2h, a3h, b0, b1);
            }
        }
    }

    float il0 = 1.f / l0, il1 = 1.f / l1;
    #pragma unroll
    for (int j2 = 0; j2 < 8; j2++) {
        #pragma unroll
        for (int e = 0; e < 2; e++) {
            int d = 8 * j2 + t2 + e;
            if (qi0 < TT) {
                size_t mtk = (size_t)(b * TT + qi0) * EE + h * DHEAD + d;
                __half hv, lv; h_split(acc_o[j2][e] * il0, hv, lv);
                oh[mtk] = hv; ol[mtk] = lv;
            }
            if (qi1 < TT) {
                size_t mtk = (size_t)(b * TT + qi1) * EE + h * DHEAD + d;
                __half hv, lv; h_split(acc_o[j2][e + 2] * il1, hv, lv);
                oh[mtk] = hv; ol[mtk] = lv;
            }
        }
    }
}

// ---------------- layernorm: warp per token, single-pass stats ----------------
__global__ void ln_kernel(const float* __restrict__ x, const float* __restrict__ g,
                          const float* __restrict__ bp, __half* __restrict__ yh,
                          __half* __restrict__ yl)
{
    int warp = threadIdx.x >> 5, lane = threadIdx.x & 31;
    int m = blockIdx.x * 8 + warp;
    const float4* xr = reinterpret_cast<const float4*>(x + (size_t)m * EE);

    float4 v[6];
    float s = 0.f, s2 = 0.f;
    #pragma unroll
    for (int k = 0; k < 6; k++) {
        v[k] = xr[lane + 32 * k];
        s  += v[k].x + v[k].y + v[k].z + v[k].w;
        s2 += v[k].x * v[k].x + v[k].y * v[k].y + v[k].z * v[k].z + v[k].w * v[k].w;
    }
    #pragma unroll
    for (int o = 16; o > 0; o >>= 1) {
        s  += __shfl_xor_sync(0xFFFFFFFFu, s, o);
        s2 += __shfl_xor_sync(0xFFFFFFFFu, s2, o);
    }
    float mean = s * (1.0f / EE);
    float inv = rsqrtf(s2 * (1.0f / EE) - mean * mean + 1e-5f);

    __half2* ph = reinterpret_cast<__half2*>(yh + (size_t)m * EE);
    __half2* pl = reinterpret_cast<__half2*>(yl + (size_t)m * EE);
    #pragma unroll
    for (int k = 0; k < 6; k++) {
        float4 gg = reinterpret_cast<const float4*>(g)[lane + 32 * k];
        float4 bb = reinterpret_cast<const float4*>(bp)[lane + 32 * k];
        float o0 = (v[k].x - mean) * inv * gg.x + bb.x;
        float o1 = (v[k].y - mean) * inv * gg.y + bb.y;
        float o2 = (v[k].z - mean) * inv * gg.z + bb.z;
        float o3 = (v[k].w - mean) * inv * gg.w + bb.w;
        __half h0, l0, h1, l1, h2, l2, h3, l3;
        h_split(o0, h0, l0); h_split(o1, h1, l1);
        h_split(o2, h2, l2); h_split(o3, h3, l3);
        int idx = (lane + 32 * k) * 2;
        ph[idx]     = __halves2half2(h0, h1);
        ph[idx + 1] = __halves2half2(h2, h3);
        pl[idx]     = __halves2half2(l0, l1);
        pl[idx + 1] = __halves2half2(l2, l3);
    }
}

// ---------------- head + flux ----------------
__global__ void head_kernel(const float* __restrict__ hbuf,
                            const float* __restrict__ lnw, const float* __restrict__ lnb,
                            const float* __restrict__ hw, const float* __restrict__ hb,
                            const float* __restrict__ mean_s, const float* __restrict__ std_s,
                            float* __restrict__ out)
{
    int warp = threadIdx.x >> 5, lane = threadIdx.x & 31;
    int m = blockIdx.x * 8 + warp;
    const float4* xr = reinterpret_cast<const float4*>(hbuf + (size_t)m * EE);

    float4 v[6];
    float s = 0.f, s2 = 0.f;
    #pragma unroll
    for (int k = 0; k < 6; k++) {
        v[k] = xr[lane + 32 * k];
        s  += v[k].x + v[k].y + v[k].z + v[k].w;
        s2 += v[k].x * v[k].x + v[k].y * v[k].y + v[k].z * v[k].z + v[k].w * v[k].w;
    }
    #pragma unroll
    for (int o = 16; o > 0; o >>= 1) {
        s  += __shfl_xor_sync(0xFFFFFFFFu, s, o);
        s2 += __shfl_xor_sync(0xFFFFFFFFu, s2, o);
    }
    float mean = s * (1.0f / EE);
    float inv = rsqrtf(s2 * (1.0f / EE) - mean * mean + 1e-5f);

    float dot = 0.f;
    #pragma unroll
    for (int k = 0; k < 6; k++) {
        float4 gg = reinterpret_cast<const float4*>(lnw)[lane + 32 * k];
        float4 bb = reinterpret_cast<const float4*>(lnb)[lane + 32 * k];
        float4 ww = reinterpret_cast<const float4*>(hw)[lane + 32 * k];
        dot += ((v[k].x - mean) * inv * gg.x + bb.x) * ww.x;
        dot += ((v[k].y - mean) * inv * gg.y + bb.y) * ww.y;
        dot += ((v[k].z - mean) * inv * gg.z + bb.z) * ww.z;
        dot += ((v[k].w - mean) * inv * gg.w + bb.w) * ww.w;
    }
    #pragma unroll
    for (int o = 16; o > 0; o >>= 1)
        dot += __shfl_xor_sync(0xFFFFFFFFu, dot, o);

    if (lane == 0) {
        float logit = dot + hb[0];
        float lg = logit * std_s[0] + mean_s[0];
        float pf = exp10f(lg) - 1e-8f;
        pf = fminf(fmaxf(pf, 1e-15f), 1.0f);
        out[BB + m] = pf;
    }
}

__global__ void flux_reduce(float* __restrict__ out)
{
    int b = blockIdx.x;
    __shared__ float red[256];
    int tid = threadIdx.x;
    float s = 0.f;
    for (int i = tid; i < TT; i += 256) s += out[BB + b * TT + i];
    red[tid] = s; __syncthreads();
    for (int st = 128; st > 0; st >>= 1) { if (tid < st) red[tid] += red[tid + st]; __syncthreads(); }
    if (tid == 0) out[b] = fmaxf(red[0], 1e-15f);
}

// ---------------- launcher ----------------
extern "C" void kernel_launch(void* const* d_in, const int* in_sizes, int n_in,
                              void* d_out, int out_size)
{
    const float* x        = (const float*)d_in[0];
    const float* sxr_mean = (const float*)d_in[1];
    const float* sxr_std  = (const float*)d_in[2];
    const float* input_w  = (const float*)d_in[3];
    const float* input_b  = (const float*)d_in[4];
    const float* pos_emb  = (const float*)d_in[5];
    const float* ln1_w    = (const float*)d_in[6];
    const float* ln1_b    = (const float*)d_in[7];
    const float* in_w     = (const float*)d_in[8];
    const float* in_b     = (const float*)d_in[9];
    const float* out_w    = (const float*)d_in[10];
    const float* out_b    = (const float*)d_in[11];
    const float* ln2_w    = (const float*)d_in[12];
    const float* ln2_b    = (const float*)d_in[13];
    const float* w1       = (const float*)d_in[14];
    const float* b1       = (const float*)d_in[15];
    const float* w2       = (const float*)d_in[16];
    const float* b2       = (const float*)d_in[17];
    const float* head_lnw = (const float*)d_in[18];
    const float* head_lnb = (const float*)d_in[19];
    const float* head_w   = (const float*)d_in[20];
    const float* head_b   = (const float*)d_in[21];
    float* out = (float*)d_out;

    __half *xph, *xpl, *yh, *yl, *qkvh, *qkvl, *ohb, *olb, *mlph, *mlpl;
    __half *iwh, *inwh, *outwh, *w1h, *w2h;
    float *h;
    cudaGetSymbolAddress((void**)&xph,   g_xp_h);   cudaGetSymbolAddress((void**)&xpl,   g_xp_l);
    cudaGetSymbolAddress((void**)&h,     g_h);
    cudaGetSymbolAddress((void**)&yh,    g_y_h);    cudaGetSymbolAddress((void**)&yl,    g_y_l);
    cudaGetSymbolAddress((void**)&qkvh,  g_qkv_h);  cudaGetSymbolAddress((void**)&qkvl,  g_qkv_l);
    cudaGetSymbolAddress((void**)&ohb,   g_o_h);    cudaGetSymbolAddress((void**)&olb,   g_o_l);
    cudaGetSymbolAddress((void**)&mlph,  g_mlp_h);  cudaGetSymbolAddress((void**)&mlpl,  g_mlp_l);
    cudaGetSymbolAddress((void**)&iwh,   g_iw_h);
    cudaGetSymbolAddress((void**)&inwh,  g_inw_h);
    cudaGetSymbolAddress((void**)&outwh, g_outw_h);
    cudaGetSymbolAddress((void**)&w1h,   g_w1_h);
    cudaGetSymbolAddress((void**)&w2h,   g_w2_h);

    static bool attr_done = false;
    if (!attr_done) {
        cudaFuncSetAttribute(gemm_h, cudaFuncAttributeMaxDynamicSharedMemorySize, 40960);
        cudaFuncSetAttribute(flash_attn, cudaFuncAttributeMaxDynamicSharedMemorySize, 74752);
        attr_done = true;
    }

    // single merged weight conversion launch
    {
        long total = (long)CN0 + CN1 + CN2 + CN3 + CN4;
        int blocks = (int)((total + 255) / 256);
        conv_all<<<blocks, 256>>>(
            (const float4*)input_w, (const float4*)in_w, (const float4*)out_w,
            (const float4*)w1, (const float4*)w2,
            (__half2*)iwh, (__half2*)inwh, (__half2*)outwh,
            (__half2*)w1h, (__half2*)w2h);
    }

    patch_gather<<<(MM * EE + 255) / 256, 256>>>(x, xph, xpl);
    gemm_h<<<dim3(EE / 128, MPAD / 64), 256, 40960>>>(
        xph, xpl, iwh, input_b, pos_emb, h, nullptr, nullptr,
        MPAD, EE, EE, EPI_POS, 0);

    for (int l = 0; l < NLAYERS; l++) {
        const float* l1w = ln1_w + (size_t)l * EE;
        const float* l1b = ln1_b + (size_t)l * EE;
        const float* ib  = in_b  + (size_t)l * 3 * EE;
        const float* ob  = out_b + (size_t)l * EE;
        const float* l2w = ln2_w + (size_t)l * EE;
        const float* l2b = ln2_b + (size_t)l * EE;
        const float* B1  = b1 + (size_t)l * HDIM;
        const float* B2  = b2 + (size_t)l * EE;
        size_t inoff  = (size_t)l * 3 * EE * EE;
        size_t outoff = (size_t)l * EE * EE;
        size_t w1off  = (size_t)l * HDIM * EE;
        size_t w2off  = (size_t)l * EE * HDIM;

        ln_kernel<<<MM / 8, 256>>>(h, l1w, l1b, yh, yl);
        gemm_h<<<dim3(3 * EE / 128, MPAD / 64), 256, 40960>>>(
            yh, yl, inwh + inoff, ib, nullptr,
            nullptr, qkvh, qkvl, MPAD, 3 * EE, EE, EPI_NONE, 1);
        flash_attn<<<dim3(7, NBH), 256, 74752>>>(qkvh, qkvl, ohb, olb);
        gemm_h<<<dim3(EE / 128, MPAD / 64), 256, 40960>>>(
            ohb, olb, outwh + outoff, ob, h,
            h, nullptr, nullptr, MPAD, EE, EE, EPI_RES, 0);
        ln_kernel<<<MM / 8, 256>>>(h, l2w, l2b, yh, yl);
        gemm_h<<<dim3(HDIM / 128, MPAD / 64), 256, 40960>>>(
            yh, yl, w1h + w1off, B1, nullptr,
            nullptr, mlph, mlpl, MPAD, HDIM, EE, EPI_GELU, 1);
        gemm_h<<<dim3(EE / 128, MPAD / 64), 256, 40960>>>(
            mlph, mlpl, w2h + w2off, B2, h,
            h, nullptr, nullptr, MPAD, EE, HDIM, EPI_RES, 0);
    }

    head_kernel<<<MM / 8, 256>>>(h, head_lnw, head_lnb, head_w, head_b,
                                 sxr_mean, sxr_std, out);
    flux_reduce<<<BB, 256>>>(out);
}

// round 12
// speedup vs baseline: 1.0091x; 1.0091x over previous
#include <cuda_runtime.h>
#include <cuda_fp16.h>
#include <math.h>
#include <stdint.h>

// ---------------- problem constants ----------------
#define BB 4
#define TT 784
#define GG 28
#define EE 768
#define HDIM 3072
#define NHEADS 12
#define DHEAD 64
#define NLAYERS 6
#define MM (BB*TT)        // 3136
#define MPAD 3200
#define NBH (BB*NHEADS)   // 48

// ---------------- scratch ----------------
__device__ __half g_xp_h[MPAD * EE];
__device__ __half g_xp_l[MPAD * EE];
__device__ float  g_h[MPAD * EE];
__device__ __half g_y_h[MPAD * EE];
__device__ __half g_y_l[MPAD * EE];
__device__ __half g_qkv_h[MPAD * 3 * EE];
__device__ __half g_qkv_l[MPAD * 3 * EE];
__device__ __half g_o_h[MPAD * EE];
__device__ __half g_o_l[MPAD * EE];
__device__ __half g_mlp_h[MPAD * HDIM];
__device__ __half g_mlp_l[MPAD * HDIM];
// pre-converted weights (fp16; B-side of 2-pass scheme)
__device__ __half g_iw_h[EE * EE];
__device__ __half g_inw_h[NLAYERS * 3 * EE * EE];
__device__ __half g_outw_h[NLAYERS * EE * EE];
__device__ __half g_w1_h[NLAYERS * HDIM * EE];
__device__ __half g_w2_h[NLAYERS * EE * HDIM];

#define EPI_NONE 0
#define EPI_POS  1
#define EPI_RES  2
#define EPI_GELU 3

// ---------------- helpers ----------------
__device__ __forceinline__ void h_split(float v, __half& hi, __half& lo) {
    hi = __float2half_rn(v);
    lo = __float2half_rn(v - __half2float(hi));
}

__device__ __forceinline__ uint32_t packh2(__half a, __half b) {
    __half2 x = __halves2half2(a, b);
    return *reinterpret_cast<uint32_t*>(&x);
}

__device__ __forceinline__ void mma_f16(float d[4],
                                        uint32_t a0, uint32_t a1, uint32_t a2, uint32_t a3,
                                        uint32_t b0, uint32_t b1) {
    asm volatile(
        "mma.sync.aligned.m16n8k16.row.col.f32.f16.f16.f32 "
        "{%0,%1,%2,%3}, {%4,%5,%6,%7}, {%8,%9}, {%0,%1,%2,%3};"
        : "+f"(d[0]), "+f"(d[1]), "+f"(d[2]), "+f"(d[3])
        : "r"(a0), "r"(a1), "r"(a2), "r"(a3), "r"(b0), "r"(b1));
}

#define LDSM_X4(r0, r1, r2, r3, addr) \
    asm volatile("ldmatrix.sync.aligned.m8n8.x4.shared.b16 {%0,%1,%2,%3}, [%4];" \
        : "=r"(r0), "=r"(r1), "=r"(r2), "=r"(r3) : "r"(addr))

__device__ __forceinline__ void cpa16(uint32_t dst, const void* src) {
    asm volatile("cp.async.cg.shared.global [%0], [%1], 16;" :: "r"(dst), "l"(src));
}
__device__ __forceinline__ void cpa16z(uint32_t dst, const void* src, bool valid) {
    int sz = valid ? 16 : 0;
    asm volatile("cp.async.cg.shared.global [%0], [%1], 16, %2;"
                 :: "r"(dst), "l"(src), "r"(sz));
}
__device__ __forceinline__ void cp_commit() { asm volatile("cp.async.commit_group;"); }
__device__ __forceinline__ void cp_wait0() { asm volatile("cp.async.wait_group 0;"); }
__device__ __forceinline__ void cp_wait1() { asm volatile("cp.async.wait_group 1;"); }

// ---------------- epilogue (shared by both GEMMs) ----------------
__device__ __forceinline__ void epi_store(float v, int m, int n, int N, int epi, int split,
                                          const float* bias, const float* extra,
                                          float* C, __half* Ch, __half* Cl)
{
    v += bias[n];
    if (epi == EPI_POS)       v += extra[(size_t)(m % TT) * N + n];
    else if (epi == EPI_RES)  v += extra[(size_t)m * N + n];
    else if (epi == EPI_GELU) v = 0.5f * v * (1.0f + erff(v * 0.70710678118654752f));
    if (split) {
        __half hv, lv; h_split(v, hv, lv);
        Ch[(size_t)m * N + n] = hv;
        Cl[(size_t)m * N + n] = lv;
    } else {
        C[(size_t)m * N + n] = v;
    }
}

// ---------------- merged weight convert ----------------
#define CN0 ((EE*EE)/4)
#define CN1 ((NLAYERS*3*EE*EE)/4)
#define CN2 ((NLAYERS*EE*EE)/4)
#define CN3 ((NLAYERS*HDIM*EE)/4)
#define CN4 ((NLAYERS*EE*HDIM)/4)
__global__ void conv_all(const float4* __restrict__ s0, const float4* __restrict__ s1,
                         const float4* __restrict__ s2, const float4* __restrict__ s3,
                         const float4* __restrict__ s4,
                         __half2* __restrict__ d0, __half2* __restrict__ d1,
                         __half2* __restrict__ d2, __half2* __restrict__ d3,
                         __half2* __restrict__ d4)
{
    long i = (long)blockIdx.x * 256 + threadIdx.x;
    const float4* s; __half2* d; long off;
    if (i < CN0)                                    { s = s0; d = d0; off = i; }
    else if (i < (long)CN0 + CN1)                   { s = s1; d = d1; off = i - CN0; }
    else if (i < (long)CN0 + CN1 + CN2)             { s = s2; d = d2; off = i - CN0 - CN1; }
    else if (i < (long)CN0 + CN1 + CN2 + CN3)       { s = s3; d = d3; off = i - CN0 - CN1 - CN2; }
    else if (i < (long)CN0 + CN1 + CN2 + CN3 + CN4) { s = s4; d = d4; off = i - CN0 - CN1 - CN2 - CN3; }
    else return;
    float4 a = s[off];
    d[2 * off]     = __halves2half2(__float2half_rn(a.x), __float2half_rn(a.y));
    d[2 * off + 1] = __halves2half2(__float2half_rn(a.z), __float2half_rn(a.w));
}

// ---------------- patch gather ----------------
__global__ void patch_gather(const float* __restrict__ x, __half* __restrict__ xh,
                             __half* __restrict__ xl) {
    int idx = blockIdx.x * 256 + threadIdx.x;
    if (idx >= MM * EE) return;
    int j = idx % EE;
    int m = idx / EE;
    int b = m / TT, t = m % TT;
    int gr = t / GG, gc = t % GG;
    int ch = j >> 8, pr = (j >> 4) & 15, pc = j & 15;
    float v = x[(((size_t)b * 448 + gr * 16 + pr) * 448 + (gc * 16 + pc)) * 3 + ch];
    __half hv, lv;
    h_split(v, hv, lv);
    xh[idx] = hv; xl[idx] = lv;
}

// ---------------- GEMM A: 128x128 block tile (wide-N GEMMs) ----------------
#define GST 40
__global__ __launch_bounds__(256, 2)
void gemm128(const __half* __restrict__ Ah, const __half* __restrict__ Al,
             const __half* __restrict__ Wh,
             const float* __restrict__ bias, const float* __restrict__ extra,
             float* __restrict__ C, __half* __restrict__ Ch, __half* __restrict__ Cl,
             int M, int N, int K, int epi, int split)
{
    extern __shared__ __half smh[];
    int tid = threadIdx.x, warp = tid >> 5, lane = tid & 31;
    int r = lane >> 2, t2 = (lane & 3) * 2;
    int m0 = blockIdx.y * 128, n0 = blockIdx.x * 128;
    int wm = (warp & 3) * 32, wn = (warp >> 2) * 64;
    uint32_t smb = (uint32_t)__cvta_generic_to_shared(smh);

    int lrow = tid >> 1, lpart = tid & 1;
    const __half* srcA_h = Ah + (size_t)(m0 + lrow) * K + lpart * 16;
    const __half* srcA_l = Al + (size_t)(m0 + lrow) * K + lpart * 16;
    const __half* srcW_h = Wh + (size_t)(n0 + lrow) * K + lpart * 16;
    uint32_t dbase = smb + lrow * (GST * 2) + lpart * 32;

    int a_row = wm + (lane & 15);
    int a_col = (lane >> 4) << 3;
    int b_row = wn + ((lane >> 4) << 3) + (lane & 7);
    int b_col = ((lane >> 3) & 1) << 3;

    float acc[2][8][4] = {};
    const int KT = K >> 5;

    auto issue = [&](int st, int kc) {
        int k0 = kc << 5;
        uint32_t d = dbase + st * 30720;
        cpa16(d,         srcA_h + k0); cpa16(d + 16,         srcA_h + k0 + 8);
        cpa16(d + 10240, srcA_l + k0); cpa16(d + 10240 + 16, srcA_l + k0 + 8);
        cpa16(d + 20480, srcW_h + k0); cpa16(d + 20480 + 16, srcW_h + k0 + 8);
    };

    issue(0, 0); cp_commit();

    for (int kc = 0; kc < KT; kc++) {
        if (kc + 1 < KT) { issue((kc + 1) & 1, kc + 1); cp_commit(); cp_wait1(); }
        else cp_wait0();
        __syncthreads();

        uint32_t aAh = smb + (kc & 1) * 30720;
        uint32_t aAl = aAh + 10240;
        uint32_t aWh = aAh + 20480;

        #pragma unroll
        for (int s = 0; s < 2; s++) {
            int ks = s * 16;
            uint32_t ah[2][4], al[2][4];
            #pragma unroll
            for (int i2 = 0; i2 < 2; i2++) {
                uint32_t adr = (uint32_t)((a_row + 16 * i2) * GST + ks + a_col) * 2;
                LDSM_X4(ah[i2][0], ah[i2][1], ah[i2][2], ah[i2][3], aAh + adr);
                LDSM_X4(al[i2][0], al[i2][1], al[i2][2], al[i2][3], aAl + adr);
            }
            #pragma unroll
            for (int jj = 0; jj < 4; jj++) {
                uint32_t badr = aWh + (uint32_t)((b_row + 16 * jj) * GST + ks + b_col) * 2;
                uint32_t b00, b01, b10, b11;
                LDSM_X4(b00, b01, b10, b11, badr);
                #pragma unroll
                for (int i2 = 0; i2 < 2; i2++) {
                    mma_f16(acc[i2][2 * jj],     al[i2][0], al[i2][1], al[i2][2], al[i2][3], b00, b01);
                    mma_f16(acc[i2][2 * jj],     ah[i2][0], ah[i2][1], ah[i2][2], ah[i2][3], b00, b01);
                    mma_f16(acc[i2][2 * jj + 1], al[i2][0], al[i2][1], al[i2][2], al[i2][3], b10, b11);
                    mma_f16(acc[i2][2 * jj + 1], ah[i2][0], ah[i2][1], ah[i2][2], ah[i2][3], b10, b11);
                }
            }
        }
        __syncthreads();
    }

    #pragma unroll
    for (int i2 = 0; i2 < 2; i2++) {
        #pragma unroll
        for (int j = 0; j < 8; j++) {
            #pragma unroll
            for (int half = 0; half < 2; half++) {
                int m = m0 + wm + 16 * i2 + r + half * 8;
                #pragma unroll
                for (int e = 0; e < 2; e++) {
                    int n = n0 + wn + 8 * j + t2 + e;
                    epi_store(acc[i2][j][half * 2 + e], m, n, N, epi, split,
                              bias, extra, C, Ch, Cl);
                }
            }
        }
    }
}

// ---------------- GEMM B: 64x128 block tile (narrow-N GEMMs: N==768) ----------------
// 8 warps (4 M x 2 N), warp tile 16x64. Stage: Ah(5120B) Al(5120B) W(10240B) = 20480B.
#define STG64 20480
__global__ __launch_bounds__(256, 3)
void gemm64(const __half* __restrict__ Ah, const __half* __restrict__ Al,
            const __half* __restrict__ Wh,
            const float* __restrict__ bias, const float* __restrict__ extra,
            float* __restrict__ C, __half* __restrict__ Ch, __half* __restrict__ Cl,
            int M, int N, int K, int epi, int split)
{
    extern __shared__ __half smh[];
    int tid = threadIdx.x, warp = tid >> 5, lane = tid & 31;
    int r = lane >> 2, t2 = (lane & 3) * 2;
    int m0 = blockIdx.y * 64, n0 = blockIdx.x * 128;
    int wm = (warp & 3) * 16, wn = (warp >> 2) * 64;
    uint32_t smb = (uint32_t)__cvta_generic_to_shared(smh);

    int a_lrow = tid >> 2, a_seg = tid & 3;
    int w_lrow = tid >> 1, w_seg0 = (tid & 1) * 2;
    const __half* srcA_h = Ah + (size_t)(m0 + a_lrow) * K + a_seg * 8;
    const __half* srcA_l = Al + (size_t)(m0 + a_lrow) * K + a_seg * 8;
    const __half* srcW_h = Wh + (size_t)(n0 + w_lrow) * K;
    uint32_t dA = smb + (uint32_t)(a_lrow * GST + a_seg * 8) * 2;
    uint32_t dW = smb + 10240 + (uint32_t)(w_lrow * GST) * 2;

    int a_row = wm + (lane & 15);
    int a_col = (lane >> 4) << 3;
    int b_row = wn + ((lane >> 4) << 3) + (lane & 7);
    int b_col = ((lane >> 3) & 1) << 3;

    float acc[8][4] = {};
    const int KT = K >> 5;

    auto issue = [&](int st, int kc) {
        int k0 = kc << 5;
        uint32_t sb = st * STG64;
        cpa16(dA + sb,        srcA_h + k0);
        cpa16(dA + sb + 5120, srcA_l + k0);
        cpa16(dW + sb + w_seg0 * 16,       srcW_h + k0 + w_seg0 * 8);
        cpa16(dW + sb + (w_seg0 + 1) * 16, srcW_h + k0 + (w_seg0 + 1) * 8);
    };

    issue(0, 0); cp_commit();

    for (int kc = 0; kc < KT; kc++) {
        if (kc + 1 < KT) { issue((kc + 1) & 1, kc + 1); cp_commit(); cp_wait1(); }
        else cp_wait0();
        __syncthreads();

        uint32_t aAh = smb + (kc & 1) * STG64;
        uint32_t aAl = aAh + 5120;
        uint32_t aWh = aAh + 10240;

        #pragma unroll
        for (int s = 0; s < 2; s++) {
            int ks = s * 16;
            uint32_t ah[4], al[4];
            {
                uint32_t adr = (uint32_t)(a_row * GST + ks + a_col) * 2;
                LDSM_X4(ah[0], ah[1], ah[2], ah[3], aAh + adr);
                LDSM_X4(al[0], al[1], al[2], al[3], aAl + adr);
            }
            #pragma unroll
            for (int jj = 0; jj < 4; jj++) {
                uint32_t badr = aWh + (uint32_t)((b_row + 16 * jj) * GST + ks + b_col) * 2;
                uint32_t b00, b01, b10, b11;
                LDSM_X4(b00, b01, b10, b11, badr);
                mma_f16(acc[2 * jj],     al[0], al[1], al[2], al[3], b00, b01);
                mma_f16(acc[2 * jj],     ah[0], ah[1], ah[2], ah[3], b00, b01);
                mma_f16(acc[2 * jj + 1], al[0], al[1], al[2], al[3], b10, b11);
                mma_f16(acc[2 * jj + 1], ah[0], ah[1], ah[2], ah[3], b10, b11);
            }
        }
        __syncthreads();
    }

    #pragma unroll
    for (int j = 0; j < 8; j++) {
        #pragma unroll
        for (int half = 0; half < 2; half++) {
            int m = m0 + wm + r + half * 8;
            #pragma unroll
            for (int e = 0; e < 2; e++) {
                int n = n0 + wn + 8 * j + t2 + e;
                epi_store(acc[j][half * 2 + e], m, n, N, epi, split,
                          bias, extra, C, Ch, Cl);
            }
        }
    }
}

// ---------------- fused flash attention (unchanged) ----------------
#define QST 72
#define VST 152
__global__ __launch_bounds__(256, 1)
void flash_attn(const __half* __restrict__ qh, const __half* __restrict__ ql,
                __half* __restrict__ oh, __half* __restrict__ ol)
{
    extern __shared__ __half sm[];
    __half* sQh = sm;
    __half* sQl = sm + 9216;
    __half* sKh = sm + 18432;
    __half* sV  = sm + 27648;

    int bh = blockIdx.y, b = bh / NHEADS, h = bh % NHEADS;
    int q0 = blockIdx.x * 128;
    int tid = threadIdx.x, warp = tid >> 5, lane = tid & 31;
    int r = lane >> 2, t2 = (lane & 3) * 2;
    uint32_t smb = (uint32_t)__cvta_generic_to_shared(sm);

    int lrow = tid >> 1, lpart = tid & 1;

    {
        int qrow = q0 + lrow;
        bool qv = qrow < TT;
        const __half* sQg = qh + (size_t)(b * TT + (qv ? qrow : 0)) * (3 * EE) + h * DHEAD + lpart * 32;
        const __half* sQg2 = ql + (size_t)(b * TT + (qv ? qrow : 0)) * (3 * EE) + h * DHEAD + lpart * 32;
        uint32_t d0 = smb + lrow * (QST * 2) + lpart * 64;
        #pragma unroll
        for (int c = 0; c < 4; c++) {
            cpa16z(d0 + c * 16,         sQg  + c * 8, qv);
            cpa16z(d0 + 18432 + c * 16, sQg2 + c * 8, qv);
        }
    }
    cp_commit();

    int qi0 = q0 + 16 * warp + r;
    int qi1 = qi0 + 8;
    int rq0 = qi0 / GG, cq0 = qi0 - rq0 * GG;
    int rq1 = qi1 / GG, cq1 = qi1 - rq1 * GG;

    float m0 = -1e30f, m1 = -1e30f, l0 = 0.f, l1 = 0.f;
    float acc_o[8][4] = {};

    const __half* vbase = qh + (size_t)(b * TT) * (3 * EE) + 2 * EE + h * DHEAD;

    for (int kb = 0; kb < 7; kb++) {
        int k0 = kb * 128;
        __syncthreads();

        {
            int krow = k0 + lrow;
            bool kv2 = krow < TT;
            const __half* sKg = qh + (size_t)(b * TT + (kv2 ? krow : 0)) * (3 * EE) + EE + h * DHEAD + lpart * 32;
            uint32_t dk = smb + 36864 + lrow * (QST * 2) + lpart * 64;
            #pragma unroll
            for (int c = 0; c < 4; c++) cpa16z(dk + c * 16, sKg + c * 8, kv2);
        }
        cp_commit();

        {
            int vd = tid & 63;
            int kbase = (tid >> 6) * 32;
            #pragma unroll
            for (int i = 0; i < 32; i++) {
                int k = kbase + i;
                int tok = k0 + k;
                __half v = (tok < TT) ? vbase[(size_t)tok * (3 * EE) + vd] : __half(0.f);
                sV[vd * VST + k] = v;
            }
        }
        cp_wait0();
        __syncthreads();

        float s[16][4] = {};
        #pragma unroll
        for (int ds = 0; ds < 4; ds++) {
            int ks = ds * 16;
            const __half* pa = sQh + (16 * warp + r) * QST + ks + t2;
            uint32_t ah0 = *(const uint32_t*)pa;
            uint32_t ah1 = *(const uint32_t*)(pa + 8 * QST);
            uint32_t ah2 = *(const uint32_t*)(pa + 8);
            uint32_t ah3 = *(const uint32_t*)(pa + 8 * QST + 8);
            const __half* pl = sQl + (16 * warp + r) * QST + ks + t2;
            uint32_t al0 = *(const uint32_t*)pl;
            uint32_t al1 = *(const uint32_t*)(pl + 8 * QST);
            uint32_t al2 = *(const uint32_t*)(pl + 8);
            uint32_t al3 = *(const uint32_t*)(pl + 8 * QST + 8);
            #pragma unroll
            for (int j = 0; j < 16; j++) {
                const __half* pk = sKh + (8 * j + r) * QST + ks + t2;
                uint32_t b0 = *(const uint32_t*)pk;
                uint32_t b1 = *(const uint32_t*)(pk + 8);
                mma_f16(s[j], al0, al1, al2, al3, b0, b1);
                mma_f16(s[j], ah0, ah1, ah2, ah3, b0, b1);
            }
        }

        float bm0 = -1e30f, bm1 = -1e30f;
        #pragma unroll
        for (int j = 0; j < 16; j++) {
            #pragma unroll
            for (int e = 0; e < 2; e++) {
                int ki = k0 + 8 * j + t2 + e;
                int rk = ki / GG, ck = ki - rk * GG;
                bool oob = ki >= TT;
                float v0 = s[j][e] * 0.125f;
                if (oob || (abs(rq0 - rk) <= 4 && abs(cq0 - ck) <= 4)) v0 = -1e30f;
                s[j][e] = v0;
                bm0 = fmaxf(bm0, v0);
                float v1 = s[j][e + 2] * 0.125f;
                if (oob || (abs(rq1 - rk) <= 4 && abs(cq1 - ck) <= 4)) v1 = -1e30f;
                s[j][e + 2] = v1;
                bm1 = fmaxf(bm1, v1);
            }
        }
        bm0 = fmaxf(bm0, __shfl_xor_sync(0xFFFFFFFFu, bm0, 1));
        bm0 = fmaxf(bm0, __shfl_xor_sync(0xFFFFFFFFu, bm0, 2));
        bm1 = fmaxf(bm1, __shfl_xor_sync(0xFFFFFFFFu, bm1, 1));
        bm1 = fmaxf(bm1, __shfl_xor_sync(0xFFFFFFFFu, bm1, 2));

        float nm0 = fmaxf(m0, bm0), nm1 = fmaxf(m1, bm1);
        float sc0 = __expf(m0 - nm0), sc1 = __expf(m1 - nm1);
        m0 = nm0; m1 = nm1;

        float rs0 = 0.f, rs1 = 0.f;
        #pragma unroll
        for (int j = 0; j < 16; j++) {
            #pragma unroll
            for (int e = 0; e < 2; e++) {
                float p0 = __expf(s[j][e] - m0);
                s[j][e] = p0; rs0 += p0;
                float p1 = __expf(s[j][e + 2] - m1);
                s[j][e + 2] = p1; rs1 += p1;
            }
        }
        rs0 += __shfl_xor_sync(0xFFFFFFFFu, rs0, 1);
        rs0 += __shfl_xor_sync(0xFFFFFFFFu, rs0, 2);
        rs1 += __shfl_xor_sync(0xFFFFFFFFu, rs1, 1);
        rs1 += __shfl_xor_sync(0xFFFFFFFFu, rs1, 2);
        l0 = l0 * sc0 + rs0;
        l1 = l1 * sc1 + rs1;

        #pragma unroll
        for (int j2 = 0; j2 < 8; j2++) {
            acc_o[j2][0] *= sc0; acc_o[j2][1] *= sc0;
            acc_o[j2][2] *= sc1; acc_o[j2][3] *= sc1;
        }

        #pragma unroll
        for (int s2 = 0; s2 < 8; s2++) {
            __half h00, l00, h01, l01, h02, l02, h03, l03;
            __half h10, l10, h11, l11, h12, l12, h13, l13;
            h_split(s[2 * s2][0], h00, l00); h_split(s[2 * s2][1], h01, l01);
            h_split(s[2 * s2][2], h02, l02); h_split(s[2 * s2][3], h03, l03);
            h_split(s[2 * s2 + 1][0], h10, l10); h_split(s[2 * s2 + 1][1], h11, l11);
            h_split(s[2 * s2 + 1][2], h12, l12); h_split(s[2 * s2 + 1][3], h13, l13);
            uint32_t a0h = packh2(h00, h01), a1h = packh2(h02, h03);
            uint32_t a2h = packh2(h10, h11), a3h = packh2(h12, h13);
            uint32_t a0l = packh2(l00, l01), a1l = packh2(l02, l03);
            uint32_t a2l = packh2(l10, l11), a3l = packh2(l12, l13);
            #pragma unroll
            for (int j2 = 0; j2 < 8; j2++) {
                const __half* pv = sV + (8 * j2 + r) * VST + 16 * s2 + t2;
                uint32_t b0 = *(const uint32_t*)pv;
                uint32_t b1 = *(const uint32_t*)(pv + 8);
                mma_f16(acc_o[j2], a0l, a1l, a2l, a3l, b0, b1);
                mma_f16(acc_o[j2], a0h, a1h, a2h, a3h, b0, b1);
            }
        }
    }

    float il0 = 1.f / l0, il1 = 1.f / l1;
    #pragma unroll
    for (int j2 = 0; j2 < 8; j2++) {
        #pragma unroll
        for (int e = 0; e < 2; e++) {
            int d = 8 * j2 + t2 + e;
            if (qi0 < TT) {
                size_t mtk = (size_t)(b * TT + qi0) * EE + h * DHEAD + d;
                __half hv, lv; h_split(acc_o[j2][e] * il0, hv, lv);
                oh[mtk] = hv; ol[mtk] = lv;
            }
            if (qi1 < TT) {
                size_t mtk = (size_t)(b * TT + qi1) * EE + h * DHEAD + d;
                __half hv, lv; h_split(acc_o[j2][e + 2] * il1, hv, lv);
                oh[mtk] = hv; ol[mtk] = lv;
            }
        }
    }
}

// ---------------- layernorm: warp per token ----------------
__global__ void ln_kernel(const float* __restrict__ x, const float* __restrict__ g,
                          const float* __restrict__ bp, __half* __restrict__ yh,
                          __half* __restrict__ yl)
{
    int warp = threadIdx.x >> 5, lane = threadIdx.x & 31;
    int m = blockIdx.x * 8 + warp;
    const float4* xr = reinterpret_cast<const float4*>(x + (size_t)m * EE);

    float4 v[6];
    float s = 0.f, s2 = 0.f;
    #pragma unroll
    for (int k = 0; k < 6; k++) {
        v[k] = xr[lane + 32 * k];
        s  += v[k].x + v[k].y + v[k].z + v[k].w;
        s2 += v[k].x * v[k].x + v[k].y * v[k].y + v[k].z * v[k].z + v[k].w * v[k].w;
    }
    #pragma unroll
    for (int o = 16; o > 0; o >>= 1) {
        s  += __shfl_xor_sync(0xFFFFFFFFu, s, o);
        s2 += __shfl_xor_sync(0xFFFFFFFFu, s2, o);
    }
    float mean = s * (1.0f / EE);
    float inv = rsqrtf(s2 * (1.0f / EE) - mean * mean + 1e-5f);

    __half2* ph = reinterpret_cast<__half2*>(yh + (size_t)m * EE);
    __half2* pl = reinterpret_cast<__half2*>(yl + (size_t)m * EE);
    #pragma unroll
    for (int k = 0; k < 6; k++) {
        float4 gg = reinterpret_cast<const float4*>(g)[lane + 32 * k];
        float4 bb = reinterpret_cast<const float4*>(bp)[lane + 32 * k];
        float o0 = (v[k].x - mean) * inv * gg.x + bb.x;
        float o1 = (v[k].y - mean) * inv * gg.y + bb.y;
        float o2 = (v[k].z - mean) * inv * gg.z + bb.z;
        float o3 = (v[k].w - mean) * inv * gg.w + bb.w;
        __half h0, l0, h1, l1, h2, l2, h3, l3;
        h_split(o0, h0, l0); h_split(o1, h1, l1);
        h_split(o2, h2, l2); h_split(o3, h3, l3);
        int idx = (lane + 32 * k) * 2;
        ph[idx]     = __halves2half2(h0, h1);
        ph[idx + 1] = __halves2half2(h2, h3);
        pl[idx]     = __halves2half2(l0, l1);
        pl[idx + 1] = __halves2half2(l2, l3);
    }
}

// ---------------- head + flux ----------------
__global__ void head_kernel(const float* __restrict__ hbuf,
                            const float* __restrict__ lnw, const float* __restrict__ lnb,
                            const float* __restrict__ hw, const float* __restrict__ hb,
                            const float* __restrict__ mean_s, const float* __restrict__ std_s,
                            float* __restrict__ out)
{
    int warp = threadIdx.x >> 5, lane = threadIdx.x & 31;
    int m = blockIdx.x * 8 + warp;
    const float4* xr = reinterpret_cast<const float4*>(hbuf + (size_t)m * EE);

    float4 v[6];
    float s = 0.f, s2 = 0.f;
    #pragma unroll
    for (int k = 0; k < 6; k++) {
        v[k] = xr[lane + 32 * k];
        s  += v[k].x + v[k].y + v[k].z + v[k].w;
        s2 += v[k].x * v[k].x + v[k].y * v[k].y + v[k].z * v[k].z + v[k].w * v[k].w;
    }
    #pragma unroll
    for (int o = 16; o > 0; o >>= 1) {
        s  += __shfl_xor_sync(0xFFFFFFFFu, s, o);
        s2 += __shfl_xor_sync(0xFFFFFFFFu, s2, o);
    }
    float mean = s * (1.0f / EE);
    float inv = rsqrtf(s2 * (1.0f / EE) - mean * mean + 1e-5f);

    float dot = 0.f;
    #pragma unroll
    for (int k = 0; k < 6; k++) {
        float4 gg = reinterpret_cast<const float4*>(lnw)[lane + 32 * k];
        float4 bb = reinterpret_cast<const float4*>(lnb)[lane + 32 * k];
        float4 ww = reinterpret_cast<const float4*>(hw)[lane + 32 * k];
        dot += ((v[k].x - mean) * inv * gg.x + bb.x) * ww.x;
        dot += ((v[k].y - mean) * inv * gg.y + bb.y) * ww.y;
        dot += ((v[k].z - mean) * inv * gg.z + bb.z) * ww.z;
        dot += ((v[k].w - mean) * inv * gg.w + bb.w) * ww.w;
    }
    #pragma unroll
    for (int o = 16; o > 0; o >>= 1)
        dot += __shfl_xor_sync(0xFFFFFFFFu, dot, o);

    if (lane == 0) {
        float logit = dot + hb[0];
        float lg = logit * std_s[0] + mean_s[0];
        float pf = exp10f(lg) - 1e-8f;
        pf = fminf(fmaxf(pf, 1e-15f), 1.0f);
        out[BB + m] = pf;
    }
}

__global__ void flux_reduce(float* __restrict__ out)
{
    int b = blockIdx.x;
    __shared__ float red[256];
    int tid = threadIdx.x;
    float s = 0.f;
    for (int i = tid; i < TT; i += 256) s += out[BB + b * TT + i];
    red[tid] = s; __syncthreads();
    for (int st = 128; st > 0; st >>= 1) { if (tid < st) red[tid] += red[tid + st]; __syncthreads(); }
    if (tid == 0) out[b] = fmaxf(red[0], 1e-15f);
}

// ---------------- launcher ----------------
extern "C" void kernel_launch(void* const* d_in, const int* in_sizes, int n_in,
                              void* d_out, int out_size)
{
    const float* x        = (const float*)d_in[0];
    const float* sxr_mean = (const float*)d_in[1];
    const float* sxr_std  = (const float*)d_in[2];
    const float* input_w  = (const float*)d_in[3];
    const float* input_b  = (const float*)d_in[4];
    const float* pos_emb  = (const float*)d_in[5];
    const float* ln1_w    = (const float*)d_in[6];
    const float* ln1_b    = (const float*)d_in[7];
    const float* in_w     = (const float*)d_in[8];
    const float* in_b     = (const float*)d_in[9];
    const float* out_w    = (const float*)d_in[10];
    const float* out_b    = (const float*)d_in[11];
    const float* ln2_w    = (const float*)d_in[12];
    const float* ln2_b    = (const float*)d_in[13];
    const float* w1       = (const float*)d_in[14];
    const float* b1       = (const float*)d_in[15];
    const float* w2       = (const float*)d_in[16];
    const float* b2       = (const float*)d_in[17];
    const float* head_lnw = (const float*)d_in[18];
    const float* head_lnb = (const float*)d_in[19];
    const float* head_w   = (const float*)d_in[20];
    const float* head_b   = (const float*)d_in[21];
    float* out = (float*)d_out;

    __half *xph, *xpl, *yh, *yl, *qkvh, *qkvl, *ohb, *olb, *mlph, *mlpl;
    __half *iwh, *inwh, *outwh, *w1h, *w2h;
    float *h;
    cudaGetSymbolAddress((void**)&xph,   g_xp_h);   cudaGetSymbolAddress((void**)&xpl,   g_xp_l);
    cudaGetSymbolAddress((void**)&h,     g_h);
    cudaGetSymbolAddress((void**)&yh,    g_y_h);    cudaGetSymbolAddress((void**)&yl,    g_y_l);
    cudaGetSymbolAddress((void**)&qkvh,  g_qkv_h);  cudaGetSymbolAddress((void**)&qkvl,  g_qkv_l);
    cudaGetSymbolAddress((void**)&ohb,   g_o_h);    cudaGetSymbolAddress((void**)&olb,   g_o_l);
    cudaGetSymbolAddress((void**)&mlph,  g_mlp_h);  cudaGetSymbolAddress((void**)&mlpl,  g_mlp_l);
    cudaGetSymbolAddress((void**)&iwh,   g_iw_h);
    cudaGetSymbolAddress((void**)&inwh,  g_inw_h);
    cudaGetSymbolAddress((void**)&outwh, g_outw_h);
    cudaGetSymbolAddress((void**)&w1h,   g_w1_h);
    cudaGetSymbolAddress((void**)&w2h,   g_w2_h);

    static bool attr_done = false;
    if (!attr_done) {
        cudaFuncSetAttribute(gemm128, cudaFuncAttributeMaxDynamicSharedMemorySize, 61440);
        cudaFuncSetAttribute(gemm64,  cudaFuncAttributeMaxDynamicSharedMemorySize, 40960);
        cudaFuncSetAttribute(flash_attn, cudaFuncAttributeMaxDynamicSharedMemorySize, 74752);
        attr_done = true;
    }

    {
        long total = (long)CN0 + CN1 + CN2 + CN3 + CN4;
        int blocks = (int)((total + 255) / 256);
        conv_all<<<blocks, 256>>>(
            (const float4*)input_w, (const float4*)in_w, (const float4*)out_w,
            (const float4*)w1, (const float4*)w2,
            (__half2*)iwh, (__half2*)inwh, (__half2*)outwh,
            (__half2*)w1h, (__half2*)w2h);
    }

    patch_gather<<<(MM * EE + 255) / 256, 256>>>(x, xph, xpl);
    // embed: N=768 -> narrow kernel
    gemm64<<<dim3(EE / 128, MPAD / 64), 256, 40960>>>(
        xph, xpl, iwh, input_b, pos_emb, h, nullptr, nullptr,
        MPAD, EE, EE, EPI_POS, 0);

    for (int l = 0; l < NLAYERS; l++) {
        const float* l1w = ln1_w + (size_t)l * EE;
        const float* l1b = ln1_b + (size_t)l * EE;
        const float* ib  = in_b  + (size_t)l * 3 * EE;
        const float* ob  = out_b + (size_t)l * EE;
        const float* l2w = ln2_w + (size_t)l * EE;
        const float* l2b = ln2_b + (size_t)l * EE;
        const float* B1  = b1 + (size_t)l * HDIM;
        const float* B2  = b2 + (size_t)l * EE;
        size_t inoff  = (size_t)l * 3 * EE * EE;
        size_t outoff = (size_t)l * EE * EE;
        size_t w1off  = (size_t)l * HDIM * EE;
        size_t w2off  = (size_t)l * EE * HDIM;

        ln_kernel<<<MM / 8, 256>>>(h, l1w, l1b, yh, yl);
        // qkv: N=2304 -> wide kernel
        gemm128<<<dim3(3 * EE / 128, MPAD / 128), 256, 61440>>>(
            yh, yl, inwh + inoff, ib, nullptr,
            nullptr, qkvh, qkvl, MPAD, 3 * EE, EE, EPI_NONE, 1);
        flash_attn<<<dim3(7, NBH), 256, 74752>>>(qkvh, qkvl, ohb, olb);
        // proj: N=768 -> narrow kernel
        gemm64<<<dim3(EE / 128, MPAD / 64), 256, 40960>>>(
            ohb, olb, outwh + outoff, ob, h,
            h, nullptr, nullptr, MPAD, EE, EE, EPI_RES, 0);
        ln_kernel<<<MM / 8, 256>>>(h, l2w, l2b, yh, yl);
        // mlp1: N=3072 -> wide kernel
        gemm128<<<dim3(HDIM / 128, MPAD / 128), 256, 61440>>>(
            yh, yl, w1h + w1off, B1, nullptr,
            nullptr, mlph, mlpl, MPAD, HDIM, EE, EPI_GELU, 1);
        // mlp2: N=768 -> narrow kernel
        gemm64<<<dim3(EE / 128, MPAD / 64), 256, 40960>>>(
            mlph, mlpl, w2h + w2off, B2, h,
            h, nullptr, nullptr, MPAD, EE, HDIM, EPI_RES, 0);
    }

    head_kernel<<<MM / 8, 256>>>(h, head_lnw, head_lnb, head_w, head_b,
                                 sxr_mean, sxr_std, out);
    flux_reduce<<<BB, 256>>>(out);
}

// round 13
// speedup vs baseline: 1.4355x; 1.4225x over previous
#include <cuda_runtime.h>
#include <cuda_fp16.h>
#include <math.h>
#include <stdint.h>

// ---------------- problem constants ----------------
#define BB 4
#define TT 784
#define GG 28
#define EE 768
#define HDIM 3072
#define NHEADS 12
#define DHEAD 64
#define NLAYERS 6
#define MM (BB*TT)        // 3136
#define MPAD 3200
#define NBH (BB*NHEADS)   // 48

// ---------------- scratch ----------------
__device__ __half g_xp[MPAD * EE];
__device__ float  g_h[MPAD * EE];
__device__ __half g_y[MPAD * EE];
__device__ __half g_qkv[MPAD * 3 * EE];
__device__ __half g_o[MPAD * EE];
__device__ __half g_mlp[MPAD * HDIM];
// pre-converted fp16 weights
__device__ __half g_iw_h[EE * EE];
__device__ __half g_inw_h[NLAYERS * 3 * EE * EE];
__device__ __half g_outw_h[NLAYERS * EE * EE];
__device__ __half g_w1_h[NLAYERS * HDIM * EE];
__device__ __half g_w2_h[NLAYERS * EE * HDIM];

#define EPI_NONE 0
#define EPI_POS  1
#define EPI_RES  2
#define EPI_GELU 3

// ---------------- helpers ----------------
__device__ __forceinline__ uint32_t packh2(__half a, __half b) {
    __half2 x = __halves2half2(a, b);
    return *reinterpret_cast<uint32_t*>(&x);
}

__device__ __forceinline__ void mma_f16(float d[4],
                                        uint32_t a0, uint32_t a1, uint32_t a2, uint32_t a3,
                                        uint32_t b0, uint32_t b1) {
    asm volatile(
        "mma.sync.aligned.m16n8k16.row.col.f32.f16.f16.f32 "
        "{%0,%1,%2,%3}, {%4,%5,%6,%7}, {%8,%9}, {%0,%1,%2,%3};"
        : "+f"(d[0]), "+f"(d[1]), "+f"(d[2]), "+f"(d[3])
        : "r"(a0), "r"(a1), "r"(a2), "r"(a3), "r"(b0), "r"(b1));
}

#define LDSM_X4(r0, r1, r2, r3, addr) \
    asm volatile("ldmatrix.sync.aligned.m8n8.x4.shared.b16 {%0,%1,%2,%3}, [%4];" \
        : "=r"(r0), "=r"(r1), "=r"(r2), "=r"(r3) : "r"(addr))

__device__ __forceinline__ void cpa16(uint32_t dst, const void* src) {
    asm volatile("cp.async.cg.shared.global [%0], [%1], 16;" :: "r"(dst), "l"(src));
}
__device__ __forceinline__ void cpa16z(uint32_t dst, const void* src, bool valid) {
    int sz = valid ? 16 : 0;
    asm volatile("cp.async.cg.shared.global [%0], [%1], 16, %2;"
                 :: "r"(dst), "l"(src), "r"(sz));
}
__device__ __forceinline__ void cp_commit() { asm volatile("cp.async.commit_group;"); }
__device__ __forceinline__ void cp_wait0() { asm volatile("cp.async.wait_group 0;"); }
__device__ __forceinline__ void cp_wait1() { asm volatile("cp.async.wait_group 1;"); }

// ---------------- epilogue ----------------
__device__ __forceinline__ void epi_store(float v, int m, int n, int N, int epi, int split,
                                          const float* bias, const float* extra,
                                          float* C, __half* Ch)
{
    v += bias[n];
    if (epi == EPI_POS)       v += extra[(size_t)(m % TT) * N + n];
    else if (epi == EPI_RES)  v += extra[(size_t)m * N + n];
    else if (epi == EPI_GELU) v = 0.5f * v * (1.0f + erff(v * 0.70710678118654752f));
    if (split) Ch[(size_t)m * N + n] = __float2half_rn(v);
    else       C[(size_t)m * N + n] = v;
}

// ---------------- merged weight convert ----------------
#define CN0 ((EE*EE)/4)
#define CN1 ((NLAYERS*3*EE*EE)/4)
#define CN2 ((NLAYERS*EE*EE)/4)
#define CN3 ((NLAYERS*HDIM*EE)/4)
#define CN4 ((NLAYERS*EE*HDIM)/4)
__global__ void conv_all(const float4* __restrict__ s0, const float4* __restrict__ s1,
                         const float4* __restrict__ s2, const float4* __restrict__ s3,
                         const float4* __restrict__ s4,
                         __half2* __restrict__ d0, __half2* __restrict__ d1,
                         __half2* __restrict__ d2, __half2* __restrict__ d3,
                         __half2* __restrict__ d4)
{
    long i = (long)blockIdx.x * 256 + threadIdx.x;
    const float4* s; __half2* d; long off;
    if (i < CN0)                                    { s = s0; d = d0; off = i; }
    else if (i < (long)CN0 + CN1)                   { s = s1; d = d1; off = i - CN0; }
    else if (i < (long)CN0 + CN1 + CN2)             { s = s2; d = d2; off = i - CN0 - CN1; }
    else if (i < (long)CN0 + CN1 + CN2 + CN3)       { s = s3; d = d3; off = i - CN0 - CN1 - CN2; }
    else if (i < (long)CN0 + CN1 + CN2 + CN3 + CN4) { s = s4; d = d4; off = i - CN0 - CN1 - CN2 - CN3; }
    else return;
    float4 a = s[off];
    d[2 * off]     = __halves2half2(__float2half_rn(a.x), __float2half_rn(a.y));
    d[2 * off + 1] = __halves2half2(__float2half_rn(a.z), __float2half_rn(a.w));
}

// ---------------- patch gather ----------------
__global__ void patch_gather(const float* __restrict__ x, __half* __restrict__ xh) {
    int idx = blockIdx.x * 256 + threadIdx.x;
    if (idx >= MM * EE) return;
    int j = idx % EE;
    int m = idx / EE;
    int b = m / TT, t = m % TT;
    int gr = t / GG, gc = t % GG;
    int ch = j >> 8, pr = (j >> 4) & 15, pc = j & 15;
    float v = x[(((size_t)b * 448 + gr * 16 + pr) * 448 + (gc * 16 + pc)) * 3 + ch];
    xh[idx] = __float2half_rn(v);
}

// ---------------- GEMM A: 128x128 block tile, pure fp16 single pass ----------------
#define GST 40
__global__ __launch_bounds__(256, 2)
void gemm128(const __half* __restrict__ Ah, const __half* __restrict__ Wh,
             const float* __restrict__ bias, const float* __restrict__ extra,
             float* __restrict__ C, __half* __restrict__ Ch,
             int M, int N, int K, int epi, int split)
{
    extern __shared__ __half smh[];
    int tid = threadIdx.x, warp = tid >> 5, lane = tid & 31;
    int r = lane >> 2, t2 = (lane & 3) * 2;
    int m0 = blockIdx.y * 128, n0 = blockIdx.x * 128;
    int wm = (warp & 3) * 32, wn = (warp >> 2) * 64;
    uint32_t smb = (uint32_t)__cvta_generic_to_shared(smh);

    int lrow = tid >> 1, lpart = tid & 1;
    const __half* srcA = Ah + (size_t)(m0 + lrow) * K + lpart * 16;
    const __half* srcW = Wh + (size_t)(n0 + lrow) * K + lpart * 16;
    uint32_t dbase = smb + lrow * (GST * 2) + lpart * 32;

    int a_row = wm + (lane & 15);
    int a_col = (lane >> 4) << 3;
    int b_row = wn + ((lane >> 4) << 3) + (lane & 7);
    int b_col = ((lane >> 3) & 1) << 3;

    float acc[2][8][4] = {};
    const int KT = K >> 5;

    auto issue = [&](int st, int kc) {
        int k0 = kc << 5;
        uint32_t d = dbase + st * 20480;
        cpa16(d,         srcA + k0); cpa16(d + 16,         srcA + k0 + 8);
        cpa16(d + 10240, srcW + k0); cpa16(d + 10240 + 16, srcW + k0 + 8);
    };

    issue(0, 0); cp_commit();

    for (int kc = 0; kc < KT; kc++) {
        if (kc + 1 < KT) { issue((kc + 1) & 1, kc + 1); cp_commit(); cp_wait1(); }
        else cp_wait0();
        __syncthreads();

        uint32_t aA = smb + (kc & 1) * 20480;
        uint32_t aW = aA + 10240;

        #pragma unroll
        for (int s = 0; s < 2; s++) {
            int ks = s * 16;
            uint32_t ah[2][4];
            #pragma unroll
            for (int i2 = 0; i2 < 2; i2++) {
                uint32_t adr = (uint32_t)((a_row + 16 * i2) * GST + ks + a_col) * 2;
                LDSM_X4(ah[i2][0], ah[i2][1], ah[i2][2], ah[i2][3], aA + adr);
            }
            #pragma unroll
            for (int jj = 0; jj < 4; jj++) {
                uint32_t badr = aW + (uint32_t)((b_row + 16 * jj) * GST + ks + b_col) * 2;
                uint32_t b00, b01, b10, b11;
                LDSM_X4(b00, b01, b10, b11, badr);
                #pragma unroll
                for (int i2 = 0; i2 < 2; i2++) {
                    mma_f16(acc[i2][2 * jj],     ah[i2][0], ah[i2][1], ah[i2][2], ah[i2][3], b00, b01);
                    mma_f16(acc[i2][2 * jj + 1], ah[i2][0], ah[i2][1], ah[i2][2], ah[i2][3], b10, b11);
                }
            }
        }
        __syncthreads();
    }

    #pragma unroll
    for (int i2 = 0; i2 < 2; i2++) {
        #pragma unroll
        for (int j = 0; j < 8; j++) {
            #pragma unroll
            for (int half = 0; half < 2; half++) {
                int m = m0 + wm + 16 * i2 + r + half * 8;
                #pragma unroll
                for (int e = 0; e < 2; e++) {
                    int n = n0 + wn + 8 * j + t2 + e;
                    epi_store(acc[i2][j][half * 2 + e], m, n, N, epi, split,
                              bias, extra, C, Ch);
                }
            }
        }
    }
}

// ---------------- GEMM B: 64x128 block tile, pure fp16 single pass ----------------
#define STG64 15360
__global__ __launch_bounds__(256, 3)
void gemm64(const __half* __restrict__ Ah, const __half* __restrict__ Wh,
            const float* __restrict__ bias, const float* __restrict__ extra,
            float* __restrict__ C, __half* __restrict__ Ch,
            int M, int N, int K, int epi, int split)
{
    extern __shared__ __half smh[];
    int tid = threadIdx.x, warp = tid >> 5, lane = tid & 31;
    int r = lane >> 2, t2 = (lane & 3) * 2;
    int m0 = blockIdx.y * 64, n0 = blockIdx.x * 128;
    int wm = (warp & 3) * 16, wn = (warp >> 2) * 64;
    uint32_t smb = (uint32_t)__cvta_generic_to_shared(smh);

    int a_lrow = tid >> 2, a_seg = tid & 3;
    int w_lrow = tid >> 1, w_seg0 = (tid & 1) * 2;
    const __half* srcA = Ah + (size_t)(m0 + a_lrow) * K + a_seg * 8;
    const __half* srcW = Wh + (size_t)(n0 + w_lrow) * K;
    uint32_t dA = smb + (uint32_t)(a_lrow * GST + a_seg * 8) * 2;
    uint32_t dW = smb + 5120 + (uint32_t)(w_lrow * GST) * 2;

    int a_row = wm + (lane & 15);
    int a_col = (lane >> 4) << 3;
    int b_row = wn + ((lane >> 4) << 3) + (lane & 7);
    int b_col = ((lane >> 3) & 1) << 3;

    float acc[8][4] = {};
    const int KT = K >> 5;

    auto issue = [&](int st, int kc) {
        int k0 = kc << 5;
        uint32_t sb = st * STG64;
        cpa16(dA + sb, srcA + k0);
        cpa16(dW + sb + w_seg0 * 16,       srcW + k0 + w_seg0 * 8);
        cpa16(dW + sb + (w_seg0 + 1) * 16, srcW + k0 + (w_seg0 + 1) * 8);
    };

    issue(0, 0); cp_commit();

    for (int kc = 0; kc < KT; kc++) {
        if (kc + 1 < KT) { issue((kc + 1) & 1, kc + 1); cp_commit(); cp_wait1(); }
        else cp_wait0();
        __syncthreads();

        uint32_t aA = smb + (kc & 1) * STG64;
        uint32_t aW = aA + 5120;

        #pragma unroll
        for (int s = 0; s < 2; s++) {
            int ks = s * 16;
            uint32_t ah[4];
            {
                uint32_t adr = (uint32_t)(a_row * GST + ks + a_col) * 2;
                LDSM_X4(ah[0], ah[1], ah[2], ah[3], aA + adr);
            }
            #pragma unroll
            for (int jj = 0; jj < 4; jj++) {
                uint32_t badr = aW + (uint32_t)((b_row + 16 * jj) * GST + ks + b_col) * 2;
                uint32_t b00, b01, b10, b11;
                LDSM_X4(b00, b01, b10, b11, badr);
                mma_f16(acc[2 * jj],     ah[0], ah[1], ah[2], ah[3], b00, b01);
                mma_f16(acc[2 * jj + 1], ah[0], ah[1], ah[2], ah[3], b10, b11);
            }
        }
        __syncthreads();
    }

    #pragma unroll
    for (int j = 0; j < 8; j++) {
        #pragma unroll
        for (int half = 0; half < 2; half++) {
            int m = m0 + wm + r + half * 8;
            #pragma unroll
            for (int e = 0; e < 2; e++) {
                int n = n0 + wn + 8 * j + t2 + e;
                epi_store(acc[j][half * 2 + e], m, n, N, epi, split,
                          bias, extra, C, Ch);
            }
        }
    }
}

// ---------------- fused flash attention, pure fp16 single pass ----------------
#define QST 72
#define VST 152
__global__ __launch_bounds__(256, 1)
void flash_attn(const __half* __restrict__ qkv, __half* __restrict__ oh)
{
    extern __shared__ __half sm[];
    __half* sQ = sm;                  // 128*72 halves
    __half* sK = sm + 9216;           // 128*72
    __half* sV = sm + 18432;          // 64*152  [d][k]

    int bh = blockIdx.y, b = bh / NHEADS, h = bh % NHEADS;
    int q0 = blockIdx.x * 128;
    int tid = threadIdx.x, warp = tid >> 5, lane = tid & 31;
    int r = lane >> 2, t2 = (lane & 3) * 2;
    uint32_t smb = (uint32_t)__cvta_generic_to_shared(sm);

    int lrow = tid >> 1, lpart = tid & 1;

    // ---- load Q tile (once) ----
    {
        int qrow = q0 + lrow;
        bool qv = qrow < TT;
        const __half* sQg = qkv + (size_t)(b * TT + (qv ? qrow : 0)) * (3 * EE) + h * DHEAD + lpart * 32;
        uint32_t d0 = smb + lrow * (QST * 2) + lpart * 64;
        #pragma unroll
        for (int c = 0; c < 4; c++) cpa16z(d0 + c * 16, sQg + c * 8, qv);
    }
    cp_commit();

    int qi0 = q0 + 16 * warp + r;
    int qi1 = qi0 + 8;
    int rq0 = qi0 / GG, cq0 = qi0 - rq0 * GG;
    int rq1 = qi1 / GG, cq1 = qi1 - rq1 * GG;

    float m0 = -1e30f, m1 = -1e30f, l0 = 0.f, l1 = 0.f;
    float acc_o[8][4] = {};

    const __half* vbase = qkv + (size_t)(b * TT) * (3 * EE) + 2 * EE + h * DHEAD;

    for (int kb = 0; kb < 7; kb++) {
        int k0 = kb * 128;
        __syncthreads();

        // ---- load K tile ----
        {
            int krow = k0 + lrow;
            bool kv2 = krow < TT;
            const __half* sKg = qkv + (size_t)(b * TT + (kv2 ? krow : 0)) * (3 * EE) + EE + h * DHEAD + lpart * 32;
            uint32_t dk = smb + 18432 + lrow * (QST * 2) + lpart * 64;
            #pragma unroll
            for (int c = 0; c < 4; c++) cpa16z(dk + c * 16, sKg + c * 8, kv2);
        }
        cp_commit();

        // ---- load V tile transposed [d][k] ----
        {
            int vd = tid & 63;
            int kbase = (tid >> 6) * 32;
            #pragma unroll
            for (int i = 0; i < 32; i++) {
                int k = kbase + i;
                int tok = k0 + k;
                __half v = (tok < TT) ? vbase[(size_t)tok * (3 * EE) + vd] : __half(0.f);
                sV[vd * VST + k] = v;
            }
        }
        cp_wait0();
        __syncthreads();

        // ---- S = Q.K^T single pass ----
        float s[16][4] = {};
        #pragma unroll
        for (int ds = 0; ds < 4; ds++) {
            int ks = ds * 16;
            const __half* pa = sQ + (16 * warp + r) * QST + ks + t2;
            uint32_t a0 = *(const uint32_t*)pa;
            uint32_t a1 = *(const uint32_t*)(pa + 8 * QST);
            uint32_t a2 = *(const uint32_t*)(pa + 8);
            uint32_t a3 = *(const uint32_t*)(pa + 8 * QST + 8);
            #pragma unroll
            for (int j = 0; j < 16; j++) {
                const __half* pk = sK + (8 * j + r) * QST + ks + t2;
                uint32_t b0 = *(const uint32_t*)pk;
                uint32_t b1 = *(const uint32_t*)(pk + 8);
                mma_f16(s[j], a0, a1, a2, a3, b0, b1);
            }
        }

        // ---- mask + scale, block row max ----
        float bm0 = -1e30f, bm1 = -1e30f;
        #pragma unroll
        for (int j = 0; j < 16; j++) {
            #pragma unroll
            for (int e = 0; e < 2; e++) {
                int ki = k0 + 8 * j + t2 + e;
                int rk = ki / GG, ck = ki - rk * GG;
                bool oob = ki >= TT;
                float v0 = s[j][e] * 0.125f;
                if (oob || (abs(rq0 - rk) <= 4 && abs(cq0 - ck) <= 4)) v0 = -1e30f;
                s[j][e] = v0;
                bm0 = fmaxf(bm0, v0);
                float v1 = s[j][e + 2] * 0.125f;
                if (oob || (abs(rq1 - rk) <= 4 && abs(cq1 - ck) <= 4)) v1 = -1e30f;
                s[j][e + 2] = v1;
                bm1 = fmaxf(bm1, v1);
            }
        }
        bm0 = fmaxf(bm0, __shfl_xor_sync(0xFFFFFFFFu, bm0, 1));
        bm0 = fmaxf(bm0, __shfl_xor_sync(0xFFFFFFFFu, bm0, 2));
        bm1 = fmaxf(bm1, __shfl_xor_sync(0xFFFFFFFFu, bm1, 1));
        bm1 = fmaxf(bm1, __shfl_xor_sync(0xFFFFFFFFu, bm1, 2));

        float nm0 = fmaxf(m0, bm0), nm1 = fmaxf(m1, bm1);
        float sc0 = __expf(m0 - nm0), sc1 = __expf(m1 - nm1);
        m0 = nm0; m1 = nm1;

        float rs0 = 0.f, rs1 = 0.f;
        #pragma unroll
        for (int j = 0; j < 16; j++) {
            #pragma unroll
            for (int e = 0; e < 2; e++) {
                float p0 = __expf(s[j][e] - m0);
                s[j][e] = p0; rs0 += p0;
                float p1 = __expf(s[j][e + 2] - m1);
                s[j][e + 2] = p1; rs1 += p1;
            }
        }
        rs0 += __shfl_xor_sync(0xFFFFFFFFu, rs0, 1);
        rs0 += __shfl_xor_sync(0xFFFFFFFFu, rs0, 2);
        rs1 += __shfl_xor_sync(0xFFFFFFFFu, rs1, 1);
        rs1 += __shfl_xor_sync(0xFFFFFFFFu, rs1, 2);
        l0 = l0 * sc0 + rs0;
        l1 = l1 * sc1 + rs1;

        #pragma unroll
        for (int j2 = 0; j2 < 8; j2++) {
            acc_o[j2][0] *= sc0; acc_o[j2][1] *= sc0;
            acc_o[j2][2] *= sc1; acc_o[j2][3] *= sc1;
        }

        // ---- O += P.V single pass (P -> fp16) ----
        #pragma unroll
        for (int s2 = 0; s2 < 8; s2++) {
            uint32_t a0 = packh2(__float2half_rn(s[2 * s2][0]),     __float2half_rn(s[2 * s2][1]));
            uint32_t a1 = packh2(__float2half_rn(s[2 * s2][2]),     __float2half_rn(s[2 * s2][3]));
            uint32_t a2 = packh2(__float2half_rn(s[2 * s2 + 1][0]), __float2half_rn(s[2 * s2 + 1][1]));
            uint32_t a3 = packh2(__float2half_rn(s[2 * s2 + 1][2]), __float2half_rn(s[2 * s2 + 1][3]));
            #pragma unroll
            for (int j2 = 0; j2 < 8; j2++) {
                const __half* pv = sV + (8 * j2 + r) * VST + 16 * s2 + t2;
                uint32_t b0 = *(const uint32_t*)pv;
                uint32_t b1 = *(const uint32_t*)(pv + 8);
                mma_f16(acc_o[j2], a0, a1, a2, a3, b0, b1);
            }
        }
    }

    // ---- epilogue ----
    float il0 = 1.f / l0, il1 = 1.f / l1;
    #pragma unroll
    for (int j2 = 0; j2 < 8; j2++) {
        #pragma unroll
        for (int e = 0; e < 2; e++) {
            int d = 8 * j2 + t2 + e;
            if (qi0 < TT)
                oh[(size_t)(b * TT + qi0) * EE + h * DHEAD + d] = __float2half_rn(acc_o[j2][e] * il0);
            if (qi1 < TT)
                oh[(size_t)(b * TT + qi1) * EE + h * DHEAD + d] = __float2half_rn(acc_o[j2][e + 2] * il1);
        }
    }
}

// ---------------- layernorm: warp per token ----------------
__global__ void ln_kernel(const float* __restrict__ x, const float* __restrict__ g,
                          const float* __restrict__ bp, __half* __restrict__ yh)
{
    int warp = threadIdx.x >> 5, lane = threadIdx.x & 31;
    int m = blockIdx.x * 8 + warp;
    const float4* xr = reinterpret_cast<const float4*>(x + (size_t)m * EE);

    float4 v[6];
    float s = 0.f, s2 = 0.f;
    #pragma unroll
    for (int k = 0; k < 6; k++) {
        v[k] = xr[lane + 32 * k];
        s  += v[k].x + v[k].y + v[k].z + v[k].w;
        s2 += v[k].x * v[k].x + v[k].y * v[k].y + v[k].z * v[k].z + v[k].w * v[k].w;
    }
    #pragma unroll
    for (int o = 16; o > 0; o >>= 1) {
        s  += __shfl_xor_sync(0xFFFFFFFFu, s, o);
        s2 += __shfl_xor_sync(0xFFFFFFFFu, s2, o);
    }
    float mean = s * (1.0f / EE);
    float inv = rsqrtf(s2 * (1.0f / EE) - mean * mean + 1e-5f);

    __half2* ph = reinterpret_cast<__half2*>(yh + (size_t)m * EE);
    #pragma unroll
    for (int k = 0; k < 6; k++) {
        float4 gg = reinterpret_cast<const float4*>(g)[lane + 32 * k];
        float4 bb = reinterpret_cast<const float4*>(bp)[lane + 32 * k];
        float o0 = (v[k].x - mean) * inv * gg.x + bb.x;
        float o1 = (v[k].y - mean) * inv * gg.y + bb.y;
        float o2 = (v[k].z - mean) * inv * gg.z + bb.z;
        float o3 = (v[k].w - mean) * inv * gg.w + bb.w;
        int idx = (lane + 32 * k) * 2;
        ph[idx]     = __halves2half2(__float2half_rn(o0), __float2half_rn(o1));
        ph[idx + 1] = __halves2half2(__float2half_rn(o2), __float2half_rn(o3));
    }
}

// ---------------- head + flux ----------------
__global__ void head_kernel(const float* __restrict__ hbuf,
                            const float* __restrict__ lnw, const float* __restrict__ lnb,
                            const float* __restrict__ hw, const float* __restrict__ hb,
                            const float* __restrict__ mean_s, const float* __restrict__ std_s,
                            float* __restrict__ out)
{
    int warp = threadIdx.x >> 5, lane = threadIdx.x & 31;
    int m = blockIdx.x * 8 + warp;
    const float4* xr = reinterpret_cast<const float4*>(hbuf + (size_t)m * EE);

    float4 v[6];
    float s = 0.f, s2 = 0.f;
    #pragma unroll
    for (int k = 0; k < 6; k++) {
        v[k] = xr[lane + 32 * k];
        s  += v[k].x + v[k].y + v[k].z + v[k].w;
        s2 += v[k].x * v[k].x + v[k].y * v[k].y + v[k].z * v[k].z + v[k].w * v[k].w;
    }
    #pragma unroll
    for (int o = 16; o > 0; o >>= 1) {
        s  += __shfl_xor_sync(0xFFFFFFFFu, s, o);
        s2 += __shfl_xor_sync(0xFFFFFFFFu, s2, o);
    }
    float mean = s * (1.0f / EE);
    float inv = rsqrtf(s2 * (1.0f / EE) - mean * mean + 1e-5f);

    float dot = 0.f;
    #pragma unroll
    for (int k = 0; k < 6; k++) {
        float4 gg = reinterpret_cast<const float4*>(lnw)[lane + 32 * k];
        float4 bb = reinterpret_cast<const float4*>(lnb)[lane + 32 * k];
        float4 ww = reinterpret_cast<const float4*>(hw)[lane + 32 * k];
        dot += ((v[k].x - mean) * inv * gg.x + bb.x) * ww.x;
        dot += ((v[k].y - mean) * inv * gg.y + bb.y) * ww.y;
        dot += ((v[k].z - mean) * inv * gg.z + bb.z) * ww.z;
        dot += ((v[k].w - mean) * inv * gg.w + bb.w) * ww.w;
    }
    #pragma unroll
    for (int o = 16; o > 0; o >>= 1)
        dot += __shfl_xor_sync(0xFFFFFFFFu, dot, o);

    if (lane == 0) {
        float logit = dot + hb[0];
        float lg = logit * std_s[0] + mean_s[0];
        float pf = exp10f(lg) - 1e-8f;
        pf = fminf(fmaxf(pf, 1e-15f), 1.0f);
        out[BB + m] = pf;
    }
}

__global__ void flux_reduce(float* __restrict__ out)
{
    int b = blockIdx.x;
    __shared__ float red[256];
    int tid = threadIdx.x;
    float s = 0.f;
    for (int i = tid; i < TT; i += 256) s += out[BB + b * TT + i];
    red[tid] = s; __syncthreads();
    for (int st = 128; st > 0; st >>= 1) { if (tid < st) red[tid] += red[tid + st]; __syncthreads(); }
    if (tid == 0) out[b] = fmaxf(red[0], 1e-15f);
}

// ---------------- launcher ----------------
extern "C" void kernel_launch(void* const* d_in, const int* in_sizes, int n_in,
                              void* d_out, int out_size)
{
    const float* x        = (const float*)d_in[0];
    const float* sxr_mean = (const float*)d_in[1];
    const float* sxr_std  = (const float*)d_in[2];
    const float* input_w  = (const float*)d_in[3];
    const float* input_b  = (const float*)d_in[4];
    const float* pos_emb  = (const float*)d_in[5];
    const float* ln1_w    = (const float*)d_in[6];
    const float* ln1_b    = (const float*)d_in[7];
    const float* in_w     = (const float*)d_in[8];
    const float* in_b     = (const float*)d_in[9];
    const float* out_w    = (const float*)d_in[10];
    const float* out_b    = (const float*)d_in[11];
    const float* ln2_w    = (const float*)d_in[12];
    const float* ln2_b    = (const float*)d_in[13];
    const float* w1       = (const float*)d_in[14];
    const float* b1       = (const float*)d_in[15];
    const float* w2       = (const float*)d_in[16];
    const float* b2       = (const float*)d_in[17];
    const float* head_lnw = (const float*)d_in[18];
    const float* head_lnb = (const float*)d_in[19];
    const float* head_w   = (const float*)d_in[20];
    const float* head_b   = (const float*)d_in[21];
    float* out = (float*)d_out;

    __half *xp, *y, *qkv, *o, *mlp;
    __half *iwh, *inwh, *outwh, *w1h, *w2h;
    float *h;
    cudaGetSymbolAddress((void**)&xp,    g_xp);
    cudaGetSymbolAddress((void**)&h,     g_h);
    cudaGetSymbolAddress((void**)&y,     g_y);
    cudaGetSymbolAddress((void**)&qkv,   g_qkv);
    cudaGetSymbolAddress((void**)&o,     g_o);
    cudaGetSymbolAddress((void**)&mlp,   g_mlp);
    cudaGetSymbolAddress((void**)&iwh,   g_iw_h);
    cudaGetSymbolAddress((void**)&inwh,  g_inw_h);
    cudaGetSymbolAddress((void**)&outwh, g_outw_h);
    cudaGetSymbolAddress((void**)&w1h,   g_w1_h);
    cudaGetSymbolAddress((void**)&w2h,   g_w2_h);

    static bool attr_done = false;
    if (!attr_done) {
        cudaFuncSetAttribute(gemm128, cudaFuncAttributeMaxDynamicSharedMemorySize, 40960);
        cudaFuncSetAttribute(gemm64,  cudaFuncAttributeMaxDynamicSharedMemorySize, 30720);
        cudaFuncSetAttribute(flash_attn, cudaFuncAttributeMaxDynamicSharedMemorySize, 56320);
        attr_done = true;
    }

    {
        long total = (long)CN0 + CN1 + CN2 + CN3 + CN4;
        int blocks = (int)((total + 255) / 256);
        conv_all<<<blocks, 256>>>(
            (const float4*)input_w, (const float4*)in_w, (const float4*)out_w,
            (const float4*)w1, (const float4*)w2,
            (__half2*)iwh, (__half2*)inwh, (__half2*)outwh,
            (__half2*)w1h, (__half2*)w2h);
    }

    patch_gather<<<(MM * EE + 255) / 256, 256>>>(x, xp);
    gemm64<<<dim3(EE / 128, MPAD / 64), 256, 30720>>>(
        xp, iwh, input_b, pos_emb, h, nullptr, MPAD, EE, EE, EPI_POS, 0);

    for (int l = 0; l < NLAYERS; l++) {
        const float* l1w = ln1_w + (size_t)l * EE;
        const float* l1b = ln1_b + (size_t)l * EE;
        const float* ib  = in_b  + (size_t)l * 3 * EE;
        const float* ob  = out_b + (size_t)l * EE;
        const float* l2w = ln2_w + (size_t)l * EE;
        const float* l2b = ln2_b + (size_t)l * EE;
        const float* B1  = b1 + (size_t)l * HDIM;
        const float* B2  = b2 + (size_t)l * EE;
        size_t inoff  = (size_t)l * 3 * EE * EE;
        size_t outoff = (size_t)l * EE * EE;
        size_t w1off  = (size_t)l * HDIM * EE;
        size_t w2off  = (size_t)l * EE * HDIM;

        ln_kernel<<<MM / 8, 256>>>(h, l1w, l1b, y);
        gemm128<<<dim3(3 * EE / 128, MPAD / 128), 256, 40960>>>(
            y, inwh + inoff, ib, nullptr, nullptr, qkv, MPAD, 3 * EE, EE, EPI_NONE, 1);
        flash_attn<<<dim3(7, NBH), 256, 56320>>>(qkv, o);
        gemm64<<<dim3(EE / 128, MPAD / 64), 256, 30720>>>(
            o, outwh + outoff, ob, h, h, nullptr, MPAD, EE, EE, EPI_RES, 0);
        ln_kernel<<<MM / 8, 256>>>(h, l2w, l2b, y);
        gemm128<<<dim3(HDIM / 128, MPAD / 128), 256, 40960>>>(
            y, w1h + w1off, B1, nullptr, nullptr, mlp, MPAD, HDIM, EE, EPI_GELU, 1);
        gemm64<<<dim3(EE / 128, MPAD / 64), 256, 30720>>>(
            mlp, w2h + w2off, B2, h, h, nullptr, MPAD, EE, HDIM, EPI_RES, 0);
    }

    head_kernel<<<MM / 8, 256>>>(h, head_lnw, head_lnb, head_w, head_b,
                                 sxr_mean, sxr_std, out);
    flux_reduce<<<BB, 256>>>(out);
}

// round 14
// speedup vs baseline: 1.4671x; 1.0220x over previous
#include <cuda_runtime.h>
#include <cuda_fp16.h>
#include <math.h>
#include <stdint.h>

// ---------------- problem constants ----------------
#define BB 4
#define TT 784
#define GG 28
#define EE 768
#define HDIM 3072
#define NHEADS 12
#define DHEAD 64
#define NLAYERS 6
#define MM (BB*TT)        // 3136
#define MPAD 3200
#define NBH (BB*NHEADS)   // 48

// ---------------- scratch ----------------
__device__ __half g_xp[MPAD * EE];
__device__ float  g_h[MPAD * EE];
__device__ __half g_y[MPAD * EE];
__device__ __half g_qkv[MPAD * 3 * EE];
__device__ __half g_o[MPAD * EE];
__device__ __half g_mlp[MPAD * HDIM];
// pre-converted fp16 weights
__device__ __half g_iw_h[EE * EE];
__device__ __half g_inw_h[NLAYERS * 3 * EE * EE];
__device__ __half g_outw_h[NLAYERS * EE * EE];
__device__ __half g_w1_h[NLAYERS * HDIM * EE];
__device__ __half g_w2_h[NLAYERS * EE * HDIM];

#define EPI_NONE 0
#define EPI_POS  1
#define EPI_RES  2
#define EPI_GELU 3

// ---------------- helpers ----------------
__device__ __forceinline__ uint32_t packh2(__half a, __half b) {
    __half2 x = __halves2half2(a, b);
    return *reinterpret_cast<uint32_t*>(&x);
}

__device__ __forceinline__ void mma_f16(float d[4],
                                        uint32_t a0, uint32_t a1, uint32_t a2, uint32_t a3,
                                        uint32_t b0, uint32_t b1) {
    asm volatile(
        "mma.sync.aligned.m16n8k16.row.col.f32.f16.f16.f32 "
        "{%0,%1,%2,%3}, {%4,%5,%6,%7}, {%8,%9}, {%0,%1,%2,%3};"
        : "+f"(d[0]), "+f"(d[1]), "+f"(d[2]), "+f"(d[3])
        : "r"(a0), "r"(a1), "r"(a2), "r"(a3), "r"(b0), "r"(b1));
}

#define LDSM_X4(r0, r1, r2, r3, addr) \
    asm volatile("ldmatrix.sync.aligned.m8n8.x4.shared.b16 {%0,%1,%2,%3}, [%4];" \
        : "=r"(r0), "=r"(r1), "=r"(r2), "=r"(r3) : "r"(addr))

__device__ __forceinline__ void cpa16(uint32_t dst, const void* src) {
    asm volatile("cp.async.cg.shared.global [%0], [%1], 16;" :: "r"(dst), "l"(src));
}
__device__ __forceinline__ void cpa16z(uint32_t dst, const void* src, bool valid) {
    int sz = valid ? 16 : 0;
    asm volatile("cp.async.cg.shared.global [%0], [%1], 16, %2;"
                 :: "r"(dst), "l"(src), "r"(sz));
}
__device__ __forceinline__ void cp_commit() { asm volatile("cp.async.commit_group;"); }
__device__ __forceinline__ void cp_wait0() { asm volatile("cp.async.wait_group 0;"); }
__device__ __forceinline__ void cp_wait1() { asm volatile("cp.async.wait_group 1;"); }

// ---------------- epilogue ----------------
__device__ __forceinline__ void epi_store(float v, int m, int n, int N, int epi, int split,
                                          const float* bias, const float* extra,
                                          float* C, __half* Ch)
{
    v += bias[n];
    if (epi == EPI_POS)       v += extra[(size_t)(m % TT) * N + n];
    else if (epi == EPI_RES)  v += extra[(size_t)m * N + n];
    else if (epi == EPI_GELU) v = 0.5f * v * (1.0f + erff(v * 0.70710678118654752f));
    if (split) Ch[(size_t)m * N + n] = __float2half_rn(v);
    else       C[(size_t)m * N + n] = v;
}

// ---------------- merged weight convert ----------------
#define CN0 ((EE*EE)/4)
#define CN1 ((NLAYERS*3*EE*EE)/4)
#define CN2 ((NLAYERS*EE*EE)/4)
#define CN3 ((NLAYERS*HDIM*EE)/4)
#define CN4 ((NLAYERS*EE*HDIM)/4)
__global__ void conv_all(const float4* __restrict__ s0, const float4* __restrict__ s1,
                         const float4* __restrict__ s2, const float4* __restrict__ s3,
                         const float4* __restrict__ s4,
                         __half2* __restrict__ d0, __half2* __restrict__ d1,
                         __half2* __restrict__ d2, __half2* __restrict__ d3,
                         __half2* __restrict__ d4)
{
    long i = (long)blockIdx.x * 256 + threadIdx.x;
    const float4* s; __half2* d; long off;
    if (i < CN0)                                    { s = s0; d = d0; off = i; }
    else if (i < (long)CN0 + CN1)                   { s = s1; d = d1; off = i - CN0; }
    else if (i < (long)CN0 + CN1 + CN2)             { s = s2; d = d2; off = i - CN0 - CN1; }
    else if (i < (long)CN0 + CN1 + CN2 + CN3)       { s = s3; d = d3; off = i - CN0 - CN1 - CN2; }
    else if (i < (long)CN0 + CN1 + CN2 + CN3 + CN4) { s = s4; d = d4; off = i - CN0 - CN1 - CN2 - CN3; }
    else return;
    float4 a = s[off];
    d[2 * off]     = __halves2half2(__float2half_rn(a.x), __float2half_rn(a.y));
    d[2 * off + 1] = __halves2half2(__float2half_rn(a.z), __float2half_rn(a.w));
}

// ---------------- patch gather ----------------
__global__ void patch_gather(const float* __restrict__ x, __half* __restrict__ xh) {
    int idx = blockIdx.x * 256 + threadIdx.x;
    if (idx >= MM * EE) return;
    int j = idx % EE;
    int m = idx / EE;
    int b = m / TT, t = m % TT;
    int gr = t / GG, gc = t % GG;
    int ch = j >> 8, pr = (j >> 4) & 15, pc = j & 15;
    float v = x[(((size_t)b * 448 + gr * 16 + pr) * 448 + (gc * 16 + pc)) * 3 + ch];
    xh[idx] = __float2half_rn(v);
}

// ---------------- GEMM A: 128x128 block tile, 3-stage pipeline ----------------
#define GST 40
#define STG128 20480
__global__ __launch_bounds__(256, 2)
void gemm128(const __half* __restrict__ Ah, const __half* __restrict__ Wh,
             const float* __restrict__ bias, const float* __restrict__ extra,
             float* __restrict__ C, __half* __restrict__ Ch,
             int M, int N, int K, int epi, int split)
{
    extern __shared__ __half smh[];
    int tid = threadIdx.x, warp = tid >> 5, lane = tid & 31;
    int r = lane >> 2, t2 = (lane & 3) * 2;
    int m0 = blockIdx.y * 128, n0 = blockIdx.x * 128;
    int wm = (warp & 3) * 32, wn = (warp >> 2) * 64;
    uint32_t smb = (uint32_t)__cvta_generic_to_shared(smh);

    int lrow = tid >> 1, lpart = tid & 1;
    const __half* srcA = Ah + (size_t)(m0 + lrow) * K + lpart * 16;
    const __half* srcW = Wh + (size_t)(n0 + lrow) * K + lpart * 16;
    uint32_t dbase = smb + lrow * (GST * 2) + lpart * 32;

    int a_row = wm + (lane & 15);
    int a_col = (lane >> 4) << 3;
    int b_row = wn + ((lane >> 4) << 3) + (lane & 7);
    int b_col = ((lane >> 3) & 1) << 3;

    float acc[2][8][4] = {};
    const int KT = K >> 5;

    auto issue = [&](int st, int kc) {
        int k0 = kc << 5;
        uint32_t d = dbase + st * STG128;
        cpa16(d,         srcA + k0); cpa16(d + 16,         srcA + k0 + 8);
        cpa16(d + 10240, srcW + k0); cpa16(d + 10240 + 16, srcW + k0 + 8);
    };

    // prologue: stages 0,1
    issue(0, 0); cp_commit();
    if (KT > 1) { issue(1, 1); cp_commit(); }

    int st2 = 2;     // next stage slot for chunk kc+2
    for (int kc = 0; kc < KT; kc++) {
        if (kc + 1 < KT) cp_wait1(); else cp_wait0();
        __syncthreads();
        if (kc + 2 < KT) {
            issue(st2, kc + 2); cp_commit();
            st2 = (st2 == 2) ? 0 : st2 + 1;
        }

        uint32_t aA = smb + (kc % 3) * STG128;
        uint32_t aW = aA + 10240;

        #pragma unroll
        for (int s = 0; s < 2; s++) {
            int ks = s * 16;
            uint32_t ah[2][4];
            #pragma unroll
            for (int i2 = 0; i2 < 2; i2++) {
                uint32_t adr = (uint32_t)((a_row + 16 * i2) * GST + ks + a_col) * 2;
                LDSM_X4(ah[i2][0], ah[i2][1], ah[i2][2], ah[i2][3], aA + adr);
            }
            #pragma unroll
            for (int jj = 0; jj < 4; jj++) {
                uint32_t badr = aW + (uint32_t)((b_row + 16 * jj) * GST + ks + b_col) * 2;
                uint32_t b00, b01, b10, b11;
                LDSM_X4(b00, b01, b10, b11, badr);
                #pragma unroll
                for (int i2 = 0; i2 < 2; i2++) {
                    mma_f16(acc[i2][2 * jj],     ah[i2][0], ah[i2][1], ah[i2][2], ah[i2][3], b00, b01);
                    mma_f16(acc[i2][2 * jj + 1], ah[i2][0], ah[i2][1], ah[i2][2], ah[i2][3], b10, b11);
                }
            }
        }
    }

    __syncthreads();
    #pragma unroll
    for (int i2 = 0; i2 < 2; i2++) {
        #pragma unroll
        for (int j = 0; j < 8; j++) {
            #pragma unroll
            for (int half = 0; half < 2; half++) {
                int m = m0 + wm + 16 * i2 + r + half * 8;
                #pragma unroll
                for (int e = 0; e < 2; e++) {
                    int n = n0 + wn + 8 * j + t2 + e;
                    epi_store(acc[i2][j][half * 2 + e], m, n, N, epi, split,
                              bias, extra, C, Ch);
                }
            }
        }
    }
}

// ---------------- GEMM B: 64x128 block tile, 3-stage pipeline ----------------
#define STG64 15360
__global__ __launch_bounds__(256, 3)
void gemm64(const __half* __restrict__ Ah, const __half* __restrict__ Wh,
            const float* __restrict__ bias, const float* __restrict__ extra,
            float* __restrict__ C, __half* __restrict__ Ch,
            int M, int N, int K, int epi, int split)
{
    extern __shared__ __half smh[];
    int tid = threadIdx.x, warp = tid >> 5, lane = tid & 31;
    int r = lane >> 2, t2 = (lane & 3) * 2;
    int m0 = blockIdx.y * 64, n0 = blockIdx.x * 128;
    int wm = (warp & 3) * 16, wn = (warp >> 2) * 64;
    uint32_t smb = (uint32_t)__cvta_generic_to_shared(smh);

    int a_lrow = tid >> 2, a_seg = tid & 3;
    int w_lrow = tid >> 1, w_seg0 = (tid & 1) * 2;
    const __half* srcA = Ah + (size_t)(m0 + a_lrow) * K + a_seg * 8;
    const __half* srcW = Wh + (size_t)(n0 + w_lrow) * K;
    uint32_t dA = smb + (uint32_t)(a_lrow * GST + a_seg * 8) * 2;
    uint32_t dW = smb + 5120 + (uint32_t)(w_lrow * GST) * 2;

    int a_row = wm + (lane & 15);
    int a_col = (lane >> 4) << 3;
    int b_row = wn + ((lane >> 4) << 3) + (lane & 7);
    int b_col = ((lane >> 3) & 1) << 3;

    float acc[8][4] = {};
    const int KT = K >> 5;

    auto issue = [&](int st, int kc) {
        int k0 = kc << 5;
        uint32_t sb = st * STG64;
        cpa16(dA + sb, srcA + k0);
        cpa16(dW + sb + w_seg0 * 16,       srcW + k0 + w_seg0 * 8);
        cpa16(dW + sb + (w_seg0 + 1) * 16, srcW + k0 + (w_seg0 + 1) * 8);
    };

    issue(0, 0); cp_commit();
    if (KT > 1) { issue(1, 1); cp_commit(); }

    int st2 = 2;
    for (int kc = 0; kc < KT; kc++) {
        if (kc + 1 < KT) cp_wait1(); else cp_wait0();
        __syncthreads();
        if (kc + 2 < KT) {
            issue(st2, kc + 2); cp_commit();
            st2 = (st2 == 2) ? 0 : st2 + 1;
        }

        uint32_t aA = smb + (kc % 3) * STG64;
        uint32_t aW = aA + 5120;

        #pragma unroll
        for (int s = 0; s < 2; s++) {
            int ks = s * 16;
            uint32_t ah[4];
            {
                uint32_t adr = (uint32_t)(a_row * GST + ks + a_col) * 2;
                LDSM_X4(ah[0], ah[1], ah[2], ah[3], aA + adr);
            }
            #pragma unroll
            for (int jj = 0; jj < 4; jj++) {
                uint32_t badr = aW + (uint32_t)((b_row + 16 * jj) * GST + ks + b_col) * 2;
                uint32_t b00, b01, b10, b11;
                LDSM_X4(b00, b01, b10, b11, badr);
                mma_f16(acc[2 * jj],     ah[0], ah[1], ah[2], ah[3], b00, b01);
                mma_f16(acc[2 * jj + 1], ah[0], ah[1], ah[2], ah[3], b10, b11);
            }
        }
    }

    __syncthreads();
    #pragma unroll
    for (int j = 0; j < 8; j++) {
        #pragma unroll
        for (int half = 0; half < 2; half++) {
            int m = m0 + wm + r + half * 8;
            #pragma unroll
            for (int e = 0; e < 2; e++) {
                int n = n0 + wn + 8 * j + t2 + e;
                epi_store(acc[j][half * 2 + e], m, n, N, epi, split,
                          bias, extra, C, Ch);
            }
        }
    }
}

// ---------------- fused flash attention, pure fp16 single pass ----------------
#define QST 72
#define VST 152
__global__ __launch_bounds__(256, 1)
void flash_attn(const __half* __restrict__ qkv, __half* __restrict__ oh)
{
    extern __shared__ __half sm[];
    __half* sQ = sm;                  // 128*72 halves
    __half* sK = sm + 9216;           // 128*72
    __half* sV = sm + 18432;          // 64*152  [d][k]

    int bh = blockIdx.y, b = bh / NHEADS, h = bh % NHEADS;
    int q0 = blockIdx.x * 128;
    int tid = threadIdx.x, warp = tid >> 5, lane = tid & 31;
    int r = lane >> 2, t2 = (lane & 3) * 2;
    uint32_t smb = (uint32_t)__cvta_generic_to_shared(sm);

    int lrow = tid >> 1, lpart = tid & 1;

    {
        int qrow = q0 + lrow;
        bool qv = qrow < TT;
        const __half* sQg = qkv + (size_t)(b * TT + (qv ? qrow : 0)) * (3 * EE) + h * DHEAD + lpart * 32;
        uint32_t d0 = smb + lrow * (QST * 2) + lpart * 64;
        #pragma unroll
        for (int c = 0; c < 4; c++) cpa16z(d0 + c * 16, sQg + c * 8, qv);
    }
    cp_commit();

    int qi0 = q0 + 16 * warp + r;
    int qi1 = qi0 + 8;
    int rq0 = qi0 / GG, cq0 = qi0 - rq0 * GG;
    int rq1 = qi1 / GG, cq1 = qi1 - rq1 * GG;

    float m0 = -1e30f, m1 = -1e30f, l0 = 0.f, l1 = 0.f;
    float acc_o[8][4] = {};

    const __half* vbase = qkv + (size_t)(b * TT) * (3 * EE) + 2 * EE + h * DHEAD;

    for (int kb = 0; kb < 7; kb++) {
        int k0 = kb * 128;
        __syncthreads();

        {
            int krow = k0 + lrow;
            bool kv2 = krow < TT;
            const __half* sKg = qkv + (size_t)(b * TT + (kv2 ? krow : 0)) * (3 * EE) + EE + h * DHEAD + lpart * 32;
            uint32_t dk = smb + 18432 + lrow * (QST * 2) + lpart * 64;
            #pragma unroll
            for (int c = 0; c < 4; c++) cpa16z(dk + c * 16, sKg + c * 8, kv2);
        }
        cp_commit();

        {
            int vd = tid & 63;
            int kbase = (tid >> 6) * 32;
            #pragma unroll
            for (int i = 0; i < 32; i++) {
                int k = kbase + i;
                int tok = k0 + k;
                __half v = (tok < TT) ? vbase[(size_t)tok * (3 * EE) + vd] : __half(0.f);
                sV[vd * VST + k] = v;
            }
        }
        cp_wait0();
        __syncthreads();

        float s[16][4] = {};
        #pragma unroll
        for (int ds = 0; ds < 4; ds++) {
            int ks = ds * 16;
            const __half* pa = sQ + (16 * warp + r) * QST + ks + t2;
            uint32_t a0 = *(const uint32_t*)pa;
            uint32_t a1 = *(const uint32_t*)(pa + 8 * QST);
            uint32_t a2 = *(const uint32_t*)(pa + 8);
            uint32_t a3 = *(const uint32_t*)(pa + 8 * QST + 8);
            #pragma unroll
            for (int j = 0; j < 16; j++) {
                const __half* pk = sK + (8 * j + r) * QST + ks + t2;
                uint32_t b0 = *(const uint32_t*)pk;
                uint32_t b1 = *(const uint32_t*)(pk + 8);
                mma_f16(s[j], a0, a1, a2, a3, b0, b1);
            }
        }

        float bm0 = -1e30f, bm1 = -1e30f;
        #pragma unroll
        for (int j = 0; j < 16; j++) {
            #pragma unroll
            for (int e = 0; e < 2; e++) {
                int ki = k0 + 8 * j + t2 + e;
                int rk = ki / GG, ck = ki - rk * GG;
                bool oob = ki >= TT;
                float v0 = s[j][e] * 0.125f;
                if (oob || (abs(rq0 - rk) <= 4 && abs(cq0 - ck) <= 4)) v0 = -1e30f;
                s[j][e] = v0;
                bm0 = fmaxf(bm0, v0);
                float v1 = s[j][e + 2] * 0.125f;
                if (oob || (abs(rq1 - rk) <= 4 && abs(cq1 - ck) <= 4)) v1 = -1e30f;
                s[j][e + 2] = v1;
                bm1 = fmaxf(bm1, v1);
            }
        }
        bm0 = fmaxf(bm0, __shfl_xor_sync(0xFFFFFFFFu, bm0, 1));
        bm0 = fmaxf(bm0, __shfl_xor_sync(0xFFFFFFFFu, bm0, 2));
        bm1 = fmaxf(bm1, __shfl_xor_sync(0xFFFFFFFFu, bm1, 1));
        bm1 = fmaxf(bm1, __shfl_xor_sync(0xFFFFFFFFu, bm1, 2));

        float nm0 = fmaxf(m0, bm0), nm1 = fmaxf(m1, bm1);
        float sc0 = __expf(m0 - nm0), sc1 = __expf(m1 - nm1);
        m0 = nm0; m1 = nm1;

        float rs0 = 0.f, rs1 = 0.f;
        #pragma unroll
        for (int j = 0; j < 16; j++) {
            #pragma unroll
            for (int e = 0; e < 2; e++) {
                float p0 = __expf(s[j][e] - m0);
                s[j][e] = p0; rs0 += p0;
                float p1 = __expf(s[j][e + 2] - m1);
                s[j][e + 2] = p1; rs1 += p1;
            }
        }
        rs0 += __shfl_xor_sync(0xFFFFFFFFu, rs0, 1);
        rs0 += __shfl_xor_sync(0xFFFFFFFFu, rs0, 2);
        rs1 += __shfl_xor_sync(0xFFFFFFFFu, rs1, 1);
        rs1 += __shfl_xor_sync(0xFFFFFFFFu, rs1, 2);
        l0 = l0 * sc0 + rs0;
        l1 = l1 * sc1 + rs1;

        #pragma unroll
        for (int j2 = 0; j2 < 8; j2++) {
            acc_o[j2][0] *= sc0; acc_o[j2][1] *= sc0;
            acc_o[j2][2] *= sc1; acc_o[j2][3] *= sc1;
        }

        #pragma unroll
        for (int s2 = 0; s2 < 8; s2++) {
            uint32_t a0 = packh2(__float2half_rn(s[2 * s2][0]),     __float2half_rn(s[2 * s2][1]));
            uint32_t a1 = packh2(__float2half_rn(s[2 * s2][2]),     __float2half_rn(s[2 * s2][3]));
            uint32_t a2 = packh2(__float2half_rn(s[2 * s2 + 1][0]), __float2half_rn(s[2 * s2 + 1][1]));
            uint32_t a3 = packh2(__float2half_rn(s[2 * s2 + 1][2]), __float2half_rn(s[2 * s2 + 1][3]));
            #pragma unroll
            for (int j2 = 0; j2 < 8; j2++) {
                const __half* pv = sV + (8 * j2 + r) * VST + 16 * s2 + t2;
                uint32_t b0 = *(const uint32_t*)pv;
                uint32_t b1 = *(const uint32_t*)(pv + 8);
                mma_f16(acc_o[j2], a0, a1, a2, a3, b0, b1);
            }
        }
    }

    float il0 = 1.f / l0, il1 = 1.f / l1;
    #pragma unroll
    for (int j2 = 0; j2 < 8; j2++) {
        #pragma unroll
        for (int e = 0; e < 2; e++) {
            int d = 8 * j2 + t2 + e;
            if (qi0 < TT)
                oh[(size_t)(b * TT + qi0) * EE + h * DHEAD + d] = __float2half_rn(acc_o[j2][e] * il0);
            if (qi1 < TT)
                oh[(size_t)(b * TT + qi1) * EE + h * DHEAD + d] = __float2half_rn(acc_o[j2][e + 2] * il1);
        }
    }
}

// ---------------- layernorm: warp per token ----------------
__global__ void ln_kernel(const float* __restrict__ x, const float* __restrict__ g,
                          const float* __restrict__ bp, __half* __restrict__ yh)
{
    int warp = threadIdx.x >> 5, lane = threadIdx.x & 31;
    int m = blockIdx.x * 8 + warp;
    const float4* xr = reinterpret_cast<const float4*>(x + (size_t)m * EE);

    float4 v[6];
    float s = 0.f, s2 = 0.f;
    #pragma unroll
    for (int k = 0; k < 6; k++) {
        v[k] = xr[lane + 32 * k];
        s  += v[k].x + v[k].y + v[k].z + v[k].w;
        s2 += v[k].x * v[k].x + v[k].y * v[k].y + v[k].z * v[k].z + v[k].w * v[k].w;
    }
    #pragma unroll
    for (int o = 16; o > 0; o >>= 1) {
        s  += __shfl_xor_sync(0xFFFFFFFFu, s, o);
        s2 += __shfl_xor_sync(0xFFFFFFFFu, s2, o);
    }
    float mean = s * (1.0f / EE);
    float inv = rsqrtf(s2 * (1.0f / EE) - mean * mean + 1e-5f);

    __half2* ph = reinterpret_cast<__half2*>(yh + (size_t)m * EE);
    #pragma unroll
    for (int k = 0; k < 6; k++) {
        float4 gg = reinterpret_cast<const float4*>(g)[lane + 32 * k];
        float4 bb = reinterpret_cast<const float4*>(bp)[lane + 32 * k];
        float o0 = (v[k].x - mean) * inv * gg.x + bb.x;
        float o1 = (v[k].y - mean) * inv * gg.y + bb.y;
        float o2 = (v[k].z - mean) * inv * gg.z + bb.z;
        float o3 = (v[k].w - mean) * inv * gg.w + bb.w;
        int idx = (lane + 32 * k) * 2;
        ph[idx]     = __halves2half2(__float2half_rn(o0), __float2half_rn(o1));
        ph[idx + 1] = __halves2half2(__float2half_rn(o2), __float2half_rn(o3));
    }
}

// ---------------- head + flux ----------------
__global__ void head_kernel(const float* __restrict__ hbuf,
                            const float* __restrict__ lnw, const float* __restrict__ lnb,
                            const float* __restrict__ hw, const float* __restrict__ hb,
                            const float* __restrict__ mean_s, const float* __restrict__ std_s,
                            float* __restrict__ out)
{
    int warp = threadIdx.x >> 5, lane = threadIdx.x & 31;
    int m = blockIdx.x * 8 + warp;
    const float4* xr = reinterpret_cast<const float4*>(hbuf + (size_t)m * EE);

    float4 v[6];
    float s = 0.f, s2 = 0.f;
    #pragma unroll
    for (int k = 0; k < 6; k++) {
        v[k] = xr[lane + 32 * k];
        s  += v[k].x + v[k].y + v[k].z + v[k].w;
        s2 += v[k].x * v[k].x + v[k].y * v[k].y + v[k].z * v[k].z + v[k].w * v[k].w;
    }
    #pragma unroll
    for (int o = 16; o > 0; o >>= 1) {
        s  += __shfl_xor_sync(0xFFFFFFFFu, s, o);
        s2 += __shfl_xor_sync(0xFFFFFFFFu, s2, o);
    }
    float mean = s * (1.0f / EE);
    float inv = rsqrtf(s2 * (1.0f / EE) - mean * mean + 1e-5f);

    float dot = 0.f;
    #pragma unroll
    for (int k = 0; k < 6; k++) {
        float4 gg = reinterpret_cast<const float4*>(lnw)[lane + 32 * k];
        float4 bb = reinterpret_cast<const float4*>(lnb)[lane + 32 * k];
        float4 ww = reinterpret_cast<const float4*>(hw)[lane + 32 * k];
        dot += ((v[k].x - mean) * inv * gg.x + bb.x) * ww.x;
        dot += ((v[k].y - mean) * inv * gg.y + bb.y) * ww.y;
        dot += ((v[k].z - mean) * inv * gg.z + bb.z) * ww.z;
        dot += ((v[k].w - mean) * inv * gg.w + bb.w) * ww.w;
    }
    #pragma unroll
    for (int o = 16; o > 0; o >>= 1)
        dot += __shfl_xor_sync(0xFFFFFFFFu, dot, o);

    if (lane == 0) {
        float logit = dot + hb[0];
        float lg = logit * std_s[0] + mean_s[0];
        float pf = exp10f(lg) - 1e-8f;
        pf = fminf(fmaxf(pf, 1e-15f), 1.0f);
        out[BB + m] = pf;
    }
}

__global__ void flux_reduce(float* __restrict__ out)
{
    int b = blockIdx.x;
    __shared__ float red[256];
    int tid = threadIdx.x;
    float s = 0.f;
    for (int i = tid; i < TT; i += 256) s += out[BB + b * TT + i];
    red[tid] = s; __syncthreads();
    for (int st = 128; st > 0; st >>= 1) { if (tid < st) red[tid] += red[tid + st]; __syncthreads(); }
    if (tid == 0) out[b] = fmaxf(red[0], 1e-15f);
}

// ---------------- launcher ----------------
extern "C" void kernel_launch(void* const* d_in, const int* in_sizes, int n_in,
                              void* d_out, int out_size)
{
    const float* x        = (const float*)d_in[0];
    const float* sxr_mean = (const float*)d_in[1];
    const float* sxr_std  = (const float*)d_in[2];
    const float* input_w  = (const float*)d_in[3];
    const float* input_b  = (const float*)d_in[4];
    const float* pos_emb  = (const float*)d_in[5];
    const float* ln1_w    = (const float*)d_in[6];
    const float* ln1_b    = (const float*)d_in[7];
    const float* in_w     = (const float*)d_in[8];
    const float* in_b     = (const float*)d_in[9];
    const float* out_w    = (const float*)d_in[10];
    const float* out_b    = (const float*)d_in[11];
    const float* ln2_w    = (const float*)d_in[12];
    const float* ln2_b    = (const float*)d_in[13];
    const float* w1       = (const float*)d_in[14];
    const float* b1       = (const float*)d_in[15];
    const float* w2       = (const float*)d_in[16];
    const float* b2       = (const float*)d_in[17];
    const float* head_lnw = (const float*)d_in[18];
    const float* head_lnb = (const float*)d_in[19];
    const float* head_w   = (const float*)d_in[20];
    const float* head_b   = (const float*)d_in[21];
    float* out = (float*)d_out;

    __half *xp, *y, *qkv, *o, *mlp;
    __half *iwh, *inwh, *outwh, *w1h, *w2h;
    float *h;
    cudaGetSymbolAddress((void**)&xp,    g_xp);
    cudaGetSymbolAddress((void**)&h,     g_h);
    cudaGetSymbolAddress((void**)&y,     g_y);
    cudaGetSymbolAddress((void**)&qkv,   g_qkv);
    cudaGetSymbolAddress((void**)&o,     g_o);
    cudaGetSymbolAddress((void**)&mlp,   g_mlp);
    cudaGetSymbolAddress((void**)&iwh,   g_iw_h);
    cudaGetSymbolAddress((void**)&inwh,  g_inw_h);
    cudaGetSymbolAddress((void**)&outwh, g_outw_h);
    cudaGetSymbolAddress((void**)&w1h,   g_w1_h);
    cudaGetSymbolAddress((void**)&w2h,   g_w2_h);

    static bool attr_done = false;
    if (!attr_done) {
        cudaFuncSetAttribute(gemm128, cudaFuncAttributeMaxDynamicSharedMemorySize, 61440);
        cudaFuncSetAttribute(gemm64,  cudaFuncAttributeMaxDynamicSharedMemorySize, 46080);
        cudaFuncSetAttribute(flash_attn, cudaFuncAttributeMaxDynamicSharedMemorySize, 56320);
        attr_done = true;
    }

    {
        long total = (long)CN0 + CN1 + CN2 + CN3 + CN4;
        int blocks = (int)((total + 255) / 256);
        conv_all<<<blocks, 256>>>(
            (const float4*)input_w, (const float4*)in_w, (const float4*)out_w,
            (const float4*)w1, (const float4*)w2,
            (__half2*)iwh, (__half2*)inwh, (__half2*)outwh,
            (__half2*)w1h, (__half2*)w2h);
    }

    patch_gather<<<(MM * EE + 255) / 256, 256>>>(x, xp);
    gemm64<<<dim3(EE / 128, MPAD / 64), 256, 46080>>>(
        xp, iwh, input_b, pos_emb, h, nullptr, MPAD, EE, EE, EPI_POS, 0);

    for (int l = 0; l < NLAYERS; l++) {
        const float* l1w = ln1_w + (size_t)l * EE;
        const float* l1b = ln1_b + (size_t)l * EE;
        const float* ib  = in_b  + (size_t)l * 3 * EE;
        const float* ob  = out_b + (size_t)l * EE;
        const float* l2w = ln2_w + (size_t)l * EE;
        const float* l2b = ln2_b + (size_t)l * EE;
        const float* B1  = b1 + (size_t)l * HDIM;
        const float* B2  = b2 + (size_t)l * EE;
        size_t inoff  = (size_t)l * 3 * EE * EE;
        size_t outoff = (size_t)l * EE * EE;
        size_t w1off  = (size_t)l * HDIM * EE;
        size_t w2off  = (size_t)l * EE * HDIM;

        ln_kernel<<<MM / 8, 256>>>(h, l1w, l1b, y);
        gemm128<<<dim3(3 * EE / 128, MPAD / 128), 256, 61440>>>(
            y, inwh + inoff, ib, nullptr, nullptr, qkv, MPAD, 3 * EE, EE, EPI_NONE, 1);
        flash_attn<<<dim3(7, NBH), 256, 56320>>>(qkv, o);
        gemm64<<<dim3(EE / 128, MPAD / 64), 256, 46080>>>(
            o, outwh + outoff, ob, h, h, nullptr, MPAD, EE, EE, EPI_RES, 0);
        ln_kernel<<<MM / 8, 256>>>(h, l2w, l2b, y);
        gemm128<<<dim3(HDIM / 128, MPAD / 128), 256, 61440>>>(
            y, w1h + w1off, B1, nullptr, nullptr, mlp, MPAD, HDIM, EE, EPI_GELU, 1);
        gemm64<<<dim3(EE / 128, MPAD / 64), 256, 46080>>>(
            mlp, w2h + w2off, B2, h, h, nullptr, MPAD, EE, HDIM, EPI_RES, 0);
    }

    head_kernel<<<MM / 8, 256>>>(h, head_lnw, head_lnb, head_w, head_b,
                                 sxr_mean, sxr_std, out);
    flux_reduce<<<BB, 256>>>(out);
}

// round 15
// speedup vs baseline: 1.4819x; 1.0101x over previous
#include <cuda_runtime.h>
#include <cuda_fp16.h>
#include <math.h>
#include <stdint.h>

// ---------------- problem constants ----------------
#define BB 4
#define TT 784
#define GG 28
#define EE 768
#define HDIM 3072
#define NHEADS 12
#define DHEAD 64
#define NLAYERS 6
#define MM (BB*TT)        // 3136
#define MPAD 3200
#define NBH (BB*NHEADS)   // 48

// ---------------- scratch ----------------
__device__ __half g_xp[MPAD * EE];
__device__ float  g_h[MPAD * EE];
__device__ __half g_y[MPAD * EE];
__device__ __half g_qkv[MPAD * 3 * EE];
__device__ __half g_o[MPAD * EE];
__device__ __half g_mlp[MPAD * HDIM];
// pre-converted fp16 weights
__device__ __half g_iw_h[EE * EE];
__device__ __half g_inw_h[NLAYERS * 3 * EE * EE];
__device__ __half g_outw_h[NLAYERS * EE * EE];
__device__ __half g_w1_h[NLAYERS * HDIM * EE];
__device__ __half g_w2_h[NLAYERS * EE * HDIM];

#define EPI_NONE 0
#define EPI_POS  1
#define EPI_RES  2
#define EPI_GELU 3

// ---------------- helpers ----------------
__device__ __forceinline__ uint32_t packh2(__half a, __half b) {
    __half2 x = __halves2half2(a, b);
    return *reinterpret_cast<uint32_t*>(&x);
}

__device__ __forceinline__ void mma_f16(float d[4],
                                        uint32_t a0, uint32_t a1, uint32_t a2, uint32_t a3,
                                        uint32_t b0, uint32_t b1) {
    asm volatile(
        "mma.sync.aligned.m16n8k16.row.col.f32.f16.f16.f32 "
        "{%0,%1,%2,%3}, {%4,%5,%6,%7}, {%8,%9}, {%0,%1,%2,%3};"
        : "+f"(d[0]), "+f"(d[1]), "+f"(d[2]), "+f"(d[3])
        : "r"(a0), "r"(a1), "r"(a2), "r"(a3), "r"(b0), "r"(b1));
}

#define LDSM_X4(r0, r1, r2, r3, addr) \
    asm volatile("ldmatrix.sync.aligned.m8n8.x4.shared.b16 {%0,%1,%2,%3}, [%4];" \
        : "=r"(r0), "=r"(r1), "=r"(r2), "=r"(r3) : "r"(addr))

__device__ __forceinline__ void cpa16(uint32_t dst, const void* src) {
    asm volatile("cp.async.cg.shared.global [%0], [%1], 16;" :: "r"(dst), "l"(src));
}
__device__ __forceinline__ void cpa16z(uint32_t dst, const void* src, bool valid) {
    int sz = valid ? 16 : 0;
    asm volatile("cp.async.cg.shared.global [%0], [%1], 16, %2;"
                 :: "r"(dst), "l"(src), "r"(sz));
}
__device__ __forceinline__ void cp_commit() { asm volatile("cp.async.commit_group;"); }
__device__ __forceinline__ void cp_wait0() { asm volatile("cp.async.wait_group 0;"); }
__device__ __forceinline__ void cp_wait1() { asm volatile("cp.async.wait_group 1;"); }

// ---------------- epilogue ----------------
__device__ __forceinline__ void epi_store(float v, int m, int n, int N, int epi, int split,
                                          const float* bias, const float* extra,
                                          float* C, __half* Ch)
{
    v += bias[n];
    if (epi == EPI_POS)       v += extra[(size_t)(m % TT) * N + n];
    else if (epi == EPI_RES)  v += extra[(size_t)m * N + n];
    else if (epi == EPI_GELU) v = 0.5f * v * (1.0f + erff(v * 0.70710678118654752f));
    if (split) Ch[(size_t)m * N + n] = __float2half_rn(v);
    else       C[(size_t)m * N + n] = v;
}

// ---------------- merged weight convert ----------------
#define CN0 ((EE*EE)/4)
#define CN1 ((NLAYERS*3*EE*EE)/4)
#define CN2 ((NLAYERS*EE*EE)/4)
#define CN3 ((NLAYERS*HDIM*EE)/4)
#define CN4 ((NLAYERS*EE*HDIM)/4)
__global__ void conv_all(const float4* __restrict__ s0, const float4* __restrict__ s1,
                         const float4* __restrict__ s2, const float4* __restrict__ s3,
                         const float4* __restrict__ s4,
                         __half2* __restrict__ d0, __half2* __restrict__ d1,
                         __half2* __restrict__ d2, __half2* __restrict__ d3,
                         __half2* __restrict__ d4)
{
    long i = (long)blockIdx.x * 256 + threadIdx.x;
    const float4* s; __half2* d; long off;
    if (i < CN0)                                    { s = s0; d = d0; off = i; }
    else if (i < (long)CN0 + CN1)                   { s = s1; d = d1; off = i - CN0; }
    else if (i < (long)CN0 + CN1 + CN2)             { s = s2; d = d2; off = i - CN0 - CN1; }
    else if (i < (long)CN0 + CN1 + CN2 + CN3)       { s = s3; d = d3; off = i - CN0 - CN1 - CN2; }
    else if (i < (long)CN0 + CN1 + CN2 + CN3 + CN4) { s = s4; d = d4; off = i - CN0 - CN1 - CN2 - CN3; }
    else return;
    float4 a = s[off];
    d[2 * off]     = __halves2half2(__float2half_rn(a.x), __float2half_rn(a.y));
    d[2 * off + 1] = __halves2half2(__float2half_rn(a.z), __float2half_rn(a.w));
}

// ---------------- patch gather ----------------
__global__ void patch_gather(const float* __restrict__ x, __half* __restrict__ xh) {
    int idx = blockIdx.x * 256 + threadIdx.x;
    if (idx >= MM * EE) return;
    int j = idx % EE;
    int m = idx / EE;
    int b = m / TT, t = m % TT;
    int gr = t / GG, gc = t % GG;
    int ch = j >> 8, pr = (j >> 4) & 15, pc = j & 15;
    float v = x[(((size_t)b * 448 + gr * 16 + pr) * 448 + (gc * 16 + pc)) * 3 + ch];
    xh[idx] = __float2half_rn(v);
}

// ---------------- GEMM A: 128x128 block tile, k-chunk 64, 3-stage ----------------
#define GSTW 72
#define STG128 36864   // (128+128) rows * 72 halves * 2B
__global__ __launch_bounds__(256, 2)
void gemm128(const __half* __restrict__ Ah, const __half* __restrict__ Wh,
             const float* __restrict__ bias, const float* __restrict__ extra,
             float* __restrict__ C, __half* __restrict__ Ch,
             int M, int N, int K, int epi, int split)
{
    extern __shared__ __half smh[];
    int tid = threadIdx.x, warp = tid >> 5, lane = tid & 31;
    int r = lane >> 2, t2 = (lane & 3) * 2;
    int m0 = blockIdx.y * 128, n0 = blockIdx.x * 128;
    int wm = (warp & 3) * 32, wn = (warp >> 2) * 64;
    uint32_t smb = (uint32_t)__cvta_generic_to_shared(smh);

    int lrow = tid >> 1, lpart = tid & 1;    // each thread loads 32 halves of A row + W row
    const __half* srcA = Ah + (size_t)(m0 + lrow) * K + lpart * 32;
    const __half* srcW = Wh + (size_t)(n0 + lrow) * K + lpart * 32;
    uint32_t dA = smb + (uint32_t)(lrow * GSTW + lpart * 32) * 2;

    int a_row = wm + (lane & 15);
    int a_col = (lane >> 4) << 3;
    int b_row = wn + ((lane >> 4) << 3) + (lane & 7);
    int b_col = ((lane >> 3) & 1) << 3;

    float acc[2][8][4] = {};
    const int KT = K >> 6;

    auto issue = [&](int st, int kc) {
        int k0 = kc << 6;
        uint32_t base = st * STG128;
        #pragma unroll
        for (int c = 0; c < 4; c++) {
            cpa16(dA + base + c * 16,         srcA + k0 + c * 8);
            cpa16(dA + base + 18432 + c * 16, srcW + k0 + c * 8);
        }
    };

    issue(0, 0); cp_commit();
    if (KT > 1) { issue(1, 1); cp_commit(); }

    int st2 = 2;
    for (int kc = 0; kc < KT; kc++) {
        if (kc + 1 < KT) cp_wait1(); else cp_wait0();
        __syncthreads();
        if (kc + 2 < KT) {
            issue(st2, kc + 2); cp_commit();
            st2 = (st2 == 2) ? 0 : st2 + 1;
        }

        uint32_t aA = smb + (kc % 3) * STG128;
        uint32_t aW = aA + 18432;

        #pragma unroll
        for (int s = 0; s < 4; s++) {
            int ks = s * 16;
            uint32_t ah[2][4];
            #pragma unroll
            for (int i2 = 0; i2 < 2; i2++) {
                uint32_t adr = (uint32_t)((a_row + 16 * i2) * GSTW + ks + a_col) * 2;
                LDSM_X4(ah[i2][0], ah[i2][1], ah[i2][2], ah[i2][3], aA + adr);
            }
            #pragma unroll
            for (int jj = 0; jj < 4; jj++) {
                uint32_t badr = aW + (uint32_t)((b_row + 16 * jj) * GSTW + ks + b_col) * 2;
                uint32_t b00, b01, b10, b11;
                LDSM_X4(b00, b01, b10, b11, badr);
                #pragma unroll
                for (int i2 = 0; i2 < 2; i2++) {
                    mma_f16(acc[i2][2 * jj],     ah[i2][0], ah[i2][1], ah[i2][2], ah[i2][3], b00, b01);
                    mma_f16(acc[i2][2 * jj + 1], ah[i2][0], ah[i2][1], ah[i2][2], ah[i2][3], b10, b11);
                }
            }
        }
    }

    __syncthreads();
    #pragma unroll
    for (int i2 = 0; i2 < 2; i2++) {
        #pragma unroll
        for (int j = 0; j < 8; j++) {
            #pragma unroll
            for (int half = 0; half < 2; half++) {
                int m = m0 + wm + 16 * i2 + r + half * 8;
                #pragma unroll
                for (int e = 0; e < 2; e++) {
                    int n = n0 + wn + 8 * j + t2 + e;
                    epi_store(acc[i2][j][half * 2 + e], m, n, N, epi, split,
                              bias, extra, C, Ch);
                }
            }
        }
    }
}

// ---------------- GEMM B: 64x128 block tile, k-chunk 32, 3-stage (unchanged) ----------------
#define GST 40
#define STG64 15360
__global__ __launch_bounds__(256, 3)
void gemm64(const __half* __restrict__ Ah, const __half* __restrict__ Wh,
            const float* __restrict__ bias, const float* __restrict__ extra,
            float* __restrict__ C, __half* __restrict__ Ch,
            int M, int N, int K, int epi, int split)
{
    extern __shared__ __half smh[];
    int tid = threadIdx.x, warp = tid >> 5, lane = tid & 31;
    int r = lane >> 2, t2 = (lane & 3) * 2;
    int m0 = blockIdx.y * 64, n0 = blockIdx.x * 128;
    int wm = (warp & 3) * 16, wn = (warp >> 2) * 64;
    uint32_t smb = (uint32_t)__cvta_generic_to_shared(smh);

    int a_lrow = tid >> 2, a_seg = tid & 3;
    int w_lrow = tid >> 1, w_seg0 = (tid & 1) * 2;
    const __half* srcA = Ah + (size_t)(m0 + a_lrow) * K + a_seg * 8;
    const __half* srcW = Wh + (size_t)(n0 + w_lrow) * K;
    uint32_t dA = smb + (uint32_t)(a_lrow * GST + a_seg * 8) * 2;
    uint32_t dW = smb + 5120 + (uint32_t)(w_lrow * GST) * 2;

    int a_row = wm + (lane & 15);
    int a_col = (lane >> 4) << 3;
    int b_row = wn + ((lane >> 4) << 3) + (lane & 7);
    int b_col = ((lane >> 3) & 1) << 3;

    float acc[8][4] = {};
    const int KT = K >> 5;

    auto issue = [&](int st, int kc) {
        int k0 = kc << 5;
        uint32_t sb = st * STG64;
        cpa16(dA + sb, srcA + k0);
        cpa16(dW + sb + w_seg0 * 16,       srcW + k0 + w_seg0 * 8);
        cpa16(dW + sb + (w_seg0 + 1) * 16, srcW + k0 + (w_seg0 + 1) * 8);
    };

    issue(0, 0); cp_commit();
    if (KT > 1) { issue(1, 1); cp_commit(); }

    int st2 = 2;
    for (int kc = 0; kc < KT; kc++) {
        if (kc + 1 < KT) cp_wait1(); else cp_wait0();
        __syncthreads();
        if (kc + 2 < KT) {
            issue(st2, kc + 2); cp_commit();
            st2 = (st2 == 2) ? 0 : st2 + 1;
        }

        uint32_t aA = smb + (kc % 3) * STG64;
        uint32_t aW = aA + 5120;

        #pragma unroll
        for (int s = 0; s < 2; s++) {
            int ks = s * 16;
            uint32_t ah[4];
            {
                uint32_t adr = (uint32_t)(a_row * GST + ks + a_col) * 2;
                LDSM_X4(ah[0], ah[1], ah[2], ah[3], aA + adr);
            }
            #pragma unroll
            for (int jj = 0; jj < 4; jj++) {
                uint32_t badr = aW + (uint32_t)((b_row + 16 * jj) * GST + ks + b_col) * 2;
                uint32_t b00, b01, b10, b11;
                LDSM_X4(b00, b01, b10, b11, badr);
                mma_f16(acc[2 * jj],     ah[0], ah[1], ah[2], ah[3], b00, b01);
                mma_f16(acc[2 * jj + 1], ah[0], ah[1], ah[2], ah[3], b10, b11);
            }
        }
    }

    __syncthreads();
    #pragma unroll
    for (int j = 0; j < 8; j++) {
        #pragma unroll
        for (int half = 0; half < 2; half++) {
            int m = m0 + wm + r + half * 8;
            #pragma unroll
            for (int e = 0; e < 2; e++) {
                int n = n0 + wn + 8 * j + t2 + e;
                epi_store(acc[j][half * 2 + e], m, n, N, epi, split,
                          bias, extra, C, Ch);
            }
        }
    }
}

// ---------------- fused flash attention, occupancy 2 ----------------
#define QST 72
#define VST 152
__global__ __launch_bounds__(256, 2)
void flash_attn(const __half* __restrict__ qkv, __half* __restrict__ oh)
{
    extern __shared__ __half sm[];
    __half* sQ = sm;                  // 128*72 halves
    __half* sK = sm + 9216;           // 128*72
    __half* sV = sm + 18432;          // 64*152  [d][k]

    int bh = blockIdx.y, b = bh / NHEADS, h = bh % NHEADS;
    int q0 = blockIdx.x * 128;
    int tid = threadIdx.x, warp = tid >> 5, lane = tid & 31;
    int r = lane >> 2, t2 = (lane & 3) * 2;
    uint32_t smb = (uint32_t)__cvta_generic_to_shared(sm);

    int lrow = tid >> 1, lpart = tid & 1;

    {
        int qrow = q0 + lrow;
        bool qv = qrow < TT;
        const __half* sQg = qkv + (size_t)(b * TT + (qv ? qrow : 0)) * (3 * EE) + h * DHEAD + lpart * 32;
        uint32_t d0 = smb + lrow * (QST * 2) + lpart * 64;
        #pragma unroll
        for (int c = 0; c < 4; c++) cpa16z(d0 + c * 16, sQg + c * 8, qv);
    }
    cp_commit();

    int qi0 = q0 + 16 * warp + r;
    int qi1 = qi0 + 8;
    int rq0 = qi0 / GG, cq0 = qi0 - rq0 * GG;
    int rq1 = qi1 / GG, cq1 = qi1 - rq1 * GG;

    float m0 = -1e30f, m1 = -1e30f, l0 = 0.f, l1 = 0.f;
    float acc_o[8][4] = {};

    const __half* vbase = qkv + (size_t)(b * TT) * (3 * EE) + 2 * EE + h * DHEAD;

    for (int kb = 0; kb < 7; kb++) {
        int k0 = kb * 128;
        __syncthreads();

        {
            int krow = k0 + lrow;
            bool kv2 = krow < TT;
            const __half* sKg = qkv + (size_t)(b * TT + (kv2 ? krow : 0)) * (3 * EE) + EE + h * DHEAD + lpart * 32;
            uint32_t dk = smb + 18432 + lrow * (QST * 2) + lpart * 64;
            #pragma unroll
            for (int c = 0; c < 4; c++) cpa16z(dk + c * 16, sKg + c * 8, kv2);
        }
        cp_commit();

        {
            int vd = tid & 63;
            int kbase = (tid >> 6) * 32;
            #pragma unroll
            for (int i = 0; i < 32; i++) {
                int k = kbase + i;
                int tok = k0 + k;
                __half v = (tok < TT) ? vbase[(size_t)tok * (3 * EE) + vd] : __half(0.f);
                sV[vd * VST + k] = v;
            }
        }
        cp_wait0();
        __syncthreads();

        float s[16][4] = {};
        #pragma unroll
        for (int ds = 0; ds < 4; ds++) {
            int ks = ds * 16;
            const __half* pa = sQ + (16 * warp + r) * QST + ks + t2;
            uint32_t a0 = *(const uint32_t*)pa;
            uint32_t a1 = *(const uint32_t*)(pa + 8 * QST);
            uint32_t a2 = *(const uint32_t*)(pa + 8);
            uint32_t a3 = *(const uint32_t*)(pa + 8 * QST + 8);
            #pragma unroll
            for (int j = 0; j < 16; j++) {
                const __half* pk = sK + (8 * j + r) * QST + ks + t2;
                uint32_t b0 = *(const uint32_t*)pk;
                uint32_t b1 = *(const uint32_t*)(pk + 8);
                mma_f16(s[j], a0, a1, a2, a3, b0, b1);
            }
        }

        float bm0 = -1e30f, bm1 = -1e30f;
        #pragma unroll
        for (int j = 0; j < 16; j++) {
            #pragma unroll
            for (int e = 0; e < 2; e++) {
                int ki = k0 + 8 * j + t2 + e;
                int rk = ki / GG, ck = ki - rk * GG;
                bool oob = ki >= TT;
                float v0 = s[j][e] * 0.125f;
                if (oob || (abs(rq0 - rk) <= 4 && abs(cq0 - ck) <= 4)) v0 = -1e30f;
                s[j][e] = v0;
                bm0 = fmaxf(bm0, v0);
                float v1 = s[j][e + 2] * 0.125f;
                if (oob || (abs(rq1 - rk) <= 4 && abs(cq1 - ck) <= 4)) v1 = -1e30f;
                s[j][e + 2] = v1;
                bm1 = fmaxf(bm1, v1);
            }
        }
        bm0 = fmaxf(bm0, __shfl_xor_sync(0xFFFFFFFFu, bm0, 1));
        bm0 = fmaxf(bm0, __shfl_xor_sync(0xFFFFFFFFu, bm0, 2));
        bm1 = fmaxf(bm1, __shfl_xor_sync(0xFFFFFFFFu, bm1, 1));
        bm1 = fmaxf(bm1, __shfl_xor_sync(0xFFFFFFFFu, bm1, 2));

        float nm0 = fmaxf(m0, bm0), nm1 = fmaxf(m1, bm1);
        float sc0 = __expf(m0 - nm0), sc1 = __expf(m1 - nm1);
        m0 = nm0; m1 = nm1;

        float rs0 = 0.f, rs1 = 0.f;
        #pragma unroll
        for (int j = 0; j < 16; j++) {
            #pragma unroll
            for (int e = 0; e < 2; e++) {
                float p0 = __expf(s[j][e] - m0);
                s[j][e] = p0; rs0 += p0;
                float p1 = __expf(s[j][e + 2] - m1);
                s[j][e + 2] = p1; rs1 += p1;
            }
        }
        rs0 += __shfl_xor_sync(0xFFFFFFFFu, rs0, 1);
        rs0 += __shfl_xor_sync(0xFFFFFFFFu, rs0, 2);
        rs1 += __shfl_xor_sync(0xFFFFFFFFu, rs1, 1);
        rs1 += __shfl_xor_sync(0xFFFFFFFFu, rs1, 2);
        l0 = l0 * sc0 + rs0;
        l1 = l1 * sc1 + rs1;

        #pragma unroll
        for (int j2 = 0; j2 < 8; j2++) {
            acc_o[j2][0] *= sc0; acc_o[j2][1] *= sc0;
            acc_o[j2][2] *= sc1; acc_o[j2][3] *= sc1;
        }

        #pragma unroll
        for (int s2 = 0; s2 < 8; s2++) {
            uint32_t a0 = packh2(__float2half_rn(s[2 * s2][0]),     __float2half_rn(s[2 * s2][1]));
            uint32_t a1 = packh2(__float2half_rn(s[2 * s2][2]),     __float2half_rn(s[2 * s2][3]));
            uint32_t a2 = packh2(__float2half_rn(s[2 * s2 + 1][0]), __float2half_rn(s[2 * s2 + 1][1]));
            uint32_t a3 = packh2(__float2half_rn(s[2 * s2 + 1][2]), __float2half_rn(s[2 * s2 + 1][3]));
            #pragma unroll
            for (int j2 = 0; j2 < 8; j2++) {
                const __half* pv = sV + (8 * j2 + r) * VST + 16 * s2 + t2;
                uint32_t b0 = *(const uint32_t*)pv;
                uint32_t b1 = *(const uint32_t*)(pv + 8);
                mma_f16(acc_o[j2], a0, a1, a2, a3, b0, b1);
            }
        }
    }

    float il0 = 1.f / l0, il1 = 1.f / l1;
    #pragma unroll
    for (int j2 = 0; j2 < 8; j2++) {
        #pragma unroll
        for (int e = 0; e < 2; e++) {
            int d = 8 * j2 + t2 + e;
            if (qi0 < TT)
                oh[(size_t)(b * TT + qi0) * EE + h * DHEAD + d] = __float2half_rn(acc_o[j2][e] * il0);
            if (qi1 < TT)
                oh[(size_t)(b * TT + qi1) * EE + h * DHEAD + d] = __float2half_rn(acc_o[j2][e + 2] * il1);
        }
    }
}

// ---------------- layernorm: warp per token ----------------
__global__ void ln_kernel(const float* __restrict__ x, const float* __restrict__ g,
                          const float* __restrict__ bp, __half* __restrict__ yh)
{
    int warp = threadIdx.x >> 5, lane = threadIdx.x & 31;
    int m = blockIdx.x * 8 + warp;
    const float4* xr = reinterpret_cast<const float4*>(x + (size_t)m * EE);

    float4 v[6];
    float s = 0.f, s2 = 0.f;
    #pragma unroll
    for (int k = 0; k < 6; k++) {
        v[k] = xr[lane + 32 * k];
        s  += v[k].x + v[k].y + v[k].z + v[k].w;
        s2 += v[k].x * v[k].x + v[k].y * v[k].y + v[k].z * v[k].z + v[k].w * v[k].w;
    }
    #pragma unroll
    for (int o = 16; o > 0; o >>= 1) {
        s  += __shfl_xor_sync(0xFFFFFFFFu, s, o);
        s2 += __shfl_xor_sync(0xFFFFFFFFu, s2, o);
    }
    float mean = s * (1.0f / EE);
    float inv = rsqrtf(s2 * (1.0f / EE) - mean * mean + 1e-5f);

    __half2* ph = reinterpret_cast<__half2*>(yh + (size_t)m * EE);
    #pragma unroll
    for (int k = 0; k < 6; k++) {
        float4 gg = reinterpret_cast<const float4*>(g)[lane + 32 * k];
        float4 bb = reinterpret_cast<const float4*>(bp)[lane + 32 * k];
        float o0 = (v[k].x - mean) * inv * gg.x + bb.x;
        float o1 = (v[k].y - mean) * inv * gg.y + bb.y;
        float o2 = (v[k].z - mean) * inv * gg.z + bb.z;
        float o3 = (v[k].w - mean) * inv * gg.w + bb.w;
        int idx = (lane + 32 * k) * 2;
        ph[idx]     = __halves2half2(__float2half_rn(o0), __float2half_rn(o1));
        ph[idx + 1] = __halves2half2(__float2half_rn(o2), __float2half_rn(o3));
    }
}

// ---------------- head + flux ----------------
__global__ void head_kernel(const float* __restrict__ hbuf,
                            const float* __restrict__ lnw, const float* __restrict__ lnb,
                            const float* __restrict__ hw, const float* __restrict__ hb,
                            const float* __restrict__ mean_s, const float* __restrict__ std_s,
                            float* __restrict__ out)
{
    int warp = threadIdx.x >> 5, lane = threadIdx.x & 31;
    int m = blockIdx.x * 8 + warp;
    const float4* xr = reinterpret_cast<const float4*>(hbuf + (size_t)m * EE);

    float4 v[6];
    float s = 0.f, s2 = 0.f;
    #pragma unroll
    for (int k = 0; k < 6; k++) {
        v[k] = xr[lane + 32 * k];
        s  += v[k].x + v[k].y + v[k].z + v[k].w;
        s2 += v[k].x * v[k].x + v[k].y * v[k].y + v[k].z * v[k].z + v[k].w * v[k].w;
    }
    #pragma unroll
    for (int o = 16; o > 0; o >>= 1) {
        s  += __shfl_xor_sync(0xFFFFFFFFu, s, o);
        s2 += __shfl_xor_sync(0xFFFFFFFFu, s2, o);
    }
    float mean = s * (1.0f / EE);
    float inv = rsqrtf(s2 * (1.0f / EE) - mean * mean + 1e-5f);

    float dot = 0.f;
    #pragma unroll
    for (int k = 0; k < 6; k++) {
        float4 gg = reinterpret_cast<const float4*>(lnw)[lane + 32 * k];
        float4 bb = reinterpret_cast<const float4*>(lnb)[lane + 32 * k];
        float4 ww = reinterpret_cast<const float4*>(hw)[lane + 32 * k];
        dot += ((v[k].x - mean) * inv * gg.x + bb.x) * ww.x;
        dot += ((v[k].y - mean) * inv * gg.y + bb.y) * ww.y;
        dot += ((v[k].z - mean) * inv * gg.z + bb.z) * ww.z;
        dot += ((v[k].w - mean) * inv * gg.w + bb.w) * ww.w;
    }
    #pragma unroll
    for (int o = 16; o > 0; o >>= 1)
        dot += __shfl_xor_sync(0xFFFFFFFFu, dot, o);

    if (lane == 0) {
        float logit = dot + hb[0];
        float lg = logit * std_s[0] + mean_s[0];
        float pf = exp10f(lg) - 1e-8f;
        pf = fminf(fmaxf(pf, 1e-15f), 1.0f);
        out[BB + m] = pf;
    }
}

__global__ void flux_reduce(float* __restrict__ out)
{
    int b = blockIdx.x;
    __shared__ float red[256];
    int tid = threadIdx.x;
    float s = 0.f;
    for (int i = tid; i < TT; i += 256) s += out[BB + b * TT + i];
    red[tid] = s; __syncthreads();
    for (int st = 128; st > 0; st >>= 1) { if (tid < st) red[tid] += red[tid + st]; __syncthreads(); }
    if (tid == 0) out[b] = fmaxf(red[0], 1e-15f);
}

// ---------------- launcher ----------------
extern "C" void kernel_launch(void* const* d_in, const int* in_sizes, int n_in,
                              void* d_out, int out_size)
{
    const float* x        = (const float*)d_in[0];
    const float* sxr_mean = (const float*)d_in[1];
    const float* sxr_std  = (const float*)d_in[2];
    const float* input_w  = (const float*)d_in[3];
    const float* input_b  = (const float*)d_in[4];
    const float* pos_emb  = (const float*)d_in[5];
    const float* ln1_w    = (const float*)d_in[6];
    const float* ln1_b    = (const float*)d_in[7];
    const float* in_w     = (const float*)d_in[8];
    const float* in_b     = (const float*)d_in[9];
    const float* out_w    = (const float*)d_in[10];
    const float* out_b    = (const float*)d_in[11];
    const float* ln2_w    = (const float*)d_in[12];
    const float* ln2_b    = (const float*)d_in[13];
    const float* w1       = (const float*)d_in[14];
    const float* b1       = (const float*)d_in[15];
    const float* w2       = (const float*)d_in[16];
    const float* b2       = (const float*)d_in[17];
    const float* head_lnw = (const float*)d_in[18];
    const float* head_lnb = (const float*)d_in[19];
    const float* head_w   = (const float*)d_in[20];
    const float* head_b   = (const float*)d_in[21];
    float* out = (float*)d_out;

    __half *xp, *y, *qkv, *o, *mlp;
    __half *iwh, *inwh, *outwh, *w1h, *w2h;
    float *h;
    cudaGetSymbolAddress((void**)&xp,    g_xp);
    cudaGetSymbolAddress((void**)&h,     g_h);
    cudaGetSymbolAddress((void**)&y,     g_y);
    cudaGetSymbolAddress((void**)&qkv,   g_qkv);
    cudaGetSymbolAddress((void**)&o,     g_o);
    cudaGetSymbolAddress((void**)&mlp,   g_mlp);
    cudaGetSymbolAddress((void**)&iwh,   g_iw_h);
    cudaGetSymbolAddress((void**)&inwh,  g_inw_h);
    cudaGetSymbolAddress((void**)&outwh, g_outw_h);
    cudaGetSymbolAddress((void**)&w1h,   g_w1_h);
    cudaGetSymbolAddress((void**)&w2h,   g_w2_h);

    static bool attr_done = false;
    if (!attr_done) {
        cudaFuncSetAttribute(gemm128, cudaFuncAttributeMaxDynamicSharedMemorySize, 110592);
        cudaFuncSetAttribute(gemm64,  cudaFuncAttributeMaxDynamicSharedMemorySize, 46080);
        cudaFuncSetAttribute(flash_attn, cudaFuncAttributeMaxDynamicSharedMemorySize, 56320);
        attr_done = true;
    }

    {
        long total = (long)CN0 + CN1 + CN2 + CN3 + CN4;
        int blocks = (int)((total + 255) / 256);
        conv_all<<<blocks, 256>>>(
            (const float4*)input_w, (const float4*)in_w, (const float4*)out_w,
            (const float4*)w1, (const float4*)w2,
            (__half2*)iwh, (__half2*)inwh, (__half2*)outwh,
            (__half2*)w1h, (__half2*)w2h);
    }

    patch_gather<<<(MM * EE + 255) / 256, 256>>>(x, xp);
    gemm64<<<dim3(EE / 128, MPAD / 64), 256, 46080>>>(
        xp, iwh, input_b, pos_emb, h, nullptr, MPAD, EE, EE, EPI_POS, 0);

    for (int l = 0; l < NLAYERS; l++) {
        const float* l1w = ln1_w + (size_t)l * EE;
        const float* l1b = ln1_b + (size_t)l * EE;
        const float* ib  = in_b  + (size_t)l * 3 * EE;
        const float* ob  = out_b + (size_t)l * EE;
        const float* l2w = ln2_w + (size_t)l * EE;
        const float* l2b = ln2_b + (size_t)l * EE;
        const float* B1  = b1 + (size_t)l * HDIM;
        const float* B2  = b2 + (size_t)l * EE;
        size_t inoff  = (size_t)l * 3 * EE * EE;
        size_t outoff = (size_t)l * EE * EE;
        size_t w1off  = (size_t)l * HDIM * EE;
        size_t w2off  = (size_t)l * EE * HDIM;

        ln_kernel<<<MM / 8, 256>>>(h, l1w, l1b, y);
        gemm128<<<dim3(3 * EE / 128, MPAD / 128), 256, 110592>>>(
            y, inwh + inoff, ib, nullptr, nullptr, qkv, MPAD, 3 * EE, EE, EPI_NONE, 1);
        flash_attn<<<dim3(7, NBH), 256, 56320>>>(qkv, o);
        gemm64<<<dim3(EE / 128, MPAD / 64), 256, 46080>>>(
            o, outwh + outoff, ob, h, h, nullptr, MPAD, EE, EE, EPI_RES, 0);
        ln_kernel<<<MM / 8, 256>>>(h, l2w, l2b, y);
        gemm128<<<dim3(HDIM / 128, MPAD / 128), 256, 110592>>>(
            y, w1h + w1off, B1, nullptr, nullptr, mlp, MPAD, HDIM, EE, EPI_GELU, 1);
        gemm64<<<dim3(EE / 128, MPAD / 64), 256, 46080>>>(
            mlp, w2h + w2off, B2, h, h, nullptr, MPAD, EE, HDIM, EPI_RES, 0);
    }

    head_kernel<<<MM / 8, 256>>>(h, head_lnw, head_lnb, head_w, head_b,
                                 sxr_mean, sxr_std, out);
    flux_reduce<<<BB, 256>>>(out);
}

// round 16
// speedup vs baseline: 1.5232x; 1.0278x over previous
#include <cuda_runtime.h>
#include <cuda_fp16.h>
#include <math.h>
#include <stdint.h>

// ---------------- problem constants ----------------
#define BB 4
#define TT 784
#define GG 28
#define EE 768
#define HDIM 3072
#define NHEADS 12
#define DHEAD 64
#define NLAYERS 6
#define MM (BB*TT)        // 3136
#define MPAD 3200
#define NBH (BB*NHEADS)   // 48

// ---------------- scratch ----------------
__device__ __half g_xp[MPAD * EE];
__device__ float  g_h[MPAD * EE];
__device__ __half g_y[MPAD * EE];
__device__ __half g_qkv[MPAD * 3 * EE];
__device__ __half g_o[MPAD * EE];
__device__ __half g_mlp[MPAD * HDIM];
// pre-converted fp16 weights
__device__ __half g_iw_h[EE * EE];
__device__ __half g_inw_h[NLAYERS * 3 * EE * EE];
__device__ __half g_outw_h[NLAYERS * EE * EE];
__device__ __half g_w1_h[NLAYERS * HDIM * EE];
__device__ __half g_w2_h[NLAYERS * EE * HDIM];

#define EPI_NONE 0
#define EPI_POS  1
#define EPI_RES  2
#define EPI_GELU 3

// ---------------- helpers ----------------
__device__ __forceinline__ uint32_t packh2(__half a, __half b) {
    __half2 x = __halves2half2(a, b);
    return *reinterpret_cast<uint32_t*>(&x);
}

__device__ __forceinline__ void mma_f16(float d[4],
                                        uint32_t a0, uint32_t a1, uint32_t a2, uint32_t a3,
                                        uint32_t b0, uint32_t b1) {
    asm volatile(
        "mma.sync.aligned.m16n8k16.row.col.f32.f16.f16.f32 "
        "{%0,%1,%2,%3}, {%4,%5,%6,%7}, {%8,%9}, {%0,%1,%2,%3};"
        : "+f"(d[0]), "+f"(d[1]), "+f"(d[2]), "+f"(d[3])
        : "r"(a0), "r"(a1), "r"(a2), "r"(a3), "r"(b0), "r"(b1));
}

#define LDSM_X4(r0, r1, r2, r3, addr) \
    asm volatile("ldmatrix.sync.aligned.m8n8.x4.shared.b16 {%0,%1,%2,%3}, [%4];" \
        : "=r"(r0), "=r"(r1), "=r"(r2), "=r"(r3) : "r"(addr))

#define LDSM_X4T(r0, r1, r2, r3, addr) \
    asm volatile("ldmatrix.sync.aligned.m8n8.x4.trans.shared.b16 {%0,%1,%2,%3}, [%4];" \
        : "=r"(r0), "=r"(r1), "=r"(r2), "=r"(r3) : "r"(addr))

__device__ __forceinline__ void cpa16(uint32_t dst, const void* src) {
    asm volatile("cp.async.cg.shared.global [%0], [%1], 16;" :: "r"(dst), "l"(src));
}
__device__ __forceinline__ void cpa16z(uint32_t dst, const void* src, bool valid) {
    int sz = valid ? 16 : 0;
    asm volatile("cp.async.cg.shared.global [%0], [%1], 16, %2;"
                 :: "r"(dst), "l"(src), "r"(sz));
}
__device__ __forceinline__ void cp_commit() { asm volatile("cp.async.commit_group;"); }
__device__ __forceinline__ void cp_wait0() { asm volatile("cp.async.wait_group 0;"); }
__device__ __forceinline__ void cp_wait1() { asm volatile("cp.async.wait_group 1;"); }

// ---------------- epilogue ----------------
__device__ __forceinline__ void epi_store(float v, int m, int n, int N, int epi, int split,
                                          const float* bias, const float* extra,
                                          float* C, __half* Ch)
{
    v += bias[n];
    if (epi == EPI_POS)       v += extra[(size_t)(m % TT) * N + n];
    else if (epi == EPI_RES)  v += extra[(size_t)m * N + n];
    else if (epi == EPI_GELU) v = 0.5f * v * (1.0f + erff(v * 0.70710678118654752f));
    if (split) Ch[(size_t)m * N + n] = __float2half_rn(v);
    else       C[(size_t)m * N + n] = v;
}

// ---------------- merged weight convert ----------------
#define CN0 ((EE*EE)/4)
#define CN1 ((NLAYERS*3*EE*EE)/4)
#define CN2 ((NLAYERS*EE*EE)/4)
#define CN3 ((NLAYERS*HDIM*EE)/4)
#define CN4 ((NLAYERS*EE*HDIM)/4)
__global__ void conv_all(const float4* __restrict__ s0, const float4* __restrict__ s1,
                         const float4* __restrict__ s2, const float4* __restrict__ s3,
                         const float4* __restrict__ s4,
                         __half2* __restrict__ d0, __half2* __restrict__ d1,
                         __half2* __restrict__ d2, __half2* __restrict__ d3,
                         __half2* __restrict__ d4)
{
    long i = (long)blockIdx.x * 256 + threadIdx.x;
    const float4* s; __half2* d; long off;
    if (i < CN0)                                    { s = s0; d = d0; off = i; }
    else if (i < (long)CN0 + CN1)                   { s = s1; d = d1; off = i - CN0; }
    else if (i < (long)CN0 + CN1 + CN2)             { s = s2; d = d2; off = i - CN0 - CN1; }
    else if (i < (long)CN0 + CN1 + CN2 + CN3)       { s = s3; d = d3; off = i - CN0 - CN1 - CN2; }
    else if (i < (long)CN0 + CN1 + CN2 + CN3 + CN4) { s = s4; d = d4; off = i - CN0 - CN1 - CN2 - CN3; }
    else return;
    float4 a = s[off];
    d[2 * off]     = __halves2half2(__float2half_rn(a.x), __float2half_rn(a.y));
    d[2 * off + 1] = __halves2half2(__float2half_rn(a.z), __float2half_rn(a.w));
}

// ---------------- patch gather ----------------
__global__ void patch_gather(const float* __restrict__ x, __half* __restrict__ xh) {
    int idx = blockIdx.x * 256 + threadIdx.x;
    if (idx >= MM * EE) return;
    int j = idx % EE;
    int m = idx / EE;
    int b = m / TT, t = m % TT;
    int gr = t / GG, gc = t % GG;
    int ch = j >> 8, pr = (j >> 4) & 15, pc = j & 15;
    float v = x[(((size_t)b * 448 + gr * 16 + pr) * 448 + (gc * 16 + pc)) * 3 + ch];
    xh[idx] = __float2half_rn(v);
}

// ---------------- GEMM A: 128x128 block tile, k-chunk 64, 3-stage ----------------
#define GSTW 72
#define STG128 36864
__global__ __launch_bounds__(256, 2)
void gemm128(const __half* __restrict__ Ah, const __half* __restrict__ Wh,
             const float* __restrict__ bias, const float* __restrict__ extra,
             float* __restrict__ C, __half* __restrict__ Ch,
             int M, int N, int K, int epi, int split)
{
    extern __shared__ __half smh[];
    int tid = threadIdx.x, warp = tid >> 5, lane = tid & 31;
    int r = lane >> 2, t2 = (lane & 3) * 2;
    int m0 = blockIdx.y * 128, n0 = blockIdx.x * 128;
    int wm = (warp & 3) * 32, wn = (warp >> 2) * 64;
    uint32_t smb = (uint32_t)__cvta_generic_to_shared(smh);

    int lrow = tid >> 1, lpart = tid & 1;
    const __half* srcA = Ah + (size_t)(m0 + lrow) * K + lpart * 32;
    const __half* srcW = Wh + (size_t)(n0 + lrow) * K + lpart * 32;
    uint32_t dA = smb + (uint32_t)(lrow * GSTW + lpart * 32) * 2;

    int a_row = wm + (lane & 15);
    int a_col = (lane >> 4) << 3;
    int b_row = wn + ((lane >> 4) << 3) + (lane & 7);
    int b_col = ((lane >> 3) & 1) << 3;

    float acc[2][8][4] = {};
    const int KT = K >> 6;

    auto issue = [&](int st, int kc) {
        int k0 = kc << 6;
        uint32_t base = st * STG128;
        #pragma unroll
        for (int c = 0; c < 4; c++) {
            cpa16(dA + base + c * 16,         srcA + k0 + c * 8);
            cpa16(dA + base + 18432 + c * 16, srcW + k0 + c * 8);
        }
    };

    issue(0, 0); cp_commit();
    if (KT > 1) { issue(1, 1); cp_commit(); }

    int st2 = 2;
    for (int kc = 0; kc < KT; kc++) {
        if (kc + 1 < KT) cp_wait1(); else cp_wait0();
        __syncthreads();
        if (kc + 2 < KT) {
            issue(st2, kc + 2); cp_commit();
            st2 = (st2 == 2) ? 0 : st2 + 1;
        }

        uint32_t aA = smb + (kc % 3) * STG128;
        uint32_t aW = aA + 18432;

        #pragma unroll
        for (int s = 0; s < 4; s++) {
            int ks = s * 16;
            uint32_t ah[2][4];
            #pragma unroll
            for (int i2 = 0; i2 < 2; i2++) {
                uint32_t adr = (uint32_t)((a_row + 16 * i2) * GSTW + ks + a_col) * 2;
                LDSM_X4(ah[i2][0], ah[i2][1], ah[i2][2], ah[i2][3], aA + adr);
            }
            #pragma unroll
            for (int jj = 0; jj < 4; jj++) {
                uint32_t badr = aW + (uint32_t)((b_row + 16 * jj) * GSTW + ks + b_col) * 2;
                uint32_t b00, b01, b10, b11;
                LDSM_X4(b00, b01, b10, b11, badr);
                #pragma unroll
                for (int i2 = 0; i2 < 2; i2++) {
                    mma_f16(acc[i2][2 * jj],     ah[i2][0], ah[i2][1], ah[i2][2], ah[i2][3], b00, b01);
                    mma_f16(acc[i2][2 * jj + 1], ah[i2][0], ah[i2][1], ah[i2][2], ah[i2][3], b10, b11);
                }
            }
        }
    }

    __syncthreads();
    #pragma unroll
    for (int i2 = 0; i2 < 2; i2++) {
        #pragma unroll
        for (int j = 0; j < 8; j++) {
            #pragma unroll
            for (int half = 0; half < 2; half++) {
                int m = m0 + wm + 16 * i2 + r + half * 8;
                #pragma unroll
                for (int e = 0; e < 2; e++) {
                    int n = n0 + wn + 8 * j + t2 + e;
                    epi_store(acc[i2][j][half * 2 + e], m, n, N, epi, split,
                              bias, extra, C, Ch);
                }
            }
        }
    }
}

// ---------------- GEMM B: 64x128 block tile, k-chunk 32, 3-stage ----------------
#define GST 40
#define STG64 15360
__global__ __launch_bounds__(256, 3)
void gemm64(const __half* __restrict__ Ah, const __half* __restrict__ Wh,
            const float* __restrict__ bias, const float* __restrict__ extra,
            float* __restrict__ C, __half* __restrict__ Ch,
            int M, int N, int K, int epi, int split)
{
    extern __shared__ __half smh[];
    int tid = threadIdx.x, warp = tid >> 5, lane = tid & 31;
    int r = lane >> 2, t2 = (lane & 3) * 2;
    int m0 = blockIdx.y * 64, n0 = blockIdx.x * 128;
    int wm = (warp & 3) * 16, wn = (warp >> 2) * 64;
    uint32_t smb = (uint32_t)__cvta_generic_to_shared(smh);

    int a_lrow = tid >> 2, a_seg = tid & 3;
    int w_lrow = tid >> 1, w_seg0 = (tid & 1) * 2;
    const __half* srcA = Ah + (size_t)(m0 + a_lrow) * K + a_seg * 8;
    const __half* srcW = Wh + (size_t)(n0 + w_lrow) * K;
    uint32_t dA = smb + (uint32_t)(a_lrow * GST + a_seg * 8) * 2;
    uint32_t dW = smb + 5120 + (uint32_t)(w_lrow * GST) * 2;

    int a_row = wm + (lane & 15);
    int a_col = (lane >> 4) << 3;
    int b_row = wn + ((lane >> 4) << 3) + (lane & 7);
    int b_col = ((lane >> 3) & 1) << 3;

    float acc[8][4] = {};
    const int KT = K >> 5;

    auto issue = [&](int st, int kc) {
        int k0 = kc << 5;
        uint32_t sb = st * STG64;
        cpa16(dA + sb, srcA + k0);
        cpa16(dW + sb + w_seg0 * 16,       srcW + k0 + w_seg0 * 8);
        cpa16(dW + sb + (w_seg0 + 1) * 16, srcW + k0 + (w_seg0 + 1) * 8);
    };

    issue(0, 0); cp_commit();
    if (KT > 1) { issue(1, 1); cp_commit(); }

    int st2 = 2;
    for (int kc = 0; kc < KT; kc++) {
        if (kc + 1 < KT) cp_wait1(); else cp_wait0();
        __syncthreads();
        if (kc + 2 < KT) {
            issue(st2, kc + 2); cp_commit();
            st2 = (st2 == 2) ? 0 : st2 + 1;
        }

        uint32_t aA = smb + (kc % 3) * STG64;
        uint32_t aW = aA + 5120;

        #pragma unroll
        for (int s = 0; s < 2; s++) {
            int ks = s * 16;
            uint32_t ah[4];
            {
                uint32_t adr = (uint32_t)(a_row * GST + ks + a_col) * 2;
                LDSM_X4(ah[0], ah[1], ah[2], ah[3], aA + adr);
            }
            #pragma unroll
            for (int jj = 0; jj < 4; jj++) {
                uint32_t badr = aW + (uint32_t)((b_row + 16 * jj) * GST + ks + b_col) * 2;
                uint32_t b00, b01, b10, b11;
                LDSM_X4(b00, b01, b10, b11, badr);
                mma_f16(acc[2 * jj],     ah[0], ah[1], ah[2], ah[3], b00, b01);
                mma_f16(acc[2 * jj + 1], ah[0], ah[1], ah[2], ah[3], b10, b11);
            }
        }
    }

    __syncthreads();
    #pragma unroll
    for (int j = 0; j < 8; j++) {
        #pragma unroll
        for (int half = 0; half < 2; half++) {
            int m = m0 + wm + r + half * 8;
            #pragma unroll
            for (int e = 0; e < 2; e++) {
                int n = n0 + wn + 8 * j + t2 + e;
                epi_store(acc[j][half * 2 + e], m, n, N, epi, split,
                          bias, extra, C, Ch);
            }
        }
    }
}

// ---------------- fused flash attention: coalesced V + ldmatrix.trans ----------------
#define QST 72
__global__ __launch_bounds__(256, 2)
void flash_attn(const __half* __restrict__ qkv, __half* __restrict__ oh)
{
    extern __shared__ __half sm[];
    __half* sQ = sm;                  // 128 x 72 halves
    __half* sK = sm + 9216;           // 128 x 72
    __half* sV = sm + 18432;          // 128 x 72  [k][d]

    int bh = blockIdx.y, b = bh / NHEADS, h = bh % NHEADS;
    int q0 = blockIdx.x * 128;
    int tid = threadIdx.x, warp = tid >> 5, lane = tid & 31;
    int r = lane >> 2, t2 = (lane & 3) * 2;
    uint32_t smb = (uint32_t)__cvta_generic_to_shared(sm);

    int lrow = tid >> 1, lpart = tid & 1;

    // ---- load Q tile (once) ----
    {
        int qrow = q0 + lrow;
        bool qv = qrow < TT;
        const __half* sQg = qkv + (size_t)(b * TT + (qv ? qrow : 0)) * (3 * EE) + h * DHEAD + lpart * 32;
        uint32_t d0 = smb + lrow * (QST * 2) + lpart * 64;
        #pragma unroll
        for (int c = 0; c < 4; c++) cpa16z(d0 + c * 16, sQg + c * 8, qv);
    }
    cp_commit();

    int qi0 = q0 + 16 * warp + r;
    int qi1 = qi0 + 8;
    int rq0 = qi0 / GG, cq0 = qi0 - rq0 * GG;
    int rq1 = qi1 / GG, cq1 = qi1 - rq1 * GG;

    float m0 = -1e30f, m1 = -1e30f, l0 = 0.f, l1 = 0.f;
    float acc_o[8][4] = {};

    for (int kb = 0; kb < 7; kb++) {
        int k0 = kb * 128;
        __syncthreads();

        // ---- load K and V tiles (both coalesced, [k][d] rows of 128B) ----
        {
            int krow = k0 + lrow;
            bool kv2 = krow < TT;
            const __half* sKg = qkv + (size_t)(b * TT + (kv2 ? krow : 0)) * (3 * EE) + EE + h * DHEAD + lpart * 32;
            const __half* sVg = qkv + (size_t)(b * TT + (kv2 ? krow : 0)) * (3 * EE) + 2 * EE + h * DHEAD + lpart * 32;
            uint32_t dk = smb + 18432 + lrow * (QST * 2) + lpart * 64;
            uint32_t dv = smb + 36864 + lrow * (QST * 2) + lpart * 64;
            #pragma unroll
            for (int c = 0; c < 4; c++) {
                cpa16z(dk + c * 16, sKg + c * 8, kv2);
                cpa16z(dv + c * 16, sVg + c * 8, kv2);
            }
        }
        cp_commit(); cp_wait0();
        __syncthreads();

        // ---- S = Q.K^T single pass ----
        float s[16][4] = {};
        #pragma unroll
        for (int ds = 0; ds < 4; ds++) {
            int ks = ds * 16;
            const __half* pa = sQ + (16 * warp + r) * QST + ks + t2;
            uint32_t a0 = *(const uint32_t*)pa;
            uint32_t a1 = *(const uint32_t*)(pa + 8 * QST);
            uint32_t a2 = *(const uint32_t*)(pa + 8);
            uint32_t a3 = *(const uint32_t*)(pa + 8 * QST + 8);
            #pragma unroll
            for (int j = 0; j < 16; j++) {
                const __half* pk = sK + (8 * j + r) * QST + ks + t2;
                uint32_t b0 = *(const uint32_t*)pk;
                uint32_t b1 = *(const uint32_t*)(pk + 8);
                mma_f16(s[j], a0, a1, a2, a3, b0, b1);
            }
        }

        // ---- mask + scale, online softmax ----
        float bm0 = -1e30f, bm1 = -1e30f;
        #pragma unroll
        for (int j = 0; j < 16; j++) {
            #pragma unroll
            for (int e = 0; e < 2; e++) {
                int ki = k0 + 8 * j + t2 + e;
                int rk = ki / GG, ck = ki - rk * GG;
                bool oob = ki >= TT;
                float v0 = s[j][e] * 0.125f;
                if (oob || (abs(rq0 - rk) <= 4 && abs(cq0 - ck) <= 4)) v0 = -1e30f;
                s[j][e] = v0;
                bm0 = fmaxf(bm0, v0);
                float v1 = s[j][e + 2] * 0.125f;
                if (oob || (abs(rq1 - rk) <= 4 && abs(cq1 - ck) <= 4)) v1 = -1e30f;
                s[j][e + 2] = v1;
                bm1 = fmaxf(bm1, v1);
            }
        }
        bm0 = fmaxf(bm0, __shfl_xor_sync(0xFFFFFFFFu, bm0, 1));
        bm0 = fmaxf(bm0, __shfl_xor_sync(0xFFFFFFFFu, bm0, 2));
        bm1 = fmaxf(bm1, __shfl_xor_sync(0xFFFFFFFFu, bm1, 1));
        bm1 = fmaxf(bm1, __shfl_xor_sync(0xFFFFFFFFu, bm1, 2));

        float nm0 = fmaxf(m0, bm0), nm1 = fmaxf(m1, bm1);
        float sc0 = __expf(m0 - nm0), sc1 = __expf(m1 - nm1);
        m0 = nm0; m1 = nm1;

        float rs0 = 0.f, rs1 = 0.f;
        #pragma unroll
        for (int j = 0; j < 16; j++) {
            #pragma unroll
            for (int e = 0; e < 2; e++) {
                float p0 = __expf(s[j][e] - m0);
                s[j][e] = p0; rs0 += p0;
                float p1 = __expf(s[j][e + 2] - m1);
                s[j][e + 2] = p1; rs1 += p1;
            }
        }
        rs0 += __shfl_xor_sync(0xFFFFFFFFu, rs0, 1);
        rs0 += __shfl_xor_sync(0xFFFFFFFFu, rs0, 2);
        rs1 += __shfl_xor_sync(0xFFFFFFFFu, rs1, 1);
        rs1 += __shfl_xor_sync(0xFFFFFFFFu, rs1, 2);
        l0 = l0 * sc0 + rs0;
        l1 = l1 * sc1 + rs1;

        #pragma unroll
        for (int j2 = 0; j2 < 8; j2++) {
            acc_o[j2][0] *= sc0; acc_o[j2][1] *= sc0;
            acc_o[j2][2] *= sc1; acc_o[j2][3] *= sc1;
        }

        // ---- O += P.V  (V [k][d] via ldmatrix.trans) ----
        #pragma unroll
        for (int s2 = 0; s2 < 8; s2++) {
            uint32_t a0 = packh2(__float2half_rn(s[2 * s2][0]),     __float2half_rn(s[2 * s2][1]));
            uint32_t a1 = packh2(__float2half_rn(s[2 * s2][2]),     __float2half_rn(s[2 * s2][3]));
            uint32_t a2 = packh2(__float2half_rn(s[2 * s2 + 1][0]), __float2half_rn(s[2 * s2 + 1][1]));
            uint32_t a3 = packh2(__float2half_rn(s[2 * s2 + 1][2]), __float2half_rn(s[2 * s2 + 1][3]));
            uint32_t vb = smb + 36864 +
                (uint32_t)((16 * s2 + (lane & 15)) * QST + 8 * (lane >> 4)) * 2;
            #pragma unroll
            for (int jp = 0; jp < 4; jp++) {
                uint32_t b00, b01, b10, b11;
                LDSM_X4T(b00, b01, b10, b11, vb + jp * 32);
                mma_f16(acc_o[2 * jp],     a0, a1, a2, a3, b00, b01);
                mma_f16(acc_o[2 * jp + 1], a0, a1, a2, a3, b10, b11);
            }
        }
    }

    // ---- epilogue ----
    float il0 = 1.f / l0, il1 = 1.f / l1;
    #pragma unroll
    for (int j2 = 0; j2 < 8; j2++) {
        #pragma unroll
        for (int e = 0; e < 2; e++) {
            int d = 8 * j2 + t2 + e;
            if (qi0 < TT)
                oh[(size_t)(b * TT + qi0) * EE + h * DHEAD + d] = __float2half_rn(acc_o[j2][e] * il0);
            if (qi1 < TT)
                oh[(size_t)(b * TT + qi1) * EE + h * DHEAD + d] = __float2half_rn(acc_o[j2][e + 2] * il1);
        }
    }
}

// ---------------- layernorm: warp per token ----------------
__global__ void ln_kernel(const float* __restrict__ x, const float* __restrict__ g,
                          const float* __restrict__ bp, __half* __restrict__ yh)
{
    int warp = threadIdx.x >> 5, lane = threadIdx.x & 31;
    int m = blockIdx.x * 8 + warp;
    const float4* xr = reinterpret_cast<const float4*>(x + (size_t)m * EE);

    float4 v[6];
    float s = 0.f, s2 = 0.f;
    #pragma unroll
    for (int k = 0; k < 6; k++) {
        v[k] = xr[lane + 32 * k];
        s  += v[k].x + v[k].y + v[k].z + v[k].w;
        s2 += v[k].x * v[k].x + v[k].y * v[k].y + v[k].z * v[k].z + v[k].w * v[k].w;
    }
    #pragma unroll
    for (int o = 16; o > 0; o >>= 1) {
        s  += __shfl_xor_sync(0xFFFFFFFFu, s, o);
        s2 += __shfl_xor_sync(0xFFFFFFFFu, s2, o);
    }
    float mean = s * (1.0f / EE);
    float inv = rsqrtf(s2 * (1.0f / EE) - mean * mean + 1e-5f);

    __half2* ph = reinterpret_cast<__half2*>(yh + (size_t)m * EE);
    #pragma unroll
    for (int k = 0; k < 6; k++) {
        float4 gg = reinterpret_cast<const float4*>(g)[lane + 32 * k];
        float4 bb = reinterpret_cast<const float4*>(bp)[lane + 32 * k];
        float o0 = (v[k].x - mean) * inv * gg.x + bb.x;
        float o1 = (v[k].y - mean) * inv * gg.y + bb.y;
        float o2 = (v[k].z - mean) * inv * gg.z + bb.z;
        float o3 = (v[k].w - mean) * inv * gg.w + bb.w;
        int idx = (lane + 32 * k) * 2;
        ph[idx]     = __halves2half2(__float2half_rn(o0), __float2half_rn(o1));
        ph[idx + 1] = __halves2half2(__float2half_rn(o2), __float2half_rn(o3));
    }
}

// ---------------- head + flux ----------------
__global__ void head_kernel(const float* __restrict__ hbuf,
                            const float* __restrict__ lnw, const float* __restrict__ lnb,
                            const float* __restrict__ hw, const float* __restrict__ hb,
                            const float* __restrict__ mean_s, const float* __restrict__ std_s,
                            float* __restrict__ out)
{
    int warp = threadIdx.x >> 5, lane = threadIdx.x & 31;
    int m = blockIdx.x * 8 + warp;
    const float4* xr = reinterpret_cast<const float4*>(hbuf + (size_t)m * EE);

    float4 v[6];
    float s = 0.f, s2 = 0.f;
    #pragma unroll
    for (int k = 0; k < 6; k++) {
        v[k] = xr[lane + 32 * k];
        s  += v[k].x + v[k].y + v[k].z + v[k].w;
        s2 += v[k].x * v[k].x + v[k].y * v[k].y + v[k].z * v[k].z + v[k].w * v[k].w;
    }
    #pragma unroll
    for (int o = 16; o > 0; o >>= 1) {
        s  += __shfl_xor_sync(0xFFFFFFFFu, s, o);
        s2 += __shfl_xor_sync(0xFFFFFFFFu, s2, o);
    }
    float mean = s * (1.0f / EE);
    float inv = rsqrtf(s2 * (1.0f / EE) - mean * mean + 1e-5f);

    float dot = 0.f;
    #pragma unroll
    for (int k = 0; k < 6; k++) {
        float4 gg = reinterpret_cast<const float4*>(lnw)[lane + 32 * k];
        float4 bb = reinterpret_cast<const float4*>(lnb)[lane + 32 * k];
        float4 ww = reinterpret_cast<const float4*>(hw)[lane + 32 * k];
        dot += ((v[k].x - mean) * inv * gg.x + bb.x) * ww.x;
        dot += ((v[k].y - mean) * inv * gg.y + bb.y) * ww.y;
        dot += ((v[k].z - mean) * inv * gg.z + bb.z) * ww.z;
        dot += ((v[k].w - mean) * inv * gg.w + bb.w) * ww.w;
    }
    #pragma unroll
    for (int o = 16; o > 0; o >>= 1)
        dot += __shfl_xor_sync(0xFFFFFFFFu, dot, o);

    if (lane == 0) {
        float logit = dot + hb[0];
        float lg = logit * std_s[0] + mean_s[0];
        float pf = exp10f(lg) - 1e-8f;
        pf = fminf(fmaxf(pf, 1e-15f), 1.0f);
        out[BB + m] = pf;
    }
}

__global__ void flux_reduce(float* __restrict__ out)
{
    int b = blockIdx.x;
    __shared__ float red[256];
    int tid = threadIdx.x;
    float s = 0.f;
    for (int i = tid; i < TT; i += 256) s += out[BB + b * TT + i];
    red[tid] = s; __syncthreads();
    for (int st = 128; st > 0; st >>= 1) { if (tid < st) red[tid] += red[tid + st]; __syncthreads(); }
    if (tid == 0) out[b] = fmaxf(red[0], 1e-15f);
}

// ---------------- launcher ----------------
extern "C" void kernel_launch(void* const* d_in, const int* in_sizes, int n_in,
                              void* d_out, int out_size)
{
    const float* x        = (const float*)d_in[0];
    const float* sxr_mean = (const float*)d_in[1];
    const float* sxr_std  = (const float*)d_in[2];
    const float* input_w  = (const float*)d_in[3];
    const float* input_b  = (const float*)d_in[4];
    const float* pos_emb  = (const float*)d_in[5];
    const float* ln1_w    = (const float*)d_in[6];
    const float* ln1_b    = (const float*)d_in[7];
    const float* in_w     = (const float*)d_in[8];
    const float* in_b     = (const float*)d_in[9];
    const float* out_w    = (const float*)d_in[10];
    const float* out_b    = (const float*)d_in[11];
    const float* ln2_w    = (const float*)d_in[12];
    const float* ln2_b    = (const float*)d_in[13];
    const float* w1       = (const float*)d_in[14];
    const float* b1       = (const float*)d_in[15];
    const float* w2       = (const float*)d_in[16];
    const float* b2       = (const float*)d_in[17];
    const float* head_lnw = (const float*)d_in[18];
    const float* head_lnb = (const float*)d_in[19];
    const float* head_w   = (const float*)d_in[20];
    const float* head_b   = (const float*)d_in[21];
    float* out = (float*)d_out;

    __half *xp, *y, *qkv, *o, *mlp;
    __half *iwh, *inwh, *outwh, *w1h, *w2h;
    float *h;
    cudaGetSymbolAddress((void**)&xp,    g_xp);
    cudaGetSymbolAddress((void**)&h,     g_h);
    cudaGetSymbolAddress((void**)&y,     g_y);
    cudaGetSymbolAddress((void**)&qkv,   g_qkv);
    cudaGetSymbolAddress((void**)&o,     g_o);
    cudaGetSymbolAddress((void**)&mlp,   g_mlp);
    cudaGetSymbolAddress((void**)&iwh,   g_iw_h);
    cudaGetSymbolAddress((void**)&inwh,  g_inw_h);
    cudaGetSymbolAddress((void**)&outwh, g_outw_h);
    cudaGetSymbolAddress((void**)&w1h,   g_w1_h);
    cudaGetSymbolAddress((void**)&w2h,   g_w2_h);

    static bool attr_done = false;
    if (!attr_done) {
        cudaFuncSetAttribute(gemm128, cudaFuncAttributeMaxDynamicSharedMemorySize, 110592);
        cudaFuncSetAttribute(gemm64,  cudaFuncAttributeMaxDynamicSharedMemorySize, 46080);
        cudaFuncSetAttribute(flash_attn, cudaFuncAttributeMaxDynamicSharedMemorySize, 55296);
        attr_done = true;
    }

    {
        long total = (long)CN0 + CN1 + CN2 + CN3 + CN4;
        int blocks = (int)((total + 255) / 256);
        conv_all<<<blocks, 256>>>(
            (const float4*)input_w, (const float4*)in_w, (const float4*)out_w,
            (const float4*)w1, (const float4*)w2,
            (__half2*)iwh, (__half2*)inwh, (__half2*)outwh,
            (__half2*)w1h, (__half2*)w2h);
    }

    patch_gather<<<(MM * EE + 255) / 256, 256>>>(x, xp);
    gemm64<<<dim3(EE / 128, MM / 64), 256, 46080>>>(
        xp, iwh, input_b, pos_emb, h, nullptr, MM, EE, EE, EPI_POS, 0);

    for (int l = 0; l < NLAYERS; l++) {
        const float* l1w = ln1_w + (size_t)l * EE;
        const float* l1b = ln1_b + (size_t)l * EE;
        const float* ib  = in_b  + (size_t)l * 3 * EE;
        const float* ob  = out_b + (size_t)l * EE;
        const float* l2w = ln2_w + (size_t)l * EE;
        const float* l2b = ln2_b + (size_t)l * EE;
        const float* B1  = b1 + (size_t)l * HDIM;
        const float* B2  = b2 + (size_t)l * EE;
        size_t inoff  = (size_t)l * 3 * EE * EE;
        size_t outoff = (size_t)l * EE * EE;
        size_t w1off  = (size_t)l * HDIM * EE;
        size_t w2off  = (size_t)l * EE * HDIM;

        ln_kernel<<<MM / 8, 256>>>(h, l1w, l1b, y);
        gemm128<<<dim3(3 * EE / 128, MPAD / 128), 256, 110592>>>(
            y, inwh + inoff, ib, nullptr, nullptr, qkv, MPAD, 3 * EE, EE, EPI_NONE, 1);
        flash_attn<<<dim3(7, NBH), 256, 55296>>>(qkv, o);
        gemm64<<<dim3(EE / 128, MM / 64), 256, 46080>>>(
            o, outwh + outoff, ob, h, h, nullptr, MM, EE, EE, EPI_RES, 0);
        ln_kernel<<<MM / 8, 256>>>(h, l2w, l2b, y);
        gemm128<<<dim3(HDIM / 128, MPAD / 128), 256, 110592>>>(
            y, w1h + w1off, B1, nullptr, nullptr, mlp, MPAD, HDIM, EE, EPI_GELU, 1);
        gemm64<<<dim3(EE / 128, MM / 64), 256, 46080>>>(
            mlp, w2h + w2off, B2, h, h, nullptr, MM, EE, HDIM, EPI_RES, 0);
    }

    head_kernel<<<MM / 8, 256>>>(h, head_lnw, head_lnb, head_w, head_b,
                                 sxr_mean, sxr_std, out);
    flux_reduce<<<BB, 256>>>(out);
}

// round 17
// speedup vs baseline: 1.5302x; 1.0046x over previous
#include <cuda_runtime.h>
#include <cuda_fp16.h>
#include <math.h>
#include <stdint.h>

// ---------------- problem constants ----------------
#define BB 4
#define TT 784
#define GG 28
#define EE 768
#define HDIM 3072
#define NHEADS 12
#define DHEAD 64
#define NLAYERS 6
#define MM (BB*TT)        // 3136
#define MPAD 3200
#define NBH (BB*NHEADS)   // 48

// ---------------- scratch ----------------
__device__ __half g_xp[MPAD * EE];
__device__ float  g_h[MPAD * EE];
__device__ __half g_y[MPAD * EE];
__device__ __half g_qkv[MPAD * 3 * EE];
__device__ __half g_o[MPAD * EE];
__device__ __half g_mlp[MPAD * HDIM];
// pre-converted fp16 weights
__device__ __half g_iw_h[EE * EE];
__device__ __half g_inw_h[NLAYERS * 3 * EE * EE];
__device__ __half g_outw_h[NLAYERS * EE * EE];
__device__ __half g_w1_h[NLAYERS * HDIM * EE];
__device__ __half g_w2_h[NLAYERS * EE * HDIM];

#define EPI_NONE 0
#define EPI_POS  1
#define EPI_RES  2
#define EPI_GELU 3

// ---------------- helpers ----------------
__device__ __forceinline__ uint32_t packh2(__half a, __half b) {
    __half2 x = __halves2half2(a, b);
    return *reinterpret_cast<uint32_t*>(&x);
}

__device__ __forceinline__ void mma_f16(float d[4],
                                        uint32_t a0, uint32_t a1, uint32_t a2, uint32_t a3,
                                        uint32_t b0, uint32_t b1) {
    asm volatile(
        "mma.sync.aligned.m16n8k16.row.col.f32.f16.f16.f32 "
        "{%0,%1,%2,%3}, {%4,%5,%6,%7}, {%8,%9}, {%0,%1,%2,%3};"
        : "+f"(d[0]), "+f"(d[1]), "+f"(d[2]), "+f"(d[3])
        : "r"(a0), "r"(a1), "r"(a2), "r"(a3), "r"(b0), "r"(b1));
}

#define LDSM_X4(r0, r1, r2, r3, addr) \
    asm volatile("ldmatrix.sync.aligned.m8n8.x4.shared.b16 {%0,%1,%2,%3}, [%4];" \
        : "=r"(r0), "=r"(r1), "=r"(r2), "=r"(r3) : "r"(addr))

#define LDSM_X4T(r0, r1, r2, r3, addr) \
    asm volatile("ldmatrix.sync.aligned.m8n8.x4.trans.shared.b16 {%0,%1,%2,%3}, [%4];" \
        : "=r"(r0), "=r"(r1), "=r"(r2), "=r"(r3) : "r"(addr))

__device__ __forceinline__ void cpa16(uint32_t dst, const void* src) {
    asm volatile("cp.async.cg.shared.global [%0], [%1], 16;" :: "r"(dst), "l"(src));
}
__device__ __forceinline__ void cpa16z(uint32_t dst, const void* src, bool valid) {
    int sz = valid ? 16 : 0;
    asm volatile("cp.async.cg.shared.global [%0], [%1], 16, %2;"
                 :: "r"(dst), "l"(src), "r"(sz));
}
__device__ __forceinline__ void cp_commit() { asm volatile("cp.async.commit_group;"); }
__device__ __forceinline__ void cp_wait0() { asm volatile("cp.async.wait_group 0;"); }
__device__ __forceinline__ void cp_wait1() { asm volatile("cp.async.wait_group 1;"); }

// ---------------- epilogue ----------------
__device__ __forceinline__ void epi_store(float v, int m, int n, int N, int epi, int split,
                                          const float* bias, const float* extra,
                                          float* C, __half* Ch)
{
    v += bias[n];
    if (epi == EPI_POS)       v += extra[(size_t)(m % TT) * N + n];
    else if (epi == EPI_RES)  v += extra[(size_t)m * N + n];
    else if (epi == EPI_GELU) v = 0.5f * v * (1.0f + erff(v * 0.70710678118654752f));
    if (split) Ch[(size_t)m * N + n] = __float2half_rn(v);
    else       C[(size_t)m * N + n] = v;
}

// ---------------- merged weight convert ----------------
#define CN0 ((EE*EE)/4)
#define CN1 ((NLAYERS*3*EE*EE)/4)
#define CN2 ((NLAYERS*EE*EE)/4)
#define CN3 ((NLAYERS*HDIM*EE)/4)
#define CN4 ((NLAYERS*EE*HDIM)/4)
__global__ void conv_all(const float4* __restrict__ s0, const float4* __restrict__ s1,
                         const float4* __restrict__ s2, const float4* __restrict__ s3,
                         const float4* __restrict__ s4,
                         __half2* __restrict__ d0, __half2* __restrict__ d1,
                         __half2* __restrict__ d2, __half2* __restrict__ d3,
                         __half2* __restrict__ d4)
{
    long i = (long)blockIdx.x * 256 + threadIdx.x;
    const float4* s; __half2* d; long off;
    if (i < CN0)                                    { s = s0; d = d0; off = i; }
    else if (i < (long)CN0 + CN1)                   { s = s1; d = d1; off = i - CN0; }
    else if (i < (long)CN0 + CN1 + CN2)             { s = s2; d = d2; off = i - CN0 - CN1; }
    else if (i < (long)CN0 + CN1 + CN2 + CN3)       { s = s3; d = d3; off = i - CN0 - CN1 - CN2; }
    else if (i < (long)CN0 + CN1 + CN2 + CN3 + CN4) { s = s4; d = d4; off = i - CN0 - CN1 - CN2 - CN3; }
    else return;
    float4 a = s[off];
    d[2 * off]     = __halves2half2(__float2half_rn(a.x), __float2half_rn(a.y));
    d[2 * off + 1] = __halves2half2(__float2half_rn(a.z), __float2half_rn(a.w));
}

// ---------------- patch gather ----------------
__global__ void patch_gather(const float* __restrict__ x, __half* __restrict__ xh) {
    int idx = blockIdx.x * 256 + threadIdx.x;
    if (idx >= MM * EE) return;
    int j = idx % EE;
    int m = idx / EE;
    int b = m / TT, t = m % TT;
    int gr = t / GG, gc = t % GG;
    int ch = j >> 8, pr = (j >> 4) & 15, pc = j & 15;
    float v = x[(((size_t)b * 448 + gr * 16 + pr) * 448 + (gc * 16 + pc)) * 3 + ch];
    xh[idx] = __float2half_rn(v);
}

// ---------------- GEMM A: 128x128 block tile, k-chunk 64, 3-stage ----------------
#define GSTW 72
#define STG128 36864
__global__ __launch_bounds__(256, 2)
void gemm128(const __half* __restrict__ Ah, const __half* __restrict__ Wh,
             const float* __restrict__ bias, const float* __restrict__ extra,
             float* __restrict__ C, __half* __restrict__ Ch,
             int M, int N, int K, int epi, int split)
{
    extern __shared__ __half smh[];
    int tid = threadIdx.x, warp = tid >> 5, lane = tid & 31;
    int r = lane >> 2, t2 = (lane & 3) * 2;
    int m0 = blockIdx.y * 128, n0 = blockIdx.x * 128;
    int wm = (warp & 3) * 32, wn = (warp >> 2) * 64;
    uint32_t smb = (uint32_t)__cvta_generic_to_shared(smh);

    int lrow = tid >> 1, lpart = tid & 1;
    const __half* srcA = Ah + (size_t)(m0 + lrow) * K + lpart * 32;
    const __half* srcW = Wh + (size_t)(n0 + lrow) * K + lpart * 32;
    uint32_t dA = smb + (uint32_t)(lrow * GSTW + lpart * 32) * 2;

    int a_row = wm + (lane & 15);
    int a_col = (lane >> 4) << 3;
    int b_row = wn + ((lane >> 4) << 3) + (lane & 7);
    int b_col = ((lane >> 3) & 1) << 3;

    float acc[2][8][4] = {};
    const int KT = K >> 6;

    auto issue = [&](int st, int kc) {
        int k0 = kc << 6;
        uint32_t base = st * STG128;
        #pragma unroll
        for (int c = 0; c < 4; c++) {
            cpa16(dA + base + c * 16,         srcA + k0 + c * 8);
            cpa16(dA + base + 18432 + c * 16, srcW + k0 + c * 8);
        }
    };

    issue(0, 0); cp_commit();
    if (KT > 1) { issue(1, 1); cp_commit(); }

    int st2 = 2;
    for (int kc = 0; kc < KT; kc++) {
        if (kc + 1 < KT) cp_wait1(); else cp_wait0();
        __syncthreads();
        if (kc + 2 < KT) {
            issue(st2, kc + 2); cp_commit();
            st2 = (st2 == 2) ? 0 : st2 + 1;
        }

        uint32_t aA = smb + (kc % 3) * STG128;
        uint32_t aW = aA + 18432;

        #pragma unroll
        for (int s = 0; s < 4; s++) {
            int ks = s * 16;
            uint32_t ah[2][4];
            #pragma unroll
            for (int i2 = 0; i2 < 2; i2++) {
                uint32_t adr = (uint32_t)((a_row + 16 * i2) * GSTW + ks + a_col) * 2;
                LDSM_X4(ah[i2][0], ah[i2][1], ah[i2][2], ah[i2][3], aA + adr);
            }
            #pragma unroll
            for (int jj = 0; jj < 4; jj++) {
                uint32_t badr = aW + (uint32_t)((b_row + 16 * jj) * GSTW + ks + b_col) * 2;
                uint32_t b00, b01, b10, b11;
                LDSM_X4(b00, b01, b10, b11, badr);
                #pragma unroll
                for (int i2 = 0; i2 < 2; i2++) {
                    mma_f16(acc[i2][2 * jj],     ah[i2][0], ah[i2][1], ah[i2][2], ah[i2][3], b00, b01);
                    mma_f16(acc[i2][2 * jj + 1], ah[i2][0], ah[i2][1], ah[i2][2], ah[i2][3], b10, b11);
                }
            }
        }
    }

    __syncthreads();
    #pragma unroll
    for (int i2 = 0; i2 < 2; i2++) {
        #pragma unroll
        for (int j = 0; j < 8; j++) {
            #pragma unroll
            for (int half = 0; half < 2; half++) {
                int m = m0 + wm + 16 * i2 + r + half * 8;
                #pragma unroll
                for (int e = 0; e < 2; e++) {
                    int n = n0 + wn + 8 * j + t2 + e;
                    epi_store(acc[i2][j][half * 2 + e], m, n, N, epi, split,
                              bias, extra, C, Ch);
                }
            }
        }
    }
}

// ---------------- GEMM B: 64x128 block tile, k-chunk 32, 3-stage ----------------
#define GST 40
#define STG64 15360
__global__ __launch_bounds__(256, 3)
void gemm64(const __half* __restrict__ Ah, const __half* __restrict__ Wh,
            const float* __restrict__ bias, const float* __restrict__ extra,
            float* __restrict__ C, __half* __restrict__ Ch,
            int M, int N, int K, int epi, int split)
{
    extern __shared__ __half smh[];
    int tid = threadIdx.x, warp = tid >> 5, lane = tid & 31;
    int r = lane >> 2, t2 = (lane & 3) * 2;
    int m0 = blockIdx.y * 64, n0 = blockIdx.x * 128;
    int wm = (warp & 3) * 16, wn = (warp >> 2) * 64;
    uint32_t smb = (uint32_t)__cvta_generic_to_shared(smh);

    int a_lrow = tid >> 2, a_seg = tid & 3;
    int w_lrow = tid >> 1, w_seg0 = (tid & 1) * 2;
    const __half* srcA = Ah + (size_t)(m0 + a_lrow) * K + a_seg * 8;
    const __half* srcW = Wh + (size_t)(n0 + w_lrow) * K;
    uint32_t dA = smb + (uint32_t)(a_lrow * GST + a_seg * 8) * 2;
    uint32_t dW = smb + 5120 + (uint32_t)(w_lrow * GST) * 2;

    int a_row = wm + (lane & 15);
    int a_col = (lane >> 4) << 3;
    int b_row = wn + ((lane >> 4) << 3) + (lane & 7);
    int b_col = ((lane >> 3) & 1) << 3;

    float acc[8][4] = {};
    const int KT = K >> 5;

    auto issue = [&](int st, int kc) {
        int k0 = kc << 5;
        uint32_t sb = st * STG64;
        cpa16(dA + sb, srcA + k0);
        cpa16(dW + sb + w_seg0 * 16,       srcW + k0 + w_seg0 * 8);
        cpa16(dW + sb + (w_seg0 + 1) * 16, srcW + k0 + (w_seg0 + 1) * 8);
    };

    issue(0, 0); cp_commit();
    if (KT > 1) { issue(1, 1); cp_commit(); }

    int st2 = 2;
    for (int kc = 0; kc < KT; kc++) {
        if (kc + 1 < KT) cp_wait1(); else cp_wait0();
        __syncthreads();
        if (kc + 2 < KT) {
            issue(st2, kc + 2); cp_commit();
            st2 = (st2 == 2) ? 0 : st2 + 1;
        }

        uint32_t aA = smb + (kc % 3) * STG64;
        uint32_t aW = aA + 5120;

        #pragma unroll
        for (int s = 0; s < 2; s++) {
            int ks = s * 16;
            uint32_t ah[4];
            {
                uint32_t adr = (uint32_t)(a_row * GST + ks + a_col) * 2;
                LDSM_X4(ah[0], ah[1], ah[2], ah[3], aA + adr);
            }
            #pragma unroll
            for (int jj = 0; jj < 4; jj++) {
                uint32_t badr = aW + (uint32_t)((b_row + 16 * jj) * GST + ks + b_col) * 2;
                uint32_t b00, b01, b10, b11;
                LDSM_X4(b00, b01, b10, b11, badr);
                mma_f16(acc[2 * jj],     ah[0], ah[1], ah[2], ah[3], b00, b01);
                mma_f16(acc[2 * jj + 1], ah[0], ah[1], ah[2], ah[3], b10, b11);
            }
        }
    }

    __syncthreads();
    #pragma unroll
    for (int j = 0; j < 8; j++) {
        #pragma unroll
        for (int half = 0; half < 2; half++) {
            int m = m0 + wm + r + half * 8;
            #pragma unroll
            for (int e = 0; e < 2; e++) {
                int n = n0 + wn + 8 * j + t2 + e;
                epi_store(acc[j][half * 2 + e], m, n, N, epi, split,
                          bias, extra, C, Ch);
            }
        }
    }
}

// ---------------- fused flash attention: coalesced V + ldmatrix.trans ----------------
#define QST 72
__global__ __launch_bounds__(256, 2)
void flash_attn(const __half* __restrict__ qkv, __half* __restrict__ oh)
{
    extern __shared__ __half sm[];
    __half* sQ = sm;                  // 128 x 72 halves
    __half* sK = sm + 9216;           // 128 x 72
    __half* sV = sm + 18432;          // 128 x 72  [k][d]

    int bh = blockIdx.y, b = bh / NHEADS, h = bh % NHEADS;
    int q0 = blockIdx.x * 128;
    int tid = threadIdx.x, warp = tid >> 5, lane = tid & 31;
    int r = lane >> 2, t2 = (lane & 3) * 2;
    uint32_t smb = (uint32_t)__cvta_generic_to_shared(sm);

    int lrow = tid >> 1, lpart = tid & 1;

    // ---- load Q tile (once) ----
    {
        int qrow = q0 + lrow;
        bool qv = qrow < TT;
        const __half* sQg = qkv + (size_t)(b * TT + (qv ? qrow : 0)) * (3 * EE) + h * DHEAD + lpart * 32;
        uint32_t d0 = smb + lrow * (QST * 2) + lpart * 64;
        #pragma unroll
        for (int c = 0; c < 4; c++) cpa16z(d0 + c * 16, sQg + c * 8, qv);
    }
    cp_commit();

    int qi0 = q0 + 16 * warp + r;
    int qi1 = qi0 + 8;
    int rq0 = qi0 / GG, cq0 = qi0 - rq0 * GG;
    int rq1 = qi1 / GG, cq1 = qi1 - rq1 * GG;

    float m0 = -1e30f, m1 = -1e30f, l0 = 0.f, l1 = 0.f;
    float acc_o[8][4] = {};

    for (int kb = 0; kb < 7; kb++) {
        int k0 = kb * 128;
        __syncthreads();

        // ---- load K and V tiles (both coalesced, [k][d] rows of 128B) ----
        {
            int krow = k0 + lrow;
            bool kv2 = krow < TT;
            const __half* sKg = qkv + (size_t)(b * TT + (kv2 ? krow : 0)) * (3 * EE) + EE + h * DHEAD + lpart * 32;
            const __half* sVg = qkv + (size_t)(b * TT + (kv2 ? krow : 0)) * (3 * EE) + 2 * EE + h * DHEAD + lpart * 32;
            uint32_t dk = smb + 18432 + lrow * (QST * 2) + lpart * 64;
            uint32_t dv = smb + 36864 + lrow * (QST * 2) + lpart * 64;
            #pragma unroll
            for (int c = 0; c < 4; c++) {
                cpa16z(dk + c * 16, sKg + c * 8, kv2);
                cpa16z(dv + c * 16, sVg + c * 8, kv2);
            }
        }
        cp_commit(); cp_wait0();
        __syncthreads();

        // ---- S = Q.K^T single pass ----
        float s[16][4] = {};
        #pragma unroll
        for (int ds = 0; ds < 4; ds++) {
            int ks = ds * 16;
            const __half* pa = sQ + (16 * warp + r) * QST + ks + t2;
            uint32_t a0 = *(const uint32_t*)pa;
            uint32_t a1 = *(const uint32_t*)(pa + 8 * QST);
            uint32_t a2 = *(const uint32_t*)(pa + 8);
            uint32_t a3 = *(const uint32_t*)(pa + 8 * QST + 8);
            #pragma unroll
            for (int j = 0; j < 16; j++) {
                const __half* pk = sK + (8 * j + r) * QST + ks + t2;
                uint32_t b0 = *(const uint32_t*)pk;
                uint32_t b1 = *(const uint32_t*)(pk + 8);
                mma_f16(s[j], a0, a1, a2, a3, b0, b1);
            }
        }

        // ---- mask + scale, online softmax ----
        float bm0 = -1e30f, bm1 = -1e30f;
        #pragma unroll
        for (int j = 0; j < 16; j++) {
            #pragma unroll
            for (int e = 0; e < 2; e++) {
                int ki = k0 + 8 * j + t2 + e;
                int rk = ki / GG, ck = ki - rk * GG;
                bool oob = ki >= TT;
                float v0 = s[j][e] * 0.125f;
                if (oob || (abs(rq0 - rk) <= 4 && abs(cq0 - ck) <= 4)) v0 = -1e30f;
                s[j][e] = v0;
                bm0 = fmaxf(bm0, v0);
                float v1 = s[j][e + 2] * 0.125f;
                if (oob || (abs(rq1 - rk) <= 4 && abs(cq1 - ck) <= 4)) v1 = -1e30f;
                s[j][e + 2] = v1;
                bm1 = fmaxf(bm1, v1);
            }
        }
        bm0 = fmaxf(bm0, __shfl_xor_sync(0xFFFFFFFFu, bm0, 1));
        bm0 = fmaxf(bm0, __shfl_xor_sync(0xFFFFFFFFu, bm0, 2));
        bm1 = fmaxf(bm1, __shfl_xor_sync(0xFFFFFFFFu, bm1, 1));
        bm1 = fmaxf(bm1, __shfl_xor_sync(0xFFFFFFFFu, bm1, 2));

        float nm0 = fmaxf(m0, bm0), nm1 = fmaxf(m1, bm1);
        float sc0 = __expf(m0 - nm0), sc1 = __expf(m1 - nm1);
        m0 = nm0; m1 = nm1;

        float rs0 = 0.f, rs1 = 0.f;
        #pragma unroll
        for (int j = 0; j < 16; j++) {
            #pragma unroll
            for (int e = 0; e < 2; e++) {
                float p0 = __expf(s[j][e] - m0);
                s[j][e] = p0; rs0 += p0;
                float p1 = __expf(s[j][e + 2] - m1);
                s[j][e + 2] = p1; rs1 += p1;
            }
        }
        rs0 += __shfl_xor_sync(0xFFFFFFFFu, rs0, 1);
        rs0 += __shfl_xor_sync(0xFFFFFFFFu, rs0, 2);
        rs1 += __shfl_xor_sync(0xFFFFFFFFu, rs1, 1);
        rs1 += __shfl_xor_sync(0xFFFFFFFFu, rs1, 2);
        l0 = l0 * sc0 + rs0;
        l1 = l1 * sc1 + rs1;

        #pragma unroll
        for (int j2 = 0; j2 < 8; j2++) {
            acc_o[j2][0] *= sc0; acc_o[j2][1] *= sc0;
            acc_o[j2][2] *= sc1; acc_o[j2][3] *= sc1;
        }

        // ---- O += P.V  (V [k][d] via ldmatrix.trans) ----
        #pragma unroll
        for (int s2 = 0; s2 < 8; s2++) {
            uint32_t a0 = packh2(__float2half_rn(s[2 * s2][0]),     __float2half_rn(s[2 * s2][1]));
            uint32_t a1 = packh2(__float2half_rn(s[2 * s2][2]),     __float2half_rn(s[2 * s2][3]));
            uint32_t a2 = packh2(__float2half_rn(s[2 * s2 + 1][0]), __float2half_rn(s[2 * s2 + 1][1]));
            uint32_t a3 = packh2(__float2half_rn(s[2 * s2 + 1][2]), __float2half_rn(s[2 * s2 + 1][3]));
            uint32_t vb = smb + 36864 +
                (uint32_t)((16 * s2 + (lane & 15)) * QST + 8 * (lane >> 4)) * 2;
            #pragma unroll
            for (int jp = 0; jp < 4; jp++) {
                uint32_t b00, b01, b10, b11;
                LDSM_X4T(b00, b01, b10, b11, vb + jp * 32);
                mma_f16(acc_o[2 * jp],     a0, a1, a2, a3, b00, b01);
                mma_f16(acc_o[2 * jp + 1], a0, a1, a2, a3, b10, b11);
            }
        }
    }

    // ---- epilogue ----
    float il0 = 1.f / l0, il1 = 1.f / l1;
    #pragma unroll
    for (int j2 = 0; j2 < 8; j2++) {
        #pragma unroll
        for (int e = 0; e < 2; e++) {
            int d = 8 * j2 + t2 + e;
            if (qi0 < TT)
                oh[(size_t)(b * TT + qi0) * EE + h * DHEAD + d] = __float2half_rn(acc_o[j2][e] * il0);
            if (qi1 < TT)
                oh[(size_t)(b * TT + qi1) * EE + h * DHEAD + d] = __float2half_rn(acc_o[j2][e + 2] * il1);
        }
    }
}

// ---------------- layernorm: warp per token ----------------
__global__ void ln_kernel(const float* __restrict__ x, const float* __restrict__ g,
                          const float* __restrict__ bp, __half* __restrict__ yh)
{
    int warp = threadIdx.x >> 5, lane = threadIdx.x & 31;
    int m = blockIdx.x * 8 + warp;
    const float4* xr = reinterpret_cast<const float4*>(x + (size_t)m * EE);

    float4 v[6];
    float s = 0.f, s2 = 0.f;
    #pragma unroll
    for (int k = 0; k < 6; k++) {
        v[k] = xr[lane + 32 * k];
        s  += v[k].x + v[k].y + v[k].z + v[k].w;
        s2 += v[k].x * v[k].x + v[k].y * v[k].y + v[k].z * v[k].z + v[k].w * v[k].w;
    }
    #pragma unroll
    for (int o = 16; o > 0; o >>= 1) {
        s  += __shfl_xor_sync(0xFFFFFFFFu, s, o);
        s2 += __shfl_xor_sync(0xFFFFFFFFu, s2, o);
    }
    float mean = s * (1.0f / EE);
    float inv = rsqrtf(s2 * (1.0f / EE) - mean * mean + 1e-5f);

    __half2* ph = reinterpret_cast<__half2*>(yh + (size_t)m * EE);
    #pragma unroll
    for (int k = 0; k < 6; k++) {
        float4 gg = reinterpret_cast<const float4*>(g)[lane + 32 * k];
        float4 bb = reinterpret_cast<const float4*>(bp)[lane + 32 * k];
        float o0 = (v[k].x - mean) * inv * gg.x + bb.x;
        float o1 = (v[k].y - mean) * inv * gg.y + bb.y;
        float o2 = (v[k].z - mean) * inv * gg.z + bb.z;
        float o3 = (v[k].w - mean) * inv * gg.w + bb.w;
        int idx = (lane + 32 * k) * 2;
        ph[idx]     = __halves2half2(__float2half_rn(o0), __float2half_rn(o1));
        ph[idx + 1] = __halves2half2(__float2half_rn(o2), __float2half_rn(o3));
    }
}

// ---------------- head + flux ----------------
__global__ void head_kernel(const float* __restrict__ hbuf,
                            const float* __restrict__ lnw, const float* __restrict__ lnb,
                            const float* __restrict__ hw, const float* __restrict__ hb,
                            const float* __restrict__ mean_s, const float* __restrict__ std_s,
                            float* __restrict__ out)
{
    int warp = threadIdx.x >> 5, lane = threadIdx.x & 31;
    int m = blockIdx.x * 8 + warp;
    const float4* xr = reinterpret_cast<const float4*>(hbuf + (size_t)m * EE);

    float4 v[6];
    float s = 0.f, s2 = 0.f;
    #pragma unroll
    for (int k = 0; k < 6; k++) {
        v[k] = xr[lane + 32 * k];
        s  += v[k].x + v[k].y + v[k].z + v[k].w;
        s2 += v[k].x * v[k].x + v[k].y * v[k].y + v[k].z * v[k].z + v[k].w * v[k].w;
    }
    #pragma unroll
    for (int o = 16; o > 0; o >>= 1) {
        s  += __shfl_xor_sync(0xFFFFFFFFu, s, o);
        s2 += __shfl_xor_sync(0xFFFFFFFFu, s2, o);
    }
    float mean = s * (1.0f / EE);
    float inv = rsqrtf(s2 * (1.0f / EE) - mean * mean + 1e-5f);

    float dot = 0.f;
    #pragma unroll
    for (int k = 0; k < 6; k++) {
        float4 gg = reinterpret_cast<const float4*>(lnw)[lane + 32 * k];
        float4 bb = reinterpret_cast<const float4*>(lnb)[lane + 32 * k];
        float4 ww = reinterpret_cast<const float4*>(hw)[lane + 32 * k];
        dot += ((v[k].x - mean) * inv * gg.x + bb.x) * ww.x;
        dot += ((v[k].y - mean) * inv * gg.y + bb.y) * ww.y;
        dot += ((v[k].z - mean) * inv * gg.z + bb.z) * ww.z;
        dot += ((v[k].w - mean) * inv * gg.w + bb.w) * ww.w;
    }
    #pragma unroll
    for (int o = 16; o > 0; o >>= 1)
        dot += __shfl_xor_sync(0xFFFFFFFFu, dot, o);

    if (lane == 0) {
        float logit = dot + hb[0];
        float lg = logit * std_s[0] + mean_s[0];
        float pf = exp10f(lg) - 1e-8f;
        pf = fminf(fmaxf(pf, 1e-15f), 1.0f);
        out[BB + m] = pf;
    }
}

__global__ void flux_reduce(float* __restrict__ out)
{
    int b = blockIdx.x;
    __shared__ float red[256];
    int tid = threadIdx.x;
    float s = 0.f;
    for (int i = tid; i < TT; i += 256) s += out[BB + b * TT + i];
    red[tid] = s; __syncthreads();
    for (int st = 128; st > 0; st >>= 1) { if (tid < st) red[tid] += red[tid + st]; __syncthreads(); }
    if (tid == 0) out[b] = fmaxf(red[0], 1e-15f);
}

// ---------------- launcher ----------------
extern "C" void kernel_launch(void* const* d_in, const int* in_sizes, int n_in,
                              void* d_out, int out_size)
{
    const float* x        = (const float*)d_in[0];
    const float* sxr_mean = (const float*)d_in[1];
    const float* sxr_std  = (const float*)d_in[2];
    const float* input_w  = (const float*)d_in[3];
    const float* input_b  = (const float*)d_in[4];
    const float* pos_emb  = (const float*)d_in[5];
    const float* ln1_w    = (const float*)d_in[6];
    const float* ln1_b    = (const float*)d_in[7];
    const float* in_w     = (const float*)d_in[8];
    const float* in_b     = (const float*)d_in[9];
    const float* out_w    = (const float*)d_in[10];
    const float* out_b    = (const float*)d_in[11];
    const float* ln2_w    = (const float*)d_in[12];
    const float* ln2_b    = (const float*)d_in[13];
    const float* w1       = (const float*)d_in[14];
    const float* b1       = (const float*)d_in[15];
    const float* w2       = (const float*)d_in[16];
    const float* b2       = (const float*)d_in[17];
    const float* head_lnw = (const float*)d_in[18];
    const float* head_lnb = (const float*)d_in[19];
    const float* head_w   = (const float*)d_in[20];
    const float* head_b   = (const float*)d_in[21];
    float* out = (float*)d_out;

    __half *xp, *y, *qkv, *o, *mlp;
    __half *iwh, *inwh, *outwh, *w1h, *w2h;
    float *h;
    cudaGetSymbolAddress((void**)&xp,    g_xp);
    cudaGetSymbolAddress((void**)&h,     g_h);
    cudaGetSymbolAddress((void**)&y,     g_y);
    cudaGetSymbolAddress((void**)&qkv,   g_qkv);
    cudaGetSymbolAddress((void**)&o,     g_o);
    cudaGetSymbolAddress((void**)&mlp,   g_mlp);
    cudaGetSymbolAddress((void**)&iwh,   g_iw_h);
    cudaGetSymbolAddress((void**)&inwh,  g_inw_h);
    cudaGetSymbolAddress((void**)&outwh, g_outw_h);
    cudaGetSymbolAddress((void**)&w1h,   g_w1_h);
    cudaGetSymbolAddress((void**)&w2h,   g_w2_h);

    static bool attr_done = false;
    if (!attr_done) {
        cudaFuncSetAttribute(gemm128, cudaFuncAttributeMaxDynamicSharedMemorySize, 110592);
        cudaFuncSetAttribute(gemm64,  cudaFuncAttributeMaxDynamicSharedMemorySize, 46080);
        cudaFuncSetAttribute(flash_attn, cudaFuncAttributeMaxDynamicSharedMemorySize, 55296);
        attr_done = true;
    }

    {
        long total = (long)CN0 + CN1 + CN2 + CN3 + CN4;
        int blocks = (int)((total + 255) / 256);
        conv_all<<<blocks, 256>>>(
            (const float4*)input_w, (const float4*)in_w, (const float4*)out_w,
            (const float4*)w1, (const float4*)w2,
            (__half2*)iwh, (__half2*)inwh, (__half2*)outwh,
            (__half2*)w1h, (__half2*)w2h);
    }

    patch_gather<<<(MM * EE + 255) / 256, 256>>>(x, xp);
    gemm64<<<dim3(EE / 128, MM / 64), 256, 46080>>>(
        xp, iwh, input_b, pos_emb, h, nullptr, MM, EE, EE, EPI_POS, 0);

    for (int l = 0; l < NLAYERS; l++) {
        const float* l1w = ln1_w + (size_t)l * EE;
        const float* l1b = ln1_b + (size_t)l * EE;
        const float* ib  = in_b  + (size_t)l * 3 * EE;
        const float* ob  = out_b + (size_t)l * EE;
        const float* l2w = ln2_w + (size_t)l * EE;
        const float* l2b = ln2_b + (size_t)l * EE;
        const float* B1  = b1 + (size_t)l * HDIM;
        const float* B2  = b2 + (size_t)l * EE;
        size_t inoff  = (size_t)l * 3 * EE * EE;
        size_t outoff = (size_t)l * EE * EE;
        size_t w1off  = (size_t)l * HDIM * EE;
        size_t w2off  = (size_t)l * EE * HDIM;

        ln_kernel<<<MM / 8, 256>>>(h, l1w, l1b, y);
        gemm128<<<dim3(3 * EE / 128, MPAD / 128), 256, 110592>>>(
            y, inwh + inoff, ib, nullptr, nullptr, qkv, MPAD, 3 * EE, EE, EPI_NONE, 1);
        flash_attn<<<dim3(7, NBH), 256, 55296>>>(qkv, o);
        gemm64<<<dim3(EE / 128, MM / 64), 256, 46080>>>(
            o, outwh + outoff, ob, h, h, nullptr, MM, EE, EE, EPI_RES, 0);
        ln_kernel<<<MM / 8, 256>>>(h, l2w, l2b, y);
        gemm128<<<dim3(HDIM / 128, MPAD / 128), 256, 110592>>>(
            y, w1h + w1off, B1, nullptr, nullptr, mlp, MPAD, HDIM, EE, EPI_GELU, 1);
        gemm64<<<dim3(EE / 128, MM / 64), 256, 46080>>>(
            mlp, w2h + w2off, B2, h, h, nullptr, MM, EE, HDIM, EPI_RES, 0);
    }

    head_kernel<<<MM / 8, 256>>>(h, head_lnw, head_lnb, head_w, head_b,
                                 sxr_mean, sxr_std, out);
    flux_reduce<<<BB, 256>>>(out);
}